// round 12
// baseline (speedup 1.0000x reference)
#include <cuda_runtime.h>
#include <cuda_bf16.h>
#include <math.h>
#include <stdint.h>

// ---------------- problem constants ----------------
#define BB     16
#define CC     128
#define TT     294
#define VV     25
#define NTOK   (BB*TT*VV)        // 117600 tokens
#define INNER  512
#define NHEAD  8
#define DH     64
#define PP     7
#define NTP    42                 // T / P
#define NKTOK  (BB*NTP*VV)        // 16800 kv tokens / patches
#define SCALE_ATT 0.125f
#define LN_EPS 1e-5f

// token order is PATCH-MAJOR: n' = ((b*NTP+tt)*VV + v)*7 + p   (t = tt*7+p)

// transposed bf16 weight layout (elements, per layer)
#define OFF_LQKV  0               // [1536,128]
#define OFF_LWO   196608          // [128,512]
#define OFF_F1A   262144          // [512,128]
#define OFF_F1B   327680          // [128,512]
#define OFF_GWQ   393216          // [512,128]
#define OFF_GWKV  458752          // [1024,896] (k index kp*128+c)
#define OFF_GWO   1376256         // [128,512]
#define OFF_F2A   1441792         // [512,128]
#define OFF_F2B   1507328         // [128,512]
#define WT_LSZ    1572864

// ---------------- scratch (static device memory; no allocs) ----------------
__device__ __align__(16) float          g_xT[NTOK*CC];          // residual, fp32
__device__ __align__(16) __nv_bfloat16  g_xn[NTOK*CC];          // LN output
__device__ __align__(16) __nv_bfloat16  g_qkv[(size_t)NTOK*1536];
__device__ __align__(16) __nv_bfloat16  g_q [NTOK*INNER];
__device__ __align__(16) __nv_bfloat16  g_kv[NKTOK*1024];
__device__ __align__(16) __nv_bfloat16  g_ao[NTOK*INNER];       // attn out / ff hidden
__device__ __align__(16) __nv_bfloat16  g_wt[2*WT_LSZ];

// ---------------- helpers ----------------
__device__ __forceinline__ uint32_t smem_u32(const void* p) {
    uint32_t a;
    asm("{ .reg .u64 t; cvta.to.shared.u64 t, %1; cvt.u32.u64 %0, t; }" : "=r"(a) : "l"(p));
    return a;
}
__device__ __forceinline__ float2 ldbf2(const __nv_bfloat16* p) {
    return __bfloat1622float2(*reinterpret_cast<const __nv_bfloat162*>(p));
}
__device__ __forceinline__ void stbf2(__nv_bfloat16* p, float2 v) {
    *reinterpret_cast<__nv_bfloat162*>(p) = __float22bfloat162_rn(v);
}
__device__ __forceinline__ float2 u2f2(uint32_t u) {
    return __bfloat1622float2(*reinterpret_cast<const __nv_bfloat162*>(&u));
}
__device__ __forceinline__ void mma_bf16(float* d, const uint32_t* a, const uint32_t* b) {
    asm volatile(
        "mma.sync.aligned.m16n8k16.row.col.f32.bf16.bf16.f32 "
        "{%0,%1,%2,%3}, {%4,%5,%6,%7}, {%8,%9}, {%0,%1,%2,%3};"
        : "+f"(d[0]), "+f"(d[1]), "+f"(d[2]), "+f"(d[3])
        : "r"(a[0]), "r"(a[1]), "r"(a[2]), "r"(a[3]), "r"(b[0]), "r"(b[1]));
}
__device__ __forceinline__ float gelu_exact(float v) {
    return 0.5f * v * (1.0f + erff(v * 0.7071067811865475f));
}

// ---------------- transpose in + fused LN(layer0,ln1), patch-major ---------
__global__ void k_tin(const float* __restrict__ x,
                      const float* __restrict__ gam, const float* __restrict__ bet) {
    int bt = blockIdx.x;
    int t = bt % TT, b = bt / TT;
    int tt = t / PP, p = t % PP;
    // n'(v) = nbase + v*7
    size_t nbase = ((size_t)(b*NTP + tt)*VV)*PP + p;
    __shared__ float sm[CC*VV];
    for (int idx = threadIdx.x; idx < CC*VV; idx += blockDim.x) {
        int c = idx / VV, v = idx % VV;
        sm[idx] = x[(((size_t)b*CC + c)*TT + t)*VV + v];
    }
    __syncthreads();
    for (int idx = threadIdx.x; idx < CC*VV; idx += blockDim.x) {
        int v = idx / CC, c = idx % CC;
        g_xT[(nbase + (size_t)v*PP)*CC + c] = sm[c*VV + v];
    }
    int wid = threadIdx.x >> 5, lane = threadIdx.x & 31;
    int c0 = lane * 4;
    float4 gg = *(const float4*)(gam + c0);
    float4 bb = *(const float4*)(bet + c0);
    for (int v = wid; v < VV; v += 8) {
        float f0 = sm[(c0+0)*VV + v], f1 = sm[(c0+1)*VV + v];
        float f2 = sm[(c0+2)*VV + v], f3 = sm[(c0+3)*VV + v];
        float s = f0+f1+f2+f3, ss = f0*f0+f1*f1+f2*f2+f3*f3;
        #pragma unroll
        for (int o = 16; o; o >>= 1) {
            s  += __shfl_xor_sync(0xffffffffu, s,  o);
            ss += __shfl_xor_sync(0xffffffffu, ss, o);
        }
        float m = s*(1.f/128.f), var = ss*(1.f/128.f) - m*m;
        float r = rsqrtf(var + LN_EPS);
        __nv_bfloat16* dst = g_xn + (nbase + (size_t)v*PP)*CC + c0;
        stbf2(dst,     make_float2((f0-m)*r*gg.x + bb.x, (f1-m)*r*gg.y + bb.y));
        stbf2(dst + 2, make_float2((f2-m)*r*gg.z + bb.z, (f3-m)*r*gg.w + bb.w));
    }
}

__global__ void k_tout(float* __restrict__ out) {
    int bt = blockIdx.x;
    int t = bt % TT, b = bt / TT;
    int tt = t / PP, p = t % PP;
    size_t nbase = ((size_t)(b*NTP + tt)*VV)*PP + p;
    __shared__ float sm[CC*VV];
    for (int idx = threadIdx.x; idx < CC*VV; idx += blockDim.x) {
        int v = idx / CC, c = idx % CC;
        sm[v*CC + c] = g_xT[(nbase + (size_t)v*PP)*CC + c];
    }
    __syncthreads();
    for (int idx = threadIdx.x; idx < CC*VV; idx += blockDim.x) {
        int c = idx / VV, v = idx % VV;
        out[(((size_t)b*CC + c)*TT + t)*VV + v] = sm[v*CC + c];
    }
}

// ---------------- weight prep: one launch per layer ------------------------
__global__ void k_wprep(const float* __restrict__ wq,  const float* __restrict__ wkv,
                        const float* __restrict__ wo,  const float* __restrict__ f1a,
                        const float* __restrict__ f1b, const float* __restrict__ gwq,
                        const float* __restrict__ gwkv,const float* __restrict__ gwo,
                        const float* __restrict__ f2a, const float* __restrict__ f2b,
                        __nv_bfloat16* __restrict__ dst)
{
    for (int idx = blockIdx.x*256 + threadIdx.x; idx < WT_LSZ; idx += gridDim.x*256) {
        float v;
        if (idx < OFF_LWO) {
            int m = idx >> 7, k = idx & 127;
            v = (m < 512) ? wq[k*512 + m] : wkv[k*1024 + (m-512)];
        } else if (idx < OFF_F1A) {
            int r = idx - OFF_LWO; int m = r >> 9, k = r & 511; v = wo[k*128 + m];
        } else if (idx < OFF_F1B) {
            int r = idx - OFF_F1A; int m = r >> 7, k = r & 127; v = f1a[k*512 + m];
        } else if (idx < OFF_GWQ) {
            int r = idx - OFF_F1B; int m = r >> 9, k = r & 511; v = f1b[k*128 + m];
        } else if (idx < OFF_GWKV) {
            int r = idx - OFF_GWQ; int m = r >> 7, k = r & 127; v = gwq[k*512 + m];
        } else if (idx < OFF_GWO) {
            int r = idx - OFF_GWKV; int i = r / 896; int kk = r - i*896;
            int kp = kk >> 7, c = kk & 127;
            v = gwkv[(c*PP + kp)*1024 + i];
        } else if (idx < OFF_F2A) {
            int r = idx - OFF_GWO; int m = r >> 9, k = r & 511; v = gwo[k*128 + m];
        } else if (idx < OFF_F2B) {
            int r = idx - OFF_F2A; int m = r >> 7, k = r & 127; v = f2a[k*512 + m];
        } else {
            int r = idx - OFF_F2B; int m = r >> 9, k = r & 511; v = f2b[k*128 + m];
        }
        dst[idx] = __float2bfloat16(v);
    }
}

// ---------------- channel layernorm: fp32 in, bf16 out ----------------
__global__ void __launch_bounds__(256) k_ln(const float* __restrict__ gam,
                                            const float* __restrict__ bet) {
    int n = blockIdx.x * 8 + (threadIdx.x >> 5);
    if (n >= NTOK) return;
    int lane = threadIdx.x & 31;
    float4 a = ((const float4*)(g_xT + (size_t)n*CC))[lane];
    float s  = a.x + a.y + a.z + a.w;
    float ss = a.x*a.x + a.y*a.y + a.z*a.z + a.w*a.w;
    #pragma unroll
    for (int o = 16; o; o >>= 1) {
        s  += __shfl_xor_sync(0xffffffffu, s,  o);
        ss += __shfl_xor_sync(0xffffffffu, ss, o);
    }
    float m   = s * (1.f/128.f);
    float var = ss * (1.f/128.f) - m*m;
    float r   = rsqrtf(var + LN_EPS);
    float4 gg = ((const float4*)gam)[lane];
    float4 bb = ((const float4*)bet)[lane];
    float2 p0 = make_float2((a.x - m)*r*gg.x + bb.x, (a.y - m)*r*gg.y + bb.y);
    float2 p1 = make_float2((a.z - m)*r*gg.z + bb.z, (a.w - m)*r*gg.w + bb.w);
    uint2 st;
    __nv_bfloat162 h0 = __float22bfloat162_rn(p0);
    __nv_bfloat162 h1 = __float22bfloat162_rn(p1);
    st.x = *reinterpret_cast<uint32_t*>(&h0);
    st.y = *reinterpret_cast<uint32_t*>(&h1);
    *reinterpret_cast<uint2*>(g_xn + (size_t)n*CC + lane*4) = st;
}

// ============================================================================
// Fused QKV GEMM + local attention.
// A-resident (128x128 A tile, 4x8KB), B streamed (4-stage ring), 12 col tiles.
// Row tile = 126 rows = 18 patches (patch-major order). After GEMM, phase 2:
// warp w = head w, 18 patches, k_lattn body on L2-hot qkv rows.
// ============================================================================
#define ARES_SMEM 65536

__global__ void __launch_bounds__(256, 2) k_qkv_attn(
    const __nv_bfloat16* __restrict__ A, const __nv_bfloat16* __restrict__ Wt,
    __nv_bfloat16* __restrict__ C, __nv_bfloat16* __restrict__ AO)
{
    extern __shared__ char smraw[];
    const uint32_t smb = smem_u32(smraw);
    const uint32_t Ab = smb;             // 4 x 8192 (A resident)
    const uint32_t Bb = smb + 32768;     // 4-stage ring x 8192

    const int t = threadIdx.x;
    const int lane = t & 31, wid = t >> 5;
    const int wr = wid & 1, wc = wid >> 1;
    const int rowBase = blockIdx.x * 126;

    const int rL = t >> 1, half = t & 1;
    int ga = rowBase + rL; if (ga >= NTOK) ga = NTOK - 1;
    const __nv_bfloat16* aP   = A  + (size_t)ga * 128 + (half << 4);
    const __nv_bfloat16* bRow = Wt + (size_t)rL * 128 + (half << 4);
    const int fL = (rL >> 1) & 3;
    const uint32_t dd = rL*64 + 16*((2*half) ^ fL);

    const int rA  = (lane & 7) + ((lane >> 3) & 1) * 8;
    const int ca  = lane >> 4;
    const int fra = (rA >> 1) & 3;
    const int g   = lane >> 3;
    const int nB  = ((g >> 1) & 1) * 8 + (lane & 7);
    const int cb  = g & 1;
    const int fnb = (nB >> 1) & 3;

    // load A resident (4 k-subtiles)
    #pragma unroll
    for (int kt = 0; kt < 4; ++kt) {
        size_t sa = __cvta_generic_to_global(aP + (kt << 5));
        uint32_t a1 = Ab + kt*8192 + dd;
        asm volatile("cp.async.cg.shared.global [%0], [%1], 16;" :: "r"(a1), "l"(sa));
        asm volatile("cp.async.cg.shared.global [%0], [%1], 16;" :: "r"(a1 ^ 16u), "l"(sa + 16));
    }

    #define B_ISSUE(i_) do {                                                       \
        size_t sb_ = __cvta_generic_to_global(bRow + ((size_t)((i_) >> 2) << 14)    \
                                              + (((i_) & 3) << 5));                 \
        uint32_t b1_ = Bb + ((i_) & 3)*8192 + dd;                                   \
        asm volatile("cp.async.cg.shared.global [%0], [%1], 16;" :: "r"(b1_), "l"(sb_)); \
        asm volatile("cp.async.cg.shared.global [%0], [%1], 16;" :: "r"(b1_ ^ 16u), "l"(sb_ + 16)); \
    } while (0)

    const int total = 48;   // 12 col tiles x 4 k-subtiles
    B_ISSUE(0); asm volatile("cp.async.commit_group;");
    B_ISSUE(1); asm volatile("cp.async.commit_group;");
    B_ISSUE(2); asm volatile("cp.async.commit_group;");

    float acc[4][4][4];
    #pragma unroll
    for (int mt = 0; mt < 4; ++mt)
        #pragma unroll
        for (int nt = 0; nt < 4; ++nt)
            #pragma unroll
            for (int e = 0; e < 4; ++e) acc[mt][nt][e] = 0.f;

    for (int i = 0; i < total; ++i) {
        asm volatile("cp.async.wait_group 2;");
        __syncthreads();
        if (i + 3 < total) B_ISSUE(i + 3);
        asm volatile("cp.async.commit_group;");

        const uint32_t stA = Ab + (uint32_t)(i & 3)*8192;
        const uint32_t stB = Bb + (uint32_t)(i & 3)*8192;
        #pragma unroll
        for (int ks = 0; ks < 2; ++ks) {
            uint32_t af[4][4], bf[4][2];
            #pragma unroll
            for (int mt = 0; mt < 4; ++mt) {
                uint32_t addr = stA + (uint32_t)((wr*64 + mt*16 + rA)*64)
                              + 16u*(uint32_t)(((ks<<1) + ca) ^ fra);
                asm volatile("ldmatrix.sync.aligned.m8n8.x4.shared.b16 {%0,%1,%2,%3}, [%4];"
                    : "=r"(af[mt][0]), "=r"(af[mt][1]), "=r"(af[mt][2]), "=r"(af[mt][3])
                    : "r"(addr));
            }
            #pragma unroll
            for (int j = 0; j < 2; ++j) {
                int n = wc*32 + j*16 + nB;
                uint32_t addr = stB + (uint32_t)(n*64)
                              + 16u*(uint32_t)(((ks<<1) + cb) ^ fnb);
                asm volatile("ldmatrix.sync.aligned.m8n8.x4.shared.b16 {%0,%1,%2,%3}, [%4];"
                    : "=r"(bf[2*j][0]), "=r"(bf[2*j][1]), "=r"(bf[2*j+1][0]), "=r"(bf[2*j+1][1])
                    : "r"(addr));
            }
            #pragma unroll
            for (int mt = 0; mt < 4; ++mt)
                #pragma unroll
                for (int nt = 0; nt < 4; ++nt)
                    mma_bf16(acc[mt][nt], af[mt], bf[nt]);
        }

        if ((i & 3) == 3) {
            const int colBase = (i >> 2) << 7;
            #pragma unroll
            for (int nt = 0; nt < 4; ++nt) {
                const int col = colBase + wc*32 + nt*8 + (lane & 3)*2;
                #pragma unroll
                for (int mt = 0; mt < 4; ++mt) {
                    #pragma unroll
                    for (int hf = 0; hf < 2; ++hf) {
                        const int rl = wr*64 + mt*16 + (lane >> 2) + hf*8;
                        const int r = rowBase + rl;
                        if (rl < 126 && r < NTOK)
                            stbf2(C + (size_t)r*1536 + col,
                                  make_float2(acc[mt][nt][hf*2], acc[mt][nt][hf*2+1]));
                        acc[mt][nt][hf*2] = 0.f; acc[mt][nt][hf*2+1] = 0.f;
                    }
                }
            }
        }
    }
    #undef B_ISSUE

    // -------- phase 2: local attention (warp = head, 18 patches) ------------
    __syncthreads();   // own-CTA global qkv writes visible block-wide
    const int h = wid;
    const int d0 = lane * 2;
    for (int pi = 0; pi < 18; ++pi) {
        const int pr = rowBase + pi*7;
        if (pr >= NTOK) break;
        float2 q[PP], kk[PP], vv[PP];
        #pragma unroll
        for (int p = 0; p < PP; ++p) {
            const __nv_bfloat16* rowp = C + (size_t)(pr + p)*1536 + h*DH + d0;
            q[p]  = ldbf2(rowp);
            kk[p] = ldbf2(rowp + 512);
            vv[p] = ldbf2(rowp + 1024);
        }
        float dots[PP][PP];
        #pragma unroll
        for (int i = 0; i < PP; ++i)
            #pragma unroll
            for (int j = 0; j < PP; ++j)
                dots[i][j] = q[i].x*kk[j].x + q[i].y*kk[j].y;
        #pragma unroll
        for (int o = 16; o; o >>= 1)
            #pragma unroll
            for (int i = 0; i < PP; ++i)
                #pragma unroll
                for (int j = 0; j < PP; ++j)
                    dots[i][j] += __shfl_xor_sync(0xffffffffu, dots[i][j], o);
        #pragma unroll
        for (int i = 0; i < PP; ++i) {
            float mx = -1e30f;
            #pragma unroll
            for (int j = 0; j < PP; ++j) {
                dots[i][j] *= SCALE_ATT;
                mx = fmaxf(mx, dots[i][j]);
            }
            float s = 0.f;
            #pragma unroll
            for (int j = 0; j < PP; ++j) { dots[i][j] = __expf(dots[i][j] - mx); s += dots[i][j]; }
            float inv = 1.f / s;
            #pragma unroll
            for (int j = 0; j < PP; ++j) dots[i][j] *= inv;
        }
        #pragma unroll
        for (int i = 0; i < PP; ++i) {
            float2 o = make_float2(0.f, 0.f);
            #pragma unroll
            for (int j = 0; j < PP; ++j) {
                o.x += dots[i][j] * vv[j].x;
                o.y += dots[i][j] * vv[j].y;
            }
            stbf2(AO + (size_t)(pr + i)*INNER + h*DH + d0, o);
        }
    }
}

// ---------------- bf16 mma GEMM (standard, R6-proven) -----------------------
// 128x128 CTA tile, K-tile 32, 4-stage cp.async ring, 2 CTAs/SM.
// EPI: 0 none (bf16 out), 2 bias+gelu (bf16 out), 3 bias+residual (fp32 out)
#define GSTAGE_BYTES 16384
#define GEMM_SMEM   (4*GSTAGE_BYTES)

template<int EPI>
__global__ void __launch_bounds__(256, 2) k_gemm_bf(
    const __nv_bfloat16* __restrict__ A, const __nv_bfloat16* __restrict__ Wt,
    const float* __restrict__ bias, const float* __restrict__ res,
    void* __restrict__ Cv, int Nrows, int K, int M)
{
    extern __shared__ char smraw[];
    const uint32_t smb = smem_u32(smraw);

    const int t = threadIdx.x;
    const int lane = t & 31, wid = t >> 5;
    const int wr = wid & 1, wc = wid >> 1;
    const int rowBase = blockIdx.y << 7, colBase = blockIdx.x << 7;

    const int rL = t >> 1, half = t & 1;
    int ga = rowBase + rL; if (ga >= Nrows) ga = Nrows - 1;
    const __nv_bfloat16* aP = A  + (size_t)ga * K + (half << 4);
    const __nv_bfloat16* bP = Wt + (size_t)(colBase + rL) * K + (half << 4);
    const int fL = (rL >> 1) & 3;
    const uint32_t dA = rL*64 + 16*((2*half) ^ fL);
    const uint32_t dB = 8192 + dA;

    const int rA  = (lane & 7) + ((lane >> 3) & 1) * 8;
    const int ca  = lane >> 4;
    const int fra = (rA >> 1) & 3;
    const int g   = lane >> 3;
    const int nB  = ((g >> 1) & 1) * 8 + (lane & 7);
    const int cb  = g & 1;
    const int fnb = (nB >> 1) & 3;

    float acc[4][4][4];
    #pragma unroll
    for (int mt = 0; mt < 4; ++mt)
        #pragma unroll
        for (int nt = 0; nt < 4; ++nt)
            #pragma unroll
            for (int e = 0; e < 4; ++e) acc[mt][nt][e] = 0.f;

    const int nk = K >> 5;

    #define G_ISSUE(kt_) do {                                                   \
        const uint32_t st_ = smb + ((kt_) & 3) * GSTAGE_BYTES;                   \
        size_t sa_ = __cvta_generic_to_global(aP + ((kt_) << 5));                \
        size_t sb_ = __cvta_generic_to_global(bP + ((kt_) << 5));                \
        uint32_t a1_ = st_ + dA, b1_ = st_ + dB;                                 \
        asm volatile("cp.async.cg.shared.global [%0], [%1], 16;" :: "r"(a1_), "l"(sa_)); \
        asm volatile("cp.async.cg.shared.global [%0], [%1], 16;" :: "r"(a1_ ^ 16u), "l"(sa_ + 16)); \
        asm volatile("cp.async.cg.shared.global [%0], [%1], 16;" :: "r"(b1_), "l"(sb_)); \
        asm volatile("cp.async.cg.shared.global [%0], [%1], 16;" :: "r"(b1_ ^ 16u), "l"(sb_ + 16)); \
    } while (0)

    G_ISSUE(0); asm volatile("cp.async.commit_group;");
    G_ISSUE(1); asm volatile("cp.async.commit_group;");
    G_ISSUE(2); asm volatile("cp.async.commit_group;");

    for (int kt = 0; kt < nk; ++kt) {
        asm volatile("cp.async.wait_group 2;");
        __syncthreads();
        if (kt + 3 < nk) G_ISSUE(kt + 3);
        asm volatile("cp.async.commit_group;");

        const uint32_t stA = smb + (kt & 3) * GSTAGE_BYTES;
        const uint32_t stB = stA + 8192;
        #pragma unroll
        for (int ks = 0; ks < 2; ++ks) {
            uint32_t af[4][4], bf[4][2];
            #pragma unroll
            for (int mt = 0; mt < 4; ++mt) {
                uint32_t addr = stA + (uint32_t)((wr*64 + mt*16 + rA)*64)
                              + 16u*(uint32_t)(((ks<<1) + ca) ^ fra);
                asm volatile("ldmatrix.sync.aligned.m8n8.x4.shared.b16 {%0,%1,%2,%3}, [%4];"
                    : "=r"(af[mt][0]), "=r"(af[mt][1]), "=r"(af[mt][2]), "=r"(af[mt][3])
                    : "r"(addr));
            }
            #pragma unroll
            for (int j = 0; j < 2; ++j) {
                int n = wc*32 + j*16 + nB;
                uint32_t addr = stB + (uint32_t)(n*64)
                              + 16u*(uint32_t)(((ks<<1) + cb) ^ fnb);
                asm volatile("ldmatrix.sync.aligned.m8n8.x4.shared.b16 {%0,%1,%2,%3}, [%4];"
                    : "=r"(bf[2*j][0]), "=r"(bf[2*j][1]), "=r"(bf[2*j+1][0]), "=r"(bf[2*j+1][1])
                    : "r"(addr));
            }
            #pragma unroll
            for (int mt = 0; mt < 4; ++mt)
                #pragma unroll
                for (int nt = 0; nt < 4; ++nt)
                    mma_bf16(acc[mt][nt], af[mt], bf[nt]);
        }
    }
    #undef G_ISSUE

    #pragma unroll
    for (int nt = 0; nt < 4; ++nt) {
        const int col = colBase + wc*32 + nt*8 + (lane & 3)*2;
        float2 bb = make_float2(0.f, 0.f);
        if (EPI >= 1) bb = *(const float2*)(bias + col);
        #pragma unroll
        for (int mt = 0; mt < 4; ++mt) {
            #pragma unroll
            for (int hf = 0; hf < 2; ++hf) {
                const int r = rowBase + wr*64 + mt*16 + (lane >> 2) + hf*8;
                if (r >= Nrows) continue;
                float2 o = make_float2(acc[mt][nt][hf*2+0] + bb.x,
                                       acc[mt][nt][hf*2+1] + bb.y);
                if (EPI == 2) { o.x = gelu_exact(o.x); o.y = gelu_exact(o.y); }
                if (EPI == 3) {
                    float2 rv = *(const float2*)(res + (size_t)r*M + col);
                    o.x += rv.x; o.y += rv.y;
                    *(float2*)((float*)Cv + (size_t)r*M + col) = o;
                } else {
                    stbf2((__nv_bfloat16*)Cv + (size_t)r*M + col, o);
                }
            }
        }
    }
}

// ---------------- global attention: one block per (b, h, v), patch-major ----
__global__ void __launch_bounds__(160) k_gattn() {
    int bid = blockIdx.x;
    int v = bid % VV;
    int rr = bid / VV;
    int h = rr & 7;
    int b = rr >> 3;
    __shared__ float ks[NTP][DH];
    __shared__ float vs[NTP][DH];
    for (int idx = threadIdx.x; idx < NTP*DH/2; idx += 160) {
        int j = idx >> 5, d2 = idx & 31;
        int nk = (b*NTP + j)*VV + v;
        size_t o = (size_t)nk*1024 + h*DH + d2*2;
        float2 kf = ldbf2(g_kv + o);
        float2 vf = ldbf2(g_kv + o + 512);
        ks[j][d2*2] = kf.x; ks[j][d2*2+1] = kf.y;
        vs[j][d2*2] = vf.x; vs[j][d2*2+1] = vf.y;
    }
    __syncthreads();
    int tid = threadIdx.x;
    if (tid >= 147) return;
    int i0 = 2*tid, i1 = i0 + 1;
    int tt0 = i0 / PP, p0 = i0 % PP;
    int tt1 = i1 / PP, p1 = i1 % PP;
    size_t q0 = ((size_t)(((b*NTP + tt0)*VV + v)*PP + p0))*INNER + h*DH;
    size_t q1 = ((size_t)(((b*NTP + tt1)*VV + v)*PP + p1))*INNER + h*DH;

    float da[NTP], db[NTP];
    #pragma unroll
    for (int j = 0; j < NTP; ++j) { da[j] = 0.f; db[j] = 0.f; }

    for (int dchunk = 0; dchunk < 4; ++dchunk) {
        int dbase = dchunk * 16;
        float qa[16], qb[16];
        {
            uint4 u0 = *(const uint4*)(g_q + q0 + dbase);
            uint4 u1 = *(const uint4*)(g_q + q0 + dbase + 8);
            uint4 w0 = *(const uint4*)(g_q + q1 + dbase);
            uint4 w1 = *(const uint4*)(g_q + q1 + dbase + 8);
            float2 f;
            f=u2f2(u0.x); qa[0]=f.x; qa[1]=f.y;  f=u2f2(u0.y); qa[2]=f.x; qa[3]=f.y;
            f=u2f2(u0.z); qa[4]=f.x; qa[5]=f.y;  f=u2f2(u0.w); qa[6]=f.x; qa[7]=f.y;
            f=u2f2(u1.x); qa[8]=f.x; qa[9]=f.y;  f=u2f2(u1.y); qa[10]=f.x; qa[11]=f.y;
            f=u2f2(u1.z); qa[12]=f.x; qa[13]=f.y; f=u2f2(u1.w); qa[14]=f.x; qa[15]=f.y;
            f=u2f2(w0.x); qb[0]=f.x; qb[1]=f.y;  f=u2f2(w0.y); qb[2]=f.x; qb[3]=f.y;
            f=u2f2(w0.z); qb[4]=f.x; qb[5]=f.y;  f=u2f2(w0.w); qb[6]=f.x; qb[7]=f.y;
            f=u2f2(w1.x); qb[8]=f.x; qb[9]=f.y;  f=u2f2(w1.y); qb[10]=f.x; qb[11]=f.y;
            f=u2f2(w1.z); qb[12]=f.x; qb[13]=f.y; f=u2f2(w1.w); qb[14]=f.x; qb[15]=f.y;
        }
        #pragma unroll
        for (int j = 0; j < NTP; ++j) {
            #pragma unroll
            for (int dd = 0; dd < 16; ++dd) {
                float kv = ks[j][dbase + dd];
                da[j] += qa[dd] * kv;
                db[j] += qb[dd] * kv;
            }
        }
    }
    {
        float mx = -1e30f;
        #pragma unroll
        for (int j = 0; j < NTP; ++j) { da[j] *= SCALE_ATT; mx = fmaxf(mx, da[j]); }
        float s = 0.f;
        #pragma unroll
        for (int j = 0; j < NTP; ++j) { da[j] = __expf(da[j] - mx); s += da[j]; }
        float inv = 1.f / s;
        #pragma unroll
        for (int j = 0; j < NTP; ++j) da[j] *= inv;
    }
    {
        float mx = -1e30f;
        #pragma unroll
        for (int j = 0; j < NTP; ++j) { db[j] *= SCALE_ATT; mx = fmaxf(mx, db[j]); }
        float s = 0.f;
        #pragma unroll
        for (int j = 0; j < NTP; ++j) { db[j] = __expf(db[j] - mx); s += db[j]; }
        float inv = 1.f / s;
        #pragma unroll
        for (int j = 0; j < NTP; ++j) db[j] *= inv;
    }
    size_t o0 = q0, o1 = q1;   // ao has same [N,512] layout
    for (int dchunk = 0; dchunk < 4; ++dchunk) {
        int dbase = dchunk * 16;
        float oa[16], ob[16];
        #pragma unroll
        for (int dd = 0; dd < 16; ++dd) { oa[dd] = 0.f; ob[dd] = 0.f; }
        #pragma unroll
        for (int j = 0; j < NTP; ++j) {
            #pragma unroll
            for (int dd = 0; dd < 16; ++dd) {
                float vv = vs[j][dbase + dd];
                oa[dd] += da[j] * vv;
                ob[dd] += db[j] * vv;
            }
        }
        #pragma unroll
        for (int dd = 0; dd < 16; dd += 2) {
            stbf2(g_ao + o0 + dbase + dd, make_float2(oa[dd], oa[dd+1]));
            stbf2(g_ao + o1 + dbase + dd, make_float2(ob[dd], ob[dd+1]));
        }
    }
}

// ---------------- launch -----------------------------------------------------
extern "C" void kernel_launch(void* const* d_in, const int* in_sizes, int n_in,
                              void* d_out, int out_size) {
    (void)in_sizes; (void)n_in; (void)out_size;
    float* p_xT;
    __nv_bfloat16 *p_xn, *p_qkv, *p_q, *p_kv, *p_ao, *p_wt;
    cudaGetSymbolAddress((void**)&p_xT,  g_xT);
    cudaGetSymbolAddress((void**)&p_xn,  g_xn);
    cudaGetSymbolAddress((void**)&p_qkv, g_qkv);
    cudaGetSymbolAddress((void**)&p_q,   g_q);
    cudaGetSymbolAddress((void**)&p_kv,  g_kv);
    cudaGetSymbolAddress((void**)&p_ao,  g_ao);
    cudaGetSymbolAddress((void**)&p_wt,  g_wt);

    cudaFuncSetAttribute(k_gemm_bf<0>, cudaFuncAttributeMaxDynamicSharedMemorySize, GEMM_SMEM);
    cudaFuncSetAttribute(k_gemm_bf<2>, cudaFuncAttributeMaxDynamicSharedMemorySize, GEMM_SMEM);
    cudaFuncSetAttribute(k_gemm_bf<3>, cudaFuncAttributeMaxDynamicSharedMemorySize, GEMM_SMEM);
    cudaFuncSetAttribute(k_qkv_attn,   cudaFuncAttributeMaxDynamicSharedMemorySize, ARES_SMEM);

    const float* x      = (const float*)d_in[0];
    const float* ln1_g  = (const float*)d_in[1];
    const float* ln1_b  = (const float*)d_in[2];
    const float* la_wq  = (const float*)d_in[3];
    const float* la_wkv = (const float*)d_in[4];
    const float* la_wo  = (const float*)d_in[5];
    const float* la_bo  = (const float*)d_in[6];
    const float* ln2_g  = (const float*)d_in[7];
    const float* ln2_b  = (const float*)d_in[8];
    const float* ff1_w1 = (const float*)d_in[9];
    const float* ff1_b1 = (const float*)d_in[10];
    const float* ff1_w2 = (const float*)d_in[11];
    const float* ff1_b2 = (const float*)d_in[12];
    const float* ln3_g  = (const float*)d_in[13];
    const float* ln3_b  = (const float*)d_in[14];
    const float* ga_wq  = (const float*)d_in[15];
    const float* ga_wkv = (const float*)d_in[16];
    const float* ga_wo  = (const float*)d_in[17];
    const float* ga_bo  = (const float*)d_in[18];
    const float* ln4_g  = (const float*)d_in[19];
    const float* ln4_b  = (const float*)d_in[20];
    const float* ff2_w1 = (const float*)d_in[21];
    const float* ff2_b1 = (const float*)d_in[22];
    const float* ff2_w2 = (const float*)d_in[23];
    const float* ff2_b2 = (const float*)d_in[24];

    for (int l = 0; l < 2; ++l) {
        k_wprep<<<4096, 256>>>(
            la_wq  + (size_t)l*CC*INNER,      la_wkv + (size_t)l*CC*2*INNER,
            la_wo  + (size_t)l*INNER*CC,      ff1_w1 + (size_t)l*CC*512,
            ff1_w2 + (size_t)l*512*CC,        ga_wq  + (size_t)l*CC*INNER,
            ga_wkv + (size_t)l*CC*PP*2*INNER, ga_wo  + (size_t)l*INNER*CC,
            ff2_w1 + (size_t)l*CC*512,        ff2_w2 + (size_t)l*512*CC,
            p_wt + (size_t)l*WT_LSZ);
    }

    const int rowTiles  = (NTOK  + 127) / 128;   // 919
    const int rowTilesG = (NKTOK + 127) / 128;   // 132
    const int qkvTiles  = (NTOK + 125) / 126;    // 934
    const int lnGrid = NTOK / 8;

    k_tin<<<BB*TT, 256>>>(x, ln1_g, ln1_b);

    for (int l = 0; l < 2; ++l) {
        __nv_bfloat16* wb = p_wt + (size_t)l*WT_LSZ;
        // --- local attention block (fused QKV GEMM + attention) ---
        k_qkv_attn<<<qkvTiles, 256, ARES_SMEM>>>(p_xn, wb + OFF_LQKV, p_qkv, p_ao);
        k_gemm_bf<3><<<dim3(1, rowTiles), 256, GEMM_SMEM>>>(
            p_ao, wb + OFF_LWO, la_bo + l*CC, p_xT, p_xT, NTOK, 512, 128);
        k_ln<<<lnGrid, 256>>>(ln2_g + l*CC, ln2_b + l*CC);
        // --- ff1 ---
        k_gemm_bf<2><<<dim3(4, rowTiles), 256, GEMM_SMEM>>>(
            p_xn, wb + OFF_F1A, ff1_b1 + l*512, nullptr, p_ao, NTOK, 128, 512);
        k_gemm_bf<3><<<dim3(1, rowTiles), 256, GEMM_SMEM>>>(
            p_ao, wb + OFF_F1B, ff1_b2 + l*CC, p_xT, p_xT, NTOK, 512, 128);
        k_ln<<<lnGrid, 256>>>(ln3_g + l*CC, ln3_b + l*CC);
        // --- global attention block (gather is identity in patch-major order) ---
        k_gemm_bf<0><<<dim3(4, rowTiles), 256, GEMM_SMEM>>>(
            p_xn, wb + OFF_GWQ, nullptr, nullptr, p_q, NTOK, 128, 512);
        k_gemm_bf<0><<<dim3(8, rowTilesG), 256, GEMM_SMEM>>>(
            p_xn, wb + OFF_GWKV, nullptr, nullptr, p_kv, NKTOK, 896, 1024);
        k_gattn<<<BB*NHEAD*VV, 160>>>();
        k_gemm_bf<3><<<dim3(1, rowTiles), 256, GEMM_SMEM>>>(
            p_ao, wb + OFF_GWO, ga_bo + l*CC, p_xT, p_xT, NTOK, 512, 128);
        k_ln<<<lnGrid, 256>>>(ln4_g + l*CC, ln4_b + l*CC);
        // --- ff2 ---
        k_gemm_bf<2><<<dim3(4, rowTiles), 256, GEMM_SMEM>>>(
            p_xn, wb + OFF_F2A, ff2_b1 + l*512, nullptr, p_ao, NTOK, 128, 512);
        k_gemm_bf<3><<<dim3(1, rowTiles), 256, GEMM_SMEM>>>(
            p_ao, wb + OFF_F2B, ff2_b2 + l*CC, p_xT, p_xT, NTOK, 512, 128);
        if (l == 0) k_ln<<<lnGrid, 256>>>(ln1_g + CC, ln1_b + CC);
    }
    k_tout<<<BB*TT, 256>>>((float*)d_out);
}

// round 13
// speedup vs baseline: 1.0228x; 1.0228x over previous
#include <cuda_runtime.h>
#include <cuda_bf16.h>
#include <math.h>
#include <stdint.h>

// ---------------- problem constants ----------------
#define BB     16
#define CC     128
#define TT     294
#define VV     25
#define NTOK   (BB*TT*VV)        // 117600 tokens
#define INNER  512
#define NHEAD  8
#define DH     64
#define PP     7
#define NTP    42                 // T / P
#define NKTOK  (BB*NTP*VV)        // 16800 kv tokens / patches
#define SCALE_ATT 0.125f
#define LN_EPS 1e-5f

// token order is PATCH-MAJOR: n' = ((b*NTP+tt)*VV + v)*7 + p   (t = tt*7+p)

// transposed bf16 weight layout (elements, per layer)
#define OFF_LQKV  0               // [1536,128]
#define OFF_LWO   196608          // [128,512]
#define OFF_F1A   262144          // [512,128]
#define OFF_F1B   327680          // [128,512]
#define OFF_GWQ   393216          // [512,128]
#define OFF_GWKV  458752          // [1024,896] (k index kp*128+c)
#define OFF_GWO   1376256         // [128,512]
#define OFF_F2A   1441792         // [512,128]
#define OFF_F2B   1507328         // [128,512]
#define WT_LSZ    1572864

// ---------------- scratch (static device memory; no allocs) ----------------
__device__ __align__(16) float          g_xT[NTOK*CC];          // residual, fp32
__device__ __align__(16) __nv_bfloat16  g_xn[NTOK*CC];          // LN output
__device__ __align__(16) __nv_bfloat16  g_qkv[(size_t)NTOK*1536];
__device__ __align__(16) __nv_bfloat16  g_q [NTOK*INNER];
__device__ __align__(16) __nv_bfloat16  g_kv[NKTOK*1024];
__device__ __align__(16) __nv_bfloat16  g_ao[NTOK*INNER];       // attn out / ff hidden
__device__ __align__(16) __nv_bfloat16  g_wt[2*WT_LSZ];

// ---------------- helpers ----------------
__device__ __forceinline__ uint32_t smem_u32(const void* p) {
    uint32_t a;
    asm("{ .reg .u64 t; cvta.to.shared.u64 t, %1; cvt.u32.u64 %0, t; }" : "=r"(a) : "l"(p));
    return a;
}
__device__ __forceinline__ float2 ldbf2(const __nv_bfloat16* p) {
    return __bfloat1622float2(*reinterpret_cast<const __nv_bfloat162*>(p));
}
__device__ __forceinline__ void stbf2(__nv_bfloat16* p, float2 v) {
    *reinterpret_cast<__nv_bfloat162*>(p) = __float22bfloat162_rn(v);
}
__device__ __forceinline__ float2 u2f2(uint32_t u) {
    return __bfloat1622float2(*reinterpret_cast<const __nv_bfloat162*>(&u));
}
__device__ __forceinline__ void mma_bf16(float* d, const uint32_t* a, const uint32_t* b) {
    asm volatile(
        "mma.sync.aligned.m16n8k16.row.col.f32.bf16.bf16.f32 "
        "{%0,%1,%2,%3}, {%4,%5,%6,%7}, {%8,%9}, {%0,%1,%2,%3};"
        : "+f"(d[0]), "+f"(d[1]), "+f"(d[2]), "+f"(d[3])
        : "r"(a[0]), "r"(a[1]), "r"(a[2]), "r"(a[3]), "r"(b[0]), "r"(b[1]));
}
__device__ __forceinline__ float gelu_exact(float v) {
    return 0.5f * v * (1.0f + erff(v * 0.7071067811865475f));
}

// ---------------- transpose in + fused LN(layer0,ln1), patch-major ---------
__global__ void k_tin(const float* __restrict__ x,
                      const float* __restrict__ gam, const float* __restrict__ bet) {
    int bt = blockIdx.x;
    int t = bt % TT, b = bt / TT;
    int tt = t / PP, p = t % PP;
    size_t nbase = ((size_t)(b*NTP + tt)*VV)*PP + p;
    __shared__ float sm[CC*VV];
    for (int idx = threadIdx.x; idx < CC*VV; idx += blockDim.x) {
        int c = idx / VV, v = idx % VV;
        sm[idx] = x[(((size_t)b*CC + c)*TT + t)*VV + v];
    }
    __syncthreads();
    for (int idx = threadIdx.x; idx < CC*VV; idx += blockDim.x) {
        int v = idx / CC, c = idx % CC;
        g_xT[(nbase + (size_t)v*PP)*CC + c] = sm[c*VV + v];
    }
    int wid = threadIdx.x >> 5, lane = threadIdx.x & 31;
    int c0 = lane * 4;
    float4 gg = *(const float4*)(gam + c0);
    float4 bb = *(const float4*)(bet + c0);
    for (int v = wid; v < VV; v += 8) {
        float f0 = sm[(c0+0)*VV + v], f1 = sm[(c0+1)*VV + v];
        float f2 = sm[(c0+2)*VV + v], f3 = sm[(c0+3)*VV + v];
        float s = f0+f1+f2+f3, ss = f0*f0+f1*f1+f2*f2+f3*f3;
        #pragma unroll
        for (int o = 16; o; o >>= 1) {
            s  += __shfl_xor_sync(0xffffffffu, s,  o);
            ss += __shfl_xor_sync(0xffffffffu, ss, o);
        }
        float m = s*(1.f/128.f), var = ss*(1.f/128.f) - m*m;
        float r = rsqrtf(var + LN_EPS);
        __nv_bfloat16* dst = g_xn + (nbase + (size_t)v*PP)*CC + c0;
        stbf2(dst,     make_float2((f0-m)*r*gg.x + bb.x, (f1-m)*r*gg.y + bb.y));
        stbf2(dst + 2, make_float2((f2-m)*r*gg.z + bb.z, (f3-m)*r*gg.w + bb.w));
    }
}

__global__ void k_tout(float* __restrict__ out) {
    int bt = blockIdx.x;
    int t = bt % TT, b = bt / TT;
    int tt = t / PP, p = t % PP;
    size_t nbase = ((size_t)(b*NTP + tt)*VV)*PP + p;
    __shared__ float sm[CC*VV];
    for (int idx = threadIdx.x; idx < CC*VV; idx += blockDim.x) {
        int v = idx / CC, c = idx % CC;
        sm[v*CC + c] = g_xT[(nbase + (size_t)v*PP)*CC + c];
    }
    __syncthreads();
    for (int idx = threadIdx.x; idx < CC*VV; idx += blockDim.x) {
        int c = idx / VV, v = idx % VV;
        out[(((size_t)b*CC + c)*TT + t)*VV + v] = sm[v*CC + c];
    }
}

// ---------------- weight prep: one launch per layer ------------------------
__global__ void k_wprep(const float* __restrict__ wq,  const float* __restrict__ wkv,
                        const float* __restrict__ wo,  const float* __restrict__ f1a,
                        const float* __restrict__ f1b, const float* __restrict__ gwq,
                        const float* __restrict__ gwkv,const float* __restrict__ gwo,
                        const float* __restrict__ f2a, const float* __restrict__ f2b,
                        __nv_bfloat16* __restrict__ dst)
{
    for (int idx = blockIdx.x*256 + threadIdx.x; idx < WT_LSZ; idx += gridDim.x*256) {
        float v;
        if (idx < OFF_LWO) {
            int m = idx >> 7, k = idx & 127;
            v = (m < 512) ? wq[k*512 + m] : wkv[k*1024 + (m-512)];
        } else if (idx < OFF_F1A) {
            int r = idx - OFF_LWO; int m = r >> 9, k = r & 511; v = wo[k*128 + m];
        } else if (idx < OFF_F1B) {
            int r = idx - OFF_F1A; int m = r >> 7, k = r & 127; v = f1a[k*512 + m];
        } else if (idx < OFF_GWQ) {
            int r = idx - OFF_F1B; int m = r >> 9, k = r & 511; v = f1b[k*128 + m];
        } else if (idx < OFF_GWKV) {
            int r = idx - OFF_GWQ; int m = r >> 7, k = r & 127; v = gwq[k*512 + m];
        } else if (idx < OFF_GWO) {
            int r = idx - OFF_GWKV; int i = r / 896; int kk = r - i*896;
            int kp = kk >> 7, c = kk & 127;
            v = gwkv[(c*PP + kp)*1024 + i];
        } else if (idx < OFF_F2A) {
            int r = idx - OFF_GWO; int m = r >> 9, k = r & 511; v = gwo[k*128 + m];
        } else if (idx < OFF_F2B) {
            int r = idx - OFF_F2A; int m = r >> 7, k = r & 127; v = f2a[k*512 + m];
        } else {
            int r = idx - OFF_F2B; int m = r >> 9, k = r & 511; v = f2b[k*128 + m];
        }
        dst[idx] = __float2bfloat16(v);
    }
}

// ---------------- channel layernorm: fp32 in, bf16 out ----------------
__global__ void __launch_bounds__(256) k_ln(const float* __restrict__ gam,
                                            const float* __restrict__ bet) {
    int n = blockIdx.x * 8 + (threadIdx.x >> 5);
    if (n >= NTOK) return;
    int lane = threadIdx.x & 31;
    float4 a = ((const float4*)(g_xT + (size_t)n*CC))[lane];
    float s  = a.x + a.y + a.z + a.w;
    float ss = a.x*a.x + a.y*a.y + a.z*a.z + a.w*a.w;
    #pragma unroll
    for (int o = 16; o; o >>= 1) {
        s  += __shfl_xor_sync(0xffffffffu, s,  o);
        ss += __shfl_xor_sync(0xffffffffu, ss, o);
    }
    float m   = s * (1.f/128.f);
    float var = ss * (1.f/128.f) - m*m;
    float r   = rsqrtf(var + LN_EPS);
    float4 gg = ((const float4*)gam)[lane];
    float4 bb = ((const float4*)bet)[lane];
    float2 p0 = make_float2((a.x - m)*r*gg.x + bb.x, (a.y - m)*r*gg.y + bb.y);
    float2 p1 = make_float2((a.z - m)*r*gg.z + bb.z, (a.w - m)*r*gg.w + bb.w);
    uint2 st;
    __nv_bfloat162 h0 = __float22bfloat162_rn(p0);
    __nv_bfloat162 h1 = __float22bfloat162_rn(p1);
    st.x = *reinterpret_cast<uint32_t*>(&h0);
    st.y = *reinterpret_cast<uint32_t*>(&h1);
    *reinterpret_cast<uint2*>(g_xn + (size_t)n*CC + lane*4) = st;
}

// ---------------- bf16 mma GEMM (R6-proven): C[N,M] = A[N,K] @ Wt[M,K]^T ---
// 128x128 CTA tile, K-tile 32, 4-stage cp.async ring, 2 CTAs/SM.
// EPI: 0 none (bf16 out), 2 bias+gelu (bf16 out), 3 bias+residual (fp32 out)
#define GSTAGE_BYTES 16384
#define GEMM_SMEM   (4*GSTAGE_BYTES)

template<int EPI>
__global__ void __launch_bounds__(256, 2) k_gemm_bf(
    const __nv_bfloat16* __restrict__ A, const __nv_bfloat16* __restrict__ Wt,
    const float* __restrict__ bias, const float* __restrict__ res,
    void* __restrict__ Cv, int Nrows, int K, int M)
{
    extern __shared__ char smraw[];
    const uint32_t smb = smem_u32(smraw);

    const int t = threadIdx.x;
    const int lane = t & 31, wid = t >> 5;
    const int wr = wid & 1, wc = wid >> 1;
    const int rowBase = blockIdx.y << 7, colBase = blockIdx.x << 7;

    const int rL = t >> 1, half = t & 1;
    int ga = rowBase + rL; if (ga >= Nrows) ga = Nrows - 1;
    const __nv_bfloat16* aP = A  + (size_t)ga * K + (half << 4);
    const __nv_bfloat16* bP = Wt + (size_t)(colBase + rL) * K + (half << 4);
    const int fL = (rL >> 1) & 3;
    const uint32_t dA = rL*64 + 16*((2*half) ^ fL);
    const uint32_t dB = 8192 + dA;

    const int rA  = (lane & 7) + ((lane >> 3) & 1) * 8;
    const int ca  = lane >> 4;
    const int fra = (rA >> 1) & 3;
    const int g   = lane >> 3;
    const int nB  = ((g >> 1) & 1) * 8 + (lane & 7);
    const int cb  = g & 1;
    const int fnb = (nB >> 1) & 3;

    float acc[4][4][4];
    #pragma unroll
    for (int mt = 0; mt < 4; ++mt)
        #pragma unroll
        for (int nt = 0; nt < 4; ++nt)
            #pragma unroll
            for (int e = 0; e < 4; ++e) acc[mt][nt][e] = 0.f;

    const int nk = K >> 5;

    #define G_ISSUE(kt_) do {                                                   \
        const uint32_t st_ = smb + ((kt_) & 3) * GSTAGE_BYTES;                   \
        size_t sa_ = __cvta_generic_to_global(aP + ((kt_) << 5));                \
        size_t sb_ = __cvta_generic_to_global(bP + ((kt_) << 5));                \
        uint32_t a1_ = st_ + dA, b1_ = st_ + dB;                                 \
        asm volatile("cp.async.cg.shared.global [%0], [%1], 16;" :: "r"(a1_), "l"(sa_)); \
        asm volatile("cp.async.cg.shared.global [%0], [%1], 16;" :: "r"(a1_ ^ 16u), "l"(sa_ + 16)); \
        asm volatile("cp.async.cg.shared.global [%0], [%1], 16;" :: "r"(b1_), "l"(sb_)); \
        asm volatile("cp.async.cg.shared.global [%0], [%1], 16;" :: "r"(b1_ ^ 16u), "l"(sb_ + 16)); \
    } while (0)

    G_ISSUE(0); asm volatile("cp.async.commit_group;");
    G_ISSUE(1); asm volatile("cp.async.commit_group;");
    G_ISSUE(2); asm volatile("cp.async.commit_group;");

    for (int kt = 0; kt < nk; ++kt) {
        asm volatile("cp.async.wait_group 2;");
        __syncthreads();
        if (kt + 3 < nk) G_ISSUE(kt + 3);
        asm volatile("cp.async.commit_group;");

        const uint32_t stA = smb + (kt & 3) * GSTAGE_BYTES;
        const uint32_t stB = stA + 8192;
        #pragma unroll
        for (int ks = 0; ks < 2; ++ks) {
            uint32_t af[4][4], bf[4][2];
            #pragma unroll
            for (int mt = 0; mt < 4; ++mt) {
                uint32_t addr = stA + (uint32_t)((wr*64 + mt*16 + rA)*64)
                              + 16u*(uint32_t)(((ks<<1) + ca) ^ fra);
                asm volatile("ldmatrix.sync.aligned.m8n8.x4.shared.b16 {%0,%1,%2,%3}, [%4];"
                    : "=r"(af[mt][0]), "=r"(af[mt][1]), "=r"(af[mt][2]), "=r"(af[mt][3])
                    : "r"(addr));
            }
            #pragma unroll
            for (int j = 0; j < 2; ++j) {
                int n = wc*32 + j*16 + nB;
                uint32_t addr = stB + (uint32_t)(n*64)
                              + 16u*(uint32_t)(((ks<<1) + cb) ^ fnb);
                asm volatile("ldmatrix.sync.aligned.m8n8.x4.shared.b16 {%0,%1,%2,%3}, [%4];"
                    : "=r"(bf[2*j][0]), "=r"(bf[2*j][1]), "=r"(bf[2*j+1][0]), "=r"(bf[2*j+1][1])
                    : "r"(addr));
            }
            #pragma unroll
            for (int mt = 0; mt < 4; ++mt)
                #pragma unroll
                for (int nt = 0; nt < 4; ++nt)
                    mma_bf16(acc[mt][nt], af[mt], bf[nt]);
        }
    }
    #undef G_ISSUE

    #pragma unroll
    for (int nt = 0; nt < 4; ++nt) {
        const int col = colBase + wc*32 + nt*8 + (lane & 3)*2;
        float2 bb = make_float2(0.f, 0.f);
        if (EPI >= 1) bb = *(const float2*)(bias + col);
        #pragma unroll
        for (int mt = 0; mt < 4; ++mt) {
            #pragma unroll
            for (int hf = 0; hf < 2; ++hf) {
                const int r = rowBase + wr*64 + mt*16 + (lane >> 2) + hf*8;
                if (r >= Nrows) continue;
                float2 o = make_float2(acc[mt][nt][hf*2+0] + bb.x,
                                       acc[mt][nt][hf*2+1] + bb.y);
                if (EPI == 2) { o.x = gelu_exact(o.x); o.y = gelu_exact(o.y); }
                if (EPI == 3) {
                    float2 rv = *(const float2*)(res + (size_t)r*M + col);
                    o.x += rv.x; o.y += rv.y;
                    *(float2*)((float*)Cv + (size_t)r*M + col) = o;
                } else {
                    stbf2((__nv_bfloat16*)Cv + (size_t)r*M + col, o);
                }
            }
        }
    }
}

// ---------------- local attention: warp per (patch, head), patch-major -----
__global__ void __launch_bounds__(256) k_lattn() {
    int w = blockIdx.x * 8 + (threadIdx.x >> 5);   // 0 .. 134399
    int lane = threadIdx.x & 31;
    int h = w & 7;
    int patch = w >> 3;                            // 0 .. 16799
    int base = patch * PP;                         // contiguous 7 rows
    int d0 = lane * 2;

    float2 q[PP], kk[PP], vv[PP];
    #pragma unroll
    for (int p = 0; p < PP; ++p) {
        const __nv_bfloat16* rowp = g_qkv + (size_t)(base + p)*1536 + h*DH + d0;
        q[p]  = ldbf2(rowp);
        kk[p] = ldbf2(rowp + 512);
        vv[p] = ldbf2(rowp + 1024);
    }
    float dots[PP][PP];
    #pragma unroll
    for (int i = 0; i < PP; ++i)
        #pragma unroll
        for (int j = 0; j < PP; ++j)
            dots[i][j] = q[i].x*kk[j].x + q[i].y*kk[j].y;
    #pragma unroll
    for (int o = 16; o; o >>= 1)
        #pragma unroll
        for (int i = 0; i < PP; ++i)
            #pragma unroll
            for (int j = 0; j < PP; ++j)
                dots[i][j] += __shfl_xor_sync(0xffffffffu, dots[i][j], o);
    #pragma unroll
    for (int i = 0; i < PP; ++i) {
        float mx = -1e30f;
        #pragma unroll
        for (int j = 0; j < PP; ++j) {
            dots[i][j] *= SCALE_ATT;
            mx = fmaxf(mx, dots[i][j]);
        }
        float s = 0.f;
        #pragma unroll
        for (int j = 0; j < PP; ++j) { dots[i][j] = __expf(dots[i][j] - mx); s += dots[i][j]; }
        float inv = 1.f / s;
        #pragma unroll
        for (int j = 0; j < PP; ++j) dots[i][j] *= inv;
    }
    #pragma unroll
    for (int i = 0; i < PP; ++i) {
        float2 o = make_float2(0.f, 0.f);
        #pragma unroll
        for (int j = 0; j < PP; ++j) {
            o.x += dots[i][j] * vv[j].x;
            o.y += dots[i][j] * vv[j].y;
        }
        stbf2(g_ao + (size_t)(base + i)*INNER + h*DH + d0, o);
    }
}

// ---------------- global attention: one block per (b, h, v), patch-major ----
__global__ void __launch_bounds__(160) k_gattn() {
    int bid = blockIdx.x;
    int v = bid % VV;
    int rr = bid / VV;
    int h = rr & 7;
    int b = rr >> 3;
    __shared__ float ks[NTP][DH];
    __shared__ float vs[NTP][DH];
    for (int idx = threadIdx.x; idx < NTP*DH/2; idx += 160) {
        int j = idx >> 5, d2 = idx & 31;
        int nk = (b*NTP + j)*VV + v;
        size_t o = (size_t)nk*1024 + h*DH + d2*2;
        float2 kf = ldbf2(g_kv + o);
        float2 vf = ldbf2(g_kv + o + 512);
        ks[j][d2*2] = kf.x; ks[j][d2*2+1] = kf.y;
        vs[j][d2*2] = vf.x; vs[j][d2*2+1] = vf.y;
    }
    __syncthreads();
    int tid = threadIdx.x;
    if (tid >= 147) return;
    int i0 = 2*tid, i1 = i0 + 1;
    int tt0 = i0 / PP, p0 = i0 % PP;
    int tt1 = i1 / PP, p1 = i1 % PP;
    size_t q0 = ((size_t)(((b*NTP + tt0)*VV + v)*PP + p0))*INNER + h*DH;
    size_t q1 = ((size_t)(((b*NTP + tt1)*VV + v)*PP + p1))*INNER + h*DH;

    float da[NTP], db[NTP];
    #pragma unroll
    for (int j = 0; j < NTP; ++j) { da[j] = 0.f; db[j] = 0.f; }

    for (int dchunk = 0; dchunk < 4; ++dchunk) {
        int dbase = dchunk * 16;
        float qa[16], qb[16];
        {
            uint4 u0 = *(const uint4*)(g_q + q0 + dbase);
            uint4 u1 = *(const uint4*)(g_q + q0 + dbase + 8);
            uint4 w0 = *(const uint4*)(g_q + q1 + dbase);
            uint4 w1 = *(const uint4*)(g_q + q1 + dbase + 8);
            float2 f;
            f=u2f2(u0.x); qa[0]=f.x; qa[1]=f.y;  f=u2f2(u0.y); qa[2]=f.x; qa[3]=f.y;
            f=u2f2(u0.z); qa[4]=f.x; qa[5]=f.y;  f=u2f2(u0.w); qa[6]=f.x; qa[7]=f.y;
            f=u2f2(u1.x); qa[8]=f.x; qa[9]=f.y;  f=u2f2(u1.y); qa[10]=f.x; qa[11]=f.y;
            f=u2f2(u1.z); qa[12]=f.x; qa[13]=f.y; f=u2f2(u1.w); qa[14]=f.x; qa[15]=f.y;
            f=u2f2(w0.x); qb[0]=f.x; qb[1]=f.y;  f=u2f2(w0.y); qb[2]=f.x; qb[3]=f.y;
            f=u2f2(w0.z); qb[4]=f.x; qb[5]=f.y;  f=u2f2(w0.w); qb[6]=f.x; qb[7]=f.y;
            f=u2f2(w1.x); qb[8]=f.x; qb[9]=f.y;  f=u2f2(w1.y); qb[10]=f.x; qb[11]=f.y;
            f=u2f2(w1.z); qb[12]=f.x; qb[13]=f.y; f=u2f2(w1.w); qb[14]=f.x; qb[15]=f.y;
        }
        #pragma unroll
        for (int j = 0; j < NTP; ++j) {
            #pragma unroll
            for (int dd = 0; dd < 16; ++dd) {
                float kv = ks[j][dbase + dd];
                da[j] += qa[dd] * kv;
                db[j] += qb[dd] * kv;
            }
        }
    }
    {
        float mx = -1e30f;
        #pragma unroll
        for (int j = 0; j < NTP; ++j) { da[j] *= SCALE_ATT; mx = fmaxf(mx, da[j]); }
        float s = 0.f;
        #pragma unroll
        for (int j = 0; j < NTP; ++j) { da[j] = __expf(da[j] - mx); s += da[j]; }
        float inv = 1.f / s;
        #pragma unroll
        for (int j = 0; j < NTP; ++j) da[j] *= inv;
    }
    {
        float mx = -1e30f;
        #pragma unroll
        for (int j = 0; j < NTP; ++j) { db[j] *= SCALE_ATT; mx = fmaxf(mx, db[j]); }
        float s = 0.f;
        #pragma unroll
        for (int j = 0; j < NTP; ++j) { db[j] = __expf(db[j] - mx); s += db[j]; }
        float inv = 1.f / s;
        #pragma unroll
        for (int j = 0; j < NTP; ++j) db[j] *= inv;
    }
    size_t o0 = q0, o1 = q1;   // ao has same [N,512] layout
    for (int dchunk = 0; dchunk < 4; ++dchunk) {
        int dbase = dchunk * 16;
        float oa[16], ob[16];
        #pragma unroll
        for (int dd = 0; dd < 16; ++dd) { oa[dd] = 0.f; ob[dd] = 0.f; }
        #pragma unroll
        for (int j = 0; j < NTP; ++j) {
            #pragma unroll
            for (int dd = 0; dd < 16; ++dd) {
                float vv = vs[j][dbase + dd];
                oa[dd] += da[j] * vv;
                ob[dd] += db[j] * vv;
            }
        }
        #pragma unroll
        for (int dd = 0; dd < 16; dd += 2) {
            stbf2(g_ao + o0 + dbase + dd, make_float2(oa[dd], oa[dd+1]));
            stbf2(g_ao + o1 + dbase + dd, make_float2(ob[dd], ob[dd+1]));
        }
    }
}

// ---------------- launch -----------------------------------------------------
extern "C" void kernel_launch(void* const* d_in, const int* in_sizes, int n_in,
                              void* d_out, int out_size) {
    (void)in_sizes; (void)n_in; (void)out_size;
    float* p_xT;
    __nv_bfloat16 *p_xn, *p_qkv, *p_q, *p_kv, *p_ao, *p_wt;
    cudaGetSymbolAddress((void**)&p_xT,  g_xT);
    cudaGetSymbolAddress((void**)&p_xn,  g_xn);
    cudaGetSymbolAddress((void**)&p_qkv, g_qkv);
    cudaGetSymbolAddress((void**)&p_q,   g_q);
    cudaGetSymbolAddress((void**)&p_kv,  g_kv);
    cudaGetSymbolAddress((void**)&p_ao,  g_ao);
    cudaGetSymbolAddress((void**)&p_wt,  g_wt);

    cudaFuncSetAttribute(k_gemm_bf<0>, cudaFuncAttributeMaxDynamicSharedMemorySize, GEMM_SMEM);
    cudaFuncSetAttribute(k_gemm_bf<2>, cudaFuncAttributeMaxDynamicSharedMemorySize, GEMM_SMEM);
    cudaFuncSetAttribute(k_gemm_bf<3>, cudaFuncAttributeMaxDynamicSharedMemorySize, GEMM_SMEM);

    const float* x      = (const float*)d_in[0];
    const float* ln1_g  = (const float*)d_in[1];
    const float* ln1_b  = (const float*)d_in[2];
    const float* la_wq  = (const float*)d_in[3];
    const float* la_wkv = (const float*)d_in[4];
    const float* la_wo  = (const float*)d_in[5];
    const float* la_bo  = (const float*)d_in[6];
    const float* ln2_g  = (const float*)d_in[7];
    const float* ln2_b  = (const float*)d_in[8];
    const float* ff1_w1 = (const float*)d_in[9];
    const float* ff1_b1 = (const float*)d_in[10];
    const float* ff1_w2 = (const float*)d_in[11];
    const float* ff1_b2 = (const float*)d_in[12];
    const float* ln3_g  = (const float*)d_in[13];
    const float* ln3_b  = (const float*)d_in[14];
    const float* ga_wq  = (const float*)d_in[15];
    const float* ga_wkv = (const float*)d_in[16];
    const float* ga_wo  = (const float*)d_in[17];
    const float* ga_bo  = (const float*)d_in[18];
    const float* ln4_g  = (const float*)d_in[19];
    const float* ln4_b  = (const float*)d_in[20];
    const float* ff2_w1 = (const float*)d_in[21];
    const float* ff2_b1 = (const float*)d_in[22];
    const float* ff2_w2 = (const float*)d_in[23];
    const float* ff2_b2 = (const float*)d_in[24];

    for (int l = 0; l < 2; ++l) {
        k_wprep<<<4096, 256>>>(
            la_wq  + (size_t)l*CC*INNER,      la_wkv + (size_t)l*CC*2*INNER,
            la_wo  + (size_t)l*INNER*CC,      ff1_w1 + (size_t)l*CC*512,
            ff1_w2 + (size_t)l*512*CC,        ga_wq  + (size_t)l*CC*INNER,
            ga_wkv + (size_t)l*CC*PP*2*INNER, ga_wo  + (size_t)l*INNER*CC,
            ff2_w1 + (size_t)l*CC*512,        ff2_w2 + (size_t)l*512*CC,
            p_wt + (size_t)l*WT_LSZ);
    }

    const int rowTiles  = (NTOK  + 127) / 128;   // 919
    const int rowTilesG = (NKTOK + 127) / 128;   // 132
    const int lnGrid = NTOK / 8;

    k_tin<<<BB*TT, 256>>>(x, ln1_g, ln1_b);

    for (int l = 0; l < 2; ++l) {
        __nv_bfloat16* wb = p_wt + (size_t)l*WT_LSZ;
        // --- local attention block ---
        k_gemm_bf<0><<<dim3(12, rowTiles), 256, GEMM_SMEM>>>(
            p_xn, wb + OFF_LQKV, nullptr, nullptr, p_qkv, NTOK, 128, 1536);
        k_lattn<<<NKTOK, 256>>>();
        k_gemm_bf<3><<<dim3(1, rowTiles), 256, GEMM_SMEM>>>(
            p_ao, wb + OFF_LWO, la_bo + l*CC, p_xT, p_xT, NTOK, 512, 128);
        k_ln<<<lnGrid, 256>>>(ln2_g + l*CC, ln2_b + l*CC);
        // --- ff1 ---
        k_gemm_bf<2><<<dim3(4, rowTiles), 256, GEMM_SMEM>>>(
            p_xn, wb + OFF_F1A, ff1_b1 + l*512, nullptr, p_ao, NTOK, 128, 512);
        k_gemm_bf<3><<<dim3(1, rowTiles), 256, GEMM_SMEM>>>(
            p_ao, wb + OFF_F1B, ff1_b2 + l*CC, p_xT, p_xT, NTOK, 512, 128);
        k_ln<<<lnGrid, 256>>>(ln3_g + l*CC, ln3_b + l*CC);
        // --- global attention block (gather identity in patch-major order) ---
        k_gemm_bf<0><<<dim3(4, rowTiles), 256, GEMM_SMEM>>>(
            p_xn, wb + OFF_GWQ, nullptr, nullptr, p_q, NTOK, 128, 512);
        k_gemm_bf<0><<<dim3(8, rowTilesG), 256, GEMM_SMEM>>>(
            p_xn, wb + OFF_GWKV, nullptr, nullptr, p_kv, NKTOK, 896, 1024);
        k_gattn<<<BB*NHEAD*VV, 160>>>();
        k_gemm_bf<3><<<dim3(1, rowTiles), 256, GEMM_SMEM>>>(
            p_ao, wb + OFF_GWO, ga_bo + l*CC, p_xT, p_xT, NTOK, 512, 128);
        k_ln<<<lnGrid, 256>>>(ln4_g + l*CC, ln4_b + l*CC);
        // --- ff2 ---
        k_gemm_bf<2><<<dim3(4, rowTiles), 256, GEMM_SMEM>>>(
            p_xn, wb + OFF_F2A, ff2_b1 + l*512, nullptr, p_ao, NTOK, 128, 512);
        k_gemm_bf<3><<<dim3(1, rowTiles), 256, GEMM_SMEM>>>(
            p_ao, wb + OFF_F2B, ff2_b2 + l*CC, p_xT, p_xT, NTOK, 512, 128);
        if (l == 0) k_ln<<<lnGrid, 256>>>(ln1_g + CC, ln1_b + CC);
    }
    k_tout<<<BB*TT, 256>>>((float*)d_out);
}

// round 14
// speedup vs baseline: 1.0345x; 1.0115x over previous
#include <cuda_runtime.h>
#include <cuda_bf16.h>
#include <math.h>
#include <stdint.h>

// ---------------- problem constants ----------------
#define BB     16
#define CC     128
#define TT     294
#define VV     25
#define NTOK   (BB*TT*VV)        // 117600 tokens
#define INNER  512
#define NHEAD  8
#define DH     64
#define PP     7
#define NTP    42                 // T / P
#define NKTOK  (BB*NTP*VV)        // 16800 kv tokens (global)
#define SCALE_ATT 0.125f
#define LN_EPS 1e-5f

// transposed bf16 weight layout (elements, per layer)
#define OFF_LQKV  0               // [1536,128]
#define OFF_LWO   196608          // [128,512]
#define OFF_F1A   262144          // [512,128]
#define OFF_F1B   327680          // [128,512]
#define OFF_GWQ   393216          // [512,128]
#define OFF_GWKV  458752          // [1024,896] (k reordered kp*128+c)
#define OFF_GWO   1376256         // [128,512]
#define OFF_F2A   1441792         // [512,128]
#define OFF_F2B   1507328         // [128,512]
#define WT_LSZ    1572864

// ---------------- scratch (static device memory; no allocs) ----------------
__device__ __align__(16) float          g_xT[NTOK*CC];          // residual, fp32
__device__ __align__(16) __nv_bfloat16  g_xn[NTOK*CC];          // LN output
__device__ __align__(16) __nv_bfloat16  g_qkv[(size_t)NTOK*1536];
__device__ __align__(16) __nv_bfloat16  g_q [NTOK*INNER];
__device__ __align__(16) __nv_bfloat16  g_kv[NKTOK*1024];
__device__ __align__(16) __nv_bfloat16  g_ao[NTOK*INNER];       // attn out / ff hidden
__device__ __align__(16) __nv_bfloat16  g_xg[NKTOK*896];
__device__ __align__(16) __nv_bfloat16  g_wt[2*WT_LSZ];

// ---------------- helpers ----------------
__device__ __forceinline__ uint32_t smem_u32(const void* p) {
    uint32_t a;
    asm("{ .reg .u64 t; cvta.to.shared.u64 t, %1; cvt.u32.u64 %0, t; }" : "=r"(a) : "l"(p));
    return a;
}
__device__ __forceinline__ float2 ldbf2(const __nv_bfloat16* p) {
    return __bfloat1622float2(*reinterpret_cast<const __nv_bfloat162*>(p));
}
__device__ __forceinline__ void stbf2(__nv_bfloat16* p, float2 v) {
    *reinterpret_cast<__nv_bfloat162*>(p) = __float22bfloat162_rn(v);
}
__device__ __forceinline__ float2 u2f2(uint32_t u) {
    return __bfloat1622float2(*reinterpret_cast<const __nv_bfloat162*>(&u));
}
__device__ __forceinline__ void mma_bf16(float* d, const uint32_t* a, const uint32_t* b) {
    asm volatile(
        "mma.sync.aligned.m16n8k16.row.col.f32.bf16.bf16.f32 "
        "{%0,%1,%2,%3}, {%4,%5,%6,%7}, {%8,%9}, {%0,%1,%2,%3};"
        : "+f"(d[0]), "+f"(d[1]), "+f"(d[2]), "+f"(d[3])
        : "r"(a[0]), "r"(a[1]), "r"(a[2]), "r"(a[3]), "r"(b[0]), "r"(b[1]));
}
__device__ __forceinline__ float gelu_exact(float v) {
    return 0.5f * v * (1.0f + erff(v * 0.7071067811865475f));
}

// ---------------- transpose in: x[B,C,T,V] -> xT[(b t v), c] ----------------
__global__ void k_tin(const float* __restrict__ x) {
    int bt = blockIdx.x;
    int t = bt % TT, b = bt / TT;
    __shared__ float sm[CC*VV];
    for (int idx = threadIdx.x; idx < CC*VV; idx += blockDim.x) {
        int c = idx / VV, v = idx % VV;
        sm[idx] = x[(((size_t)b*CC + c)*TT + t)*VV + v];
    }
    __syncthreads();
    size_t base = ((size_t)(b*TT + t))*VV*CC;
    for (int idx = threadIdx.x; idx < CC*VV; idx += blockDim.x) {
        int v = idx / CC, c = idx % CC;
        g_xT[base + idx] = sm[c*VV + v];
    }
}

__global__ void k_tout(float* __restrict__ out) {
    int bt = blockIdx.x;
    int t = bt % TT, b = bt / TT;
    __shared__ float sm[CC*VV];
    size_t base = ((size_t)(b*TT + t))*VV*CC;
    for (int idx = threadIdx.x; idx < CC*VV; idx += blockDim.x)
        sm[idx] = g_xT[base + idx];
    __syncthreads();
    for (int idx = threadIdx.x; idx < CC*VV; idx += blockDim.x) {
        int c = idx / VV, v = idx % VV;
        out[(((size_t)b*CC + c)*TT + t)*VV + v] = sm[v*CC + c];
    }
}

// ---------------- weight prep: one launch per layer ------------------------
__global__ void k_wprep(const float* __restrict__ wq,  const float* __restrict__ wkv,
                        const float* __restrict__ wo,  const float* __restrict__ f1a,
                        const float* __restrict__ f1b, const float* __restrict__ gwq,
                        const float* __restrict__ gwkv,const float* __restrict__ gwo,
                        const float* __restrict__ f2a, const float* __restrict__ f2b,
                        __nv_bfloat16* __restrict__ dst)
{
    for (int idx = blockIdx.x*256 + threadIdx.x; idx < WT_LSZ; idx += gridDim.x*256) {
        float v;
        if (idx < OFF_LWO) {
            int m = idx >> 7, k = idx & 127;
            v = (m < 512) ? wq[k*512 + m] : wkv[k*1024 + (m-512)];
        } else if (idx < OFF_F1A) {
            int r = idx - OFF_LWO; int m = r >> 9, k = r & 511; v = wo[k*128 + m];
        } else if (idx < OFF_F1B) {
            int r = idx - OFF_F1A; int m = r >> 7, k = r & 127; v = f1a[k*512 + m];
        } else if (idx < OFF_GWQ) {
            int r = idx - OFF_F1B; int m = r >> 9, k = r & 511; v = f1b[k*128 + m];
        } else if (idx < OFF_GWKV) {
            int r = idx - OFF_GWQ; int m = r >> 7, k = r & 127; v = gwq[k*512 + m];
        } else if (idx < OFF_GWO) {
            int r = idx - OFF_GWKV; int i = r / 896; int kk = r - i*896;
            int kp = kk >> 7, c = kk & 127;
            v = gwkv[(c*PP + kp)*1024 + i];
        } else if (idx < OFF_F2A) {
            int r = idx - OFF_GWO; int m = r >> 9, k = r & 511; v = gwo[k*128 + m];
        } else if (idx < OFF_F2B) {
            int r = idx - OFF_F2A; int m = r >> 7, k = r & 127; v = f2a[k*512 + m];
        } else {
            int r = idx - OFF_F2B; int m = r >> 9, k = r & 511; v = f2b[k*128 + m];
        }
        dst[idx] = __float2bfloat16(v);
    }
}

// ---------------- channel layernorm: fp32 in, bf16 out ----------------
__global__ void __launch_bounds__(256) k_ln(const float* __restrict__ gam,
                                            const float* __restrict__ bet) {
    int n = blockIdx.x * 8 + (threadIdx.x >> 5);
    if (n >= NTOK) return;
    int lane = threadIdx.x & 31;
    float4 a = ((const float4*)(g_xT + (size_t)n*CC))[lane];
    float s  = a.x + a.y + a.z + a.w;
    float ss = a.x*a.x + a.y*a.y + a.z*a.z + a.w*a.w;
    #pragma unroll
    for (int o = 16; o; o >>= 1) {
        s  += __shfl_xor_sync(0xffffffffu, s,  o);
        ss += __shfl_xor_sync(0xffffffffu, ss, o);
    }
    float m   = s * (1.f/128.f);
    float var = ss * (1.f/128.f) - m*m;
    float r   = rsqrtf(var + LN_EPS);
    float4 gg = ((const float4*)gam)[lane];
    float4 bb = ((const float4*)bet)[lane];
    float2 p0 = make_float2((a.x - m)*r*gg.x + bb.x, (a.y - m)*r*gg.y + bb.y);
    float2 p1 = make_float2((a.z - m)*r*gg.z + bb.z, (a.w - m)*r*gg.w + bb.w);
    uint2 st;
    __nv_bfloat162 h0 = __float22bfloat162_rn(p0);
    __nv_bfloat162 h1 = __float22bfloat162_rn(p1);
    st.x = *reinterpret_cast<uint32_t*>(&h0);
    st.y = *reinterpret_cast<uint32_t*>(&h1);
    *reinterpret_cast<uint2*>(g_xn + (size_t)n*CC + lane*4) = st;
}

// ---------------- GEMM mainloop body (shared by both kernels) --------------
#define GSTAGE_BYTES 16384
#define GEMM_SMEM   (4*GSTAGE_BYTES)

#define GEMM_BODY(A_, Wt_, Nrows_, K_, rowBase_, colBase_)                        \
    const int t = threadIdx.x;                                                    \
    const int lane = t & 31, wid = t >> 5;                                         \
    const int wr = wid & 1, wc = wid >> 1;                                         \
    const int rL = t >> 1, half = t & 1;                                           \
    int ga = (rowBase_) + rL; if (ga >= (Nrows_)) ga = (Nrows_) - 1;               \
    const __nv_bfloat16* aP = (A_)  + (size_t)ga * (K_) + (half << 4);             \
    const __nv_bfloat16* bP = (Wt_) + (size_t)((colBase_) + rL) * (K_) + (half << 4); \
    const int fL = (rL >> 1) & 3;                                                  \
    const uint32_t dA = rL*64 + 16*((2*half) ^ fL);                                \
    const uint32_t dB = 8192 + dA;                                                 \
    const int rA  = (lane & 7) + ((lane >> 3) & 1) * 8;                            \
    const int ca  = lane >> 4;                                                     \
    const int fra = (rA >> 1) & 3;                                                 \
    const int g   = lane >> 3;                                                     \
    const int nB  = ((g >> 1) & 1) * 8 + (lane & 7);                               \
    const int cb  = g & 1;                                                         \
    const int fnb = (nB >> 1) & 3;                                                 \
    float acc[4][4][4];                                                            \
    _Pragma("unroll")                                                              \
    for (int mt = 0; mt < 4; ++mt)                                                 \
        _Pragma("unroll")                                                          \
        for (int nt = 0; nt < 4; ++nt)                                             \
            _Pragma("unroll")                                                      \
            for (int e = 0; e < 4; ++e) acc[mt][nt][e] = 0.f;                      \
    const int nk = (K_) >> 5;                                                      \
    G_ISSUE(0); asm volatile("cp.async.commit_group;");                            \
    G_ISSUE(1); asm volatile("cp.async.commit_group;");                            \
    G_ISSUE(2); asm volatile("cp.async.commit_group;");                            \
    for (int kt = 0; kt < nk; ++kt) {                                              \
        asm volatile("cp.async.wait_group 2;");                                    \
        __syncthreads();                                                           \
        if (kt + 3 < nk) G_ISSUE(kt + 3);                                          \
        asm volatile("cp.async.commit_group;");                                    \
        const uint32_t stA = smb + (kt & 3) * GSTAGE_BYTES;                        \
        const uint32_t stB = stA + 8192;                                           \
        _Pragma("unroll")                                                          \
        for (int ks = 0; ks < 2; ++ks) {                                           \
            uint32_t af[4][4], bf[4][2];                                           \
            _Pragma("unroll")                                                      \
            for (int mt = 0; mt < 4; ++mt) {                                       \
                uint32_t addr = stA + (uint32_t)((wr*64 + mt*16 + rA)*64)          \
                              + 16u*(uint32_t)(((ks<<1) + ca) ^ fra);              \
                asm volatile("ldmatrix.sync.aligned.m8n8.x4.shared.b16 {%0,%1,%2,%3}, [%4];" \
                    : "=r"(af[mt][0]), "=r"(af[mt][1]), "=r"(af[mt][2]), "=r"(af[mt][3]) \
                    : "r"(addr));                                                  \
            }                                                                      \
            _Pragma("unroll")                                                      \
            for (int j = 0; j < 2; ++j) {                                          \
                int n = wc*32 + j*16 + nB;                                         \
                uint32_t addr = stB + (uint32_t)(n*64)                             \
                              + 16u*(uint32_t)(((ks<<1) + cb) ^ fnb);              \
                asm volatile("ldmatrix.sync.aligned.m8n8.x4.shared.b16 {%0,%1,%2,%3}, [%4];" \
                    : "=r"(bf[2*j][0]), "=r"(bf[2*j][1]), "=r"(bf[2*j+1][0]), "=r"(bf[2*j+1][1]) \
                    : "r"(addr));                                                  \
            }                                                                      \
            _Pragma("unroll")                                                      \
            for (int mt = 0; mt < 4; ++mt)                                         \
                _Pragma("unroll")                                                  \
                for (int nt = 0; nt < 4; ++nt)                                     \
                    mma_bf16(acc[mt][nt], af[mt], bf[nt]);                         \
        }                                                                          \
    }

#define G_ISSUE(kt_) do {                                                   \
    const uint32_t st_ = smb + ((kt_) & 3) * GSTAGE_BYTES;                   \
    size_t sa_ = __cvta_generic_to_global(aP + ((size_t)(kt_) << 5));        \
    size_t sb_ = __cvta_generic_to_global(bP + ((size_t)(kt_) << 5));        \
    uint32_t a1_ = st_ + dA, b1_ = st_ + dB;                                 \
    asm volatile("cp.async.cg.shared.global [%0], [%1], 16;" :: "r"(a1_), "l"(sa_)); \
    asm volatile("cp.async.cg.shared.global [%0], [%1], 16;" :: "r"(a1_ ^ 16u), "l"(sa_ + 16)); \
    asm volatile("cp.async.cg.shared.global [%0], [%1], 16;" :: "r"(b1_), "l"(sb_)); \
    asm volatile("cp.async.cg.shared.global [%0], [%1], 16;" :: "r"(b1_ ^ 16u), "l"(sb_ + 16)); \
} while (0)

// ---------------- bf16 mma GEMM (R6-proven): C[N,M] = A[N,K] @ Wt[M,K]^T ---
// EPI: 0 none (bf16 out), 2 bias+gelu (bf16 out), 3 bias+residual (fp32 out)
template<int EPI>
__global__ void __launch_bounds__(256, 2) k_gemm_bf(
    const __nv_bfloat16* __restrict__ A, const __nv_bfloat16* __restrict__ Wt,
    const float* __restrict__ bias, const float* __restrict__ res,
    void* __restrict__ Cv, int Nrows, int K, int M)
{
    extern __shared__ char smraw[];
    const uint32_t smb = smem_u32(smraw);
    const int rowBase = blockIdx.y << 7, colBase = blockIdx.x << 7;

    GEMM_BODY(A, Wt, Nrows, K, rowBase, colBase)

    #pragma unroll
    for (int nt = 0; nt < 4; ++nt) {
        const int col = colBase + wc*32 + nt*8 + (lane & 3)*2;
        float2 bb = make_float2(0.f, 0.f);
        if (EPI >= 1) bb = *(const float2*)(bias + col);
        #pragma unroll
        for (int mt = 0; mt < 4; ++mt) {
            #pragma unroll
            for (int hf = 0; hf < 2; ++hf) {
                const int r = rowBase + wr*64 + mt*16 + (lane >> 2) + hf*8;
                if (r >= Nrows) continue;
                float2 o = make_float2(acc[mt][nt][hf*2+0] + bb.x,
                                       acc[mt][nt][hf*2+1] + bb.y);
                if (EPI == 2) { o.x = gelu_exact(o.x); o.y = gelu_exact(o.y); }
                if (EPI == 3) {
                    float2 rv = *(const float2*)(res + (size_t)r*M + col);
                    o.x += rv.x; o.y += rv.y;
                    *(float2*)((float*)Cv + (size_t)r*M + col) = o;
                } else {
                    stbf2((__nv_bfloat16*)Cv + (size_t)r*M + col, o);
                }
            }
        }
    }
}

// ---------------- merged GWQ + GWKV launch (both EPI0, independent) --------
// blocks [0, 3676): GWQ  q = xn @ WtQ^T   (K=128, M=512, rows NTOK)
// blocks [3676, 4732): GWKV kv = xg @ WtKV^T (K=896, M=1024, rows NKTOK)
__global__ void __launch_bounds__(256, 2) k_gemm_gproj(
    const __nv_bfloat16* __restrict__ xn, const __nv_bfloat16* __restrict__ wtQ,
    __nv_bfloat16* __restrict__ Cq,
    const __nv_bfloat16* __restrict__ xg, const __nv_bfloat16* __restrict__ wtKV,
    __nv_bfloat16* __restrict__ Ckv)
{
    extern __shared__ char smraw[];
    const uint32_t smb = smem_u32(smraw);

    const int i = blockIdx.x;
    const bool isQ = (i < 3676);
    const __nv_bfloat16* A;
    const __nv_bfloat16* Wt;
    __nv_bfloat16* C;
    int Nrows, K, M, rowBase, colBase;
    if (isQ) {
        A = xn; Wt = wtQ; C = Cq;
        Nrows = NTOK; K = 128; M = 512;
        colBase = (i & 3) << 7; rowBase = (i >> 2) << 7;
    } else {
        int j = i - 3676;
        A = xg; Wt = wtKV; C = Ckv;
        Nrows = NKTOK; K = 896; M = 1024;
        colBase = (j & 7) << 7; rowBase = (j >> 3) << 7;
    }

    GEMM_BODY(A, Wt, Nrows, K, rowBase, colBase)

    #pragma unroll
    for (int nt = 0; nt < 4; ++nt) {
        const int col = colBase + wc*32 + nt*8 + (lane & 3)*2;
        #pragma unroll
        for (int mt = 0; mt < 4; ++mt) {
            #pragma unroll
            for (int hf = 0; hf < 2; ++hf) {
                const int r = rowBase + wr*64 + mt*16 + (lane >> 2) + hf*8;
                if (r >= Nrows) continue;
                stbf2(C + (size_t)r*M + col,
                      make_float2(acc[mt][nt][hf*2+0], acc[mt][nt][hf*2+1]));
            }
        }
    }
}

// ---------------- local attention: one warp per (b, patch, v, head) --------
__global__ void __launch_bounds__(256) k_lattn() {
    int w = blockIdx.x * 8 + (threadIdx.x >> 5);
    int lane = threadIdx.x & 31;
    int h = w & 7;
    int g = w >> 3;
    int v = g % VV;
    int r = g / VV;
    int tt = r % NTP;
    int b = r / NTP;
    int d0 = lane * 2;

    float2 q[PP], kk[PP], vv[PP];
    #pragma unroll
    for (int p = 0; p < PP; ++p) {
        int n = (b*TT + tt*PP + p)*VV + v;
        const __nv_bfloat16* rowp = g_qkv + (size_t)n*1536 + h*DH + d0;
        q[p]  = ldbf2(rowp);
        kk[p] = ldbf2(rowp + 512);
        vv[p] = ldbf2(rowp + 1024);
    }
    float dots[PP][PP];
    #pragma unroll
    for (int i = 0; i < PP; ++i)
        #pragma unroll
        for (int j = 0; j < PP; ++j)
            dots[i][j] = q[i].x*kk[j].x + q[i].y*kk[j].y;
    #pragma unroll
    for (int o = 16; o; o >>= 1)
        #pragma unroll
        for (int i = 0; i < PP; ++i)
            #pragma unroll
            for (int j = 0; j < PP; ++j)
                dots[i][j] += __shfl_xor_sync(0xffffffffu, dots[i][j], o);
    #pragma unroll
    for (int i = 0; i < PP; ++i) {
        float mx = -1e30f;
        #pragma unroll
        for (int j = 0; j < PP; ++j) {
            dots[i][j] *= SCALE_ATT;
            mx = fmaxf(mx, dots[i][j]);
        }
        float s = 0.f;
        #pragma unroll
        for (int j = 0; j < PP; ++j) { dots[i][j] = __expf(dots[i][j] - mx); s += dots[i][j]; }
        float inv = 1.f / s;
        #pragma unroll
        for (int j = 0; j < PP; ++j) dots[i][j] *= inv;
    }
    #pragma unroll
    for (int i = 0; i < PP; ++i) {
        float2 o = make_float2(0.f, 0.f);
        #pragma unroll
        for (int j = 0; j < PP; ++j) {
            o.x += dots[i][j] * vv[j].x;
            o.y += dots[i][j] * vv[j].y;
        }
        int n = (b*TT + tt*PP + i)*VV + v;
        stbf2(g_ao + (size_t)n*INNER + h*DH + d0, o);
    }
}

// ---------------- gather (coalesced row copies) -----------------------------
__global__ void k_gather() {
    int idx = blockIdx.x * 256 + threadIdx.x;     // over NKTOK * 7 * 16 (uint4 of 8 bf16)
    if (idx >= NKTOK*112) return;
    int nk = idx / 112;
    int rem = idx - nk*112;
    int kp = rem >> 4, u = rem & 15;
    int v  = nk % VV;
    int rr = nk / VV;
    int tt = rr % NTP;
    int b  = rr / NTP;
    int src = ((b*TT + tt*PP + kp)*VV + v)*CC + u*8;
    *reinterpret_cast<uint4*>(g_xg + (size_t)nk*896 + kp*128 + u*8) =
        *reinterpret_cast<const uint4*>(g_xn + src);
}

// ---------------- global attention: one block per (b, h, v) ----------------
__global__ void __launch_bounds__(160) k_gattn() {
    int bid = blockIdx.x;
    int v = bid % VV;
    int rr = bid / VV;
    int h = rr & 7;
    int b = rr >> 3;
    __shared__ float ks[NTP][DH];
    __shared__ float vs[NTP][DH];
    for (int idx = threadIdx.x; idx < NTP*DH/2; idx += 160) {
        int j = idx >> 5, d2 = idx & 31;
        int nk = (b*NTP + j)*VV + v;
        size_t o = (size_t)nk*1024 + h*DH + d2*2;
        float2 kf = ldbf2(g_kv + o);
        float2 vf = ldbf2(g_kv + o + 512);
        ks[j][d2*2] = kf.x; ks[j][d2*2+1] = kf.y;
        vs[j][d2*2] = vf.x; vs[j][d2*2+1] = vf.y;
    }
    __syncthreads();
    int tid = threadIdx.x;
    if (tid >= 147) return;
    int i0 = 2*tid;
    size_t q0 = (size_t)((b*TT + i0)*VV + v)*INNER + h*DH;
    size_t q1 = q0 + (size_t)VV*INNER;

    float da[NTP], db[NTP];
    #pragma unroll
    for (int j = 0; j < NTP; ++j) { da[j] = 0.f; db[j] = 0.f; }

    for (int dchunk = 0; dchunk < 4; ++dchunk) {
        int dbase = dchunk * 16;
        float qa[16], qb[16];
        {
            uint4 u0 = *(const uint4*)(g_q + q0 + dbase);
            uint4 u1 = *(const uint4*)(g_q + q0 + dbase + 8);
            uint4 w0 = *(const uint4*)(g_q + q1 + dbase);
            uint4 w1 = *(const uint4*)(g_q + q1 + dbase + 8);
            float2 f;
            f=u2f2(u0.x); qa[0]=f.x; qa[1]=f.y;  f=u2f2(u0.y); qa[2]=f.x; qa[3]=f.y;
            f=u2f2(u0.z); qa[4]=f.x; qa[5]=f.y;  f=u2f2(u0.w); qa[6]=f.x; qa[7]=f.y;
            f=u2f2(u1.x); qa[8]=f.x; qa[9]=f.y;  f=u2f2(u1.y); qa[10]=f.x; qa[11]=f.y;
            f=u2f2(u1.z); qa[12]=f.x; qa[13]=f.y; f=u2f2(u1.w); qa[14]=f.x; qa[15]=f.y;
            f=u2f2(w0.x); qb[0]=f.x; qb[1]=f.y;  f=u2f2(w0.y); qb[2]=f.x; qb[3]=f.y;
            f=u2f2(w0.z); qb[4]=f.x; qb[5]=f.y;  f=u2f2(w0.w); qb[6]=f.x; qb[7]=f.y;
            f=u2f2(w1.x); qb[8]=f.x; qb[9]=f.y;  f=u2f2(w1.y); qb[10]=f.x; qb[11]=f.y;
            f=u2f2(w1.z); qb[12]=f.x; qb[13]=f.y; f=u2f2(w1.w); qb[14]=f.x; qb[15]=f.y;
        }
        #pragma unroll
        for (int j = 0; j < NTP; ++j) {
            #pragma unroll
            for (int dd = 0; dd < 16; ++dd) {
                float kv = ks[j][dbase + dd];
                da[j] += qa[dd] * kv;
                db[j] += qb[dd] * kv;
            }
        }
    }
    {
        float mx = -1e30f;
        #pragma unroll
        for (int j = 0; j < NTP; ++j) { da[j] *= SCALE_ATT; mx = fmaxf(mx, da[j]); }
        float s = 0.f;
        #pragma unroll
        for (int j = 0; j < NTP; ++j) { da[j] = __expf(da[j] - mx); s += da[j]; }
        float inv = 1.f / s;
        #pragma unroll
        for (int j = 0; j < NTP; ++j) da[j] *= inv;
    }
    {
        float mx = -1e30f;
        #pragma unroll
        for (int j = 0; j < NTP; ++j) { db[j] *= SCALE_ATT; mx = fmaxf(mx, db[j]); }
        float s = 0.f;
        #pragma unroll
        for (int j = 0; j < NTP; ++j) { db[j] = __expf(db[j] - mx); s += db[j]; }
        float inv = 1.f / s;
        #pragma unroll
        for (int j = 0; j < NTP; ++j) db[j] *= inv;
    }
    size_t o0 = q0, o1 = q1;
    for (int dchunk = 0; dchunk < 4; ++dchunk) {
        int dbase = dchunk * 16;
        float oa[16], ob[16];
        #pragma unroll
        for (int dd = 0; dd < 16; ++dd) { oa[dd] = 0.f; ob[dd] = 0.f; }
        #pragma unroll
        for (int j = 0; j < NTP; ++j) {
            #pragma unroll
            for (int dd = 0; dd < 16; ++dd) {
                float vv = vs[j][dbase + dd];
                oa[dd] += da[j] * vv;
                ob[dd] += db[j] * vv;
            }
        }
        #pragma unroll
        for (int dd = 0; dd < 16; dd += 2) {
            stbf2(g_ao + o0 + dbase + dd, make_float2(oa[dd], oa[dd+1]));
            stbf2(g_ao + o1 + dbase + dd, make_float2(ob[dd], ob[dd+1]));
        }
    }
}

// ---------------- launch -----------------------------------------------------
extern "C" void kernel_launch(void* const* d_in, const int* in_sizes, int n_in,
                              void* d_out, int out_size) {
    (void)in_sizes; (void)n_in; (void)out_size;
    float* p_xT;
    __nv_bfloat16 *p_xn, *p_qkv, *p_q, *p_kv, *p_ao, *p_xg, *p_wt;
    cudaGetSymbolAddress((void**)&p_xT,  g_xT);
    cudaGetSymbolAddress((void**)&p_xn,  g_xn);
    cudaGetSymbolAddress((void**)&p_qkv, g_qkv);
    cudaGetSymbolAddress((void**)&p_q,   g_q);
    cudaGetSymbolAddress((void**)&p_kv,  g_kv);
    cudaGetSymbolAddress((void**)&p_ao,  g_ao);
    cudaGetSymbolAddress((void**)&p_xg,  g_xg);
    cudaGetSymbolAddress((void**)&p_wt,  g_wt);

    cudaFuncSetAttribute(k_gemm_bf<0>, cudaFuncAttributeMaxDynamicSharedMemorySize, GEMM_SMEM);
    cudaFuncSetAttribute(k_gemm_bf<2>, cudaFuncAttributeMaxDynamicSharedMemorySize, GEMM_SMEM);
    cudaFuncSetAttribute(k_gemm_bf<3>, cudaFuncAttributeMaxDynamicSharedMemorySize, GEMM_SMEM);
    cudaFuncSetAttribute(k_gemm_gproj, cudaFuncAttributeMaxDynamicSharedMemorySize, GEMM_SMEM);

    const float* x      = (const float*)d_in[0];
    const float* ln1_g  = (const float*)d_in[1];
    const float* ln1_b  = (const float*)d_in[2];
    const float* la_wq  = (const float*)d_in[3];
    const float* la_wkv = (const float*)d_in[4];
    const float* la_wo  = (const float*)d_in[5];
    const float* la_bo  = (const float*)d_in[6];
    const float* ln2_g  = (const float*)d_in[7];
    const float* ln2_b  = (const float*)d_in[8];
    const float* ff1_w1 = (const float*)d_in[9];
    const float* ff1_b1 = (const float*)d_in[10];
    const float* ff1_w2 = (const float*)d_in[11];
    const float* ff1_b2 = (const float*)d_in[12];
    const float* ln3_g  = (const float*)d_in[13];
    const float* ln3_b  = (const float*)d_in[14];
    const float* ga_wq  = (const float*)d_in[15];
    const float* ga_wkv = (const float*)d_in[16];
    const float* ga_wo  = (const float*)d_in[17];
    const float* ga_bo  = (const float*)d_in[18];
    const float* ln4_g  = (const float*)d_in[19];
    const float* ln4_b  = (const float*)d_in[20];
    const float* ff2_w1 = (const float*)d_in[21];
    const float* ff2_b1 = (const float*)d_in[22];
    const float* ff2_w2 = (const float*)d_in[23];
    const float* ff2_b2 = (const float*)d_in[24];

    for (int l = 0; l < 2; ++l) {
        k_wprep<<<4096, 256>>>(
            la_wq  + (size_t)l*CC*INNER,      la_wkv + (size_t)l*CC*2*INNER,
            la_wo  + (size_t)l*INNER*CC,      ff1_w1 + (size_t)l*CC*512,
            ff1_w2 + (size_t)l*512*CC,        ga_wq  + (size_t)l*CC*INNER,
            ga_wkv + (size_t)l*CC*PP*2*INNER, ga_wo  + (size_t)l*INNER*CC,
            ff2_w1 + (size_t)l*CC*512,        ff2_w2 + (size_t)l*512*CC,
            p_wt + (size_t)l*WT_LSZ);
    }

    const int rowTiles  = (NTOK  + 127) / 128;   // 919
    const int lnGrid = NTOK / 8;

    k_tin<<<BB*TT, 256>>>(x);
    for (int l = 0; l < 2; ++l) {
        __nv_bfloat16* wb = p_wt + (size_t)l*WT_LSZ;
        // --- local attention block ---
        k_ln<<<lnGrid, 256>>>(ln1_g + l*CC, ln1_b + l*CC);
        k_gemm_bf<0><<<dim3(12, rowTiles), 256, GEMM_SMEM>>>(
            p_xn, wb + OFF_LQKV, nullptr, nullptr, p_qkv, NTOK, 128, 1536);
        k_lattn<<<NKTOK, 256>>>();
        k_gemm_bf<3><<<dim3(1, rowTiles), 256, GEMM_SMEM>>>(
            p_ao, wb + OFF_LWO, la_bo + l*CC, p_xT, p_xT, NTOK, 512, 128);
        // --- ff1 ---
        k_ln<<<lnGrid, 256>>>(ln2_g + l*CC, ln2_b + l*CC);
        k_gemm_bf<2><<<dim3(4, rowTiles), 256, GEMM_SMEM>>>(
            p_xn, wb + OFF_F1A, ff1_b1 + l*512, nullptr, p_ao, NTOK, 128, 512);
        k_gemm_bf<3><<<dim3(1, rowTiles), 256, GEMM_SMEM>>>(
            p_ao, wb + OFF_F1B, ff1_b2 + l*CC, p_xT, p_xT, NTOK, 512, 128);
        // --- global attention block ---
        k_ln<<<lnGrid, 256>>>(ln3_g + l*CC, ln3_b + l*CC);
        k_gather<<<(NKTOK*112 + 255)/256, 256>>>();
        k_gemm_gproj<<<4732, 256, GEMM_SMEM>>>(
            p_xn, wb + OFF_GWQ, p_q, p_xg, wb + OFF_GWKV, p_kv);
        k_gattn<<<BB*NHEAD*VV, 160>>>();
        k_gemm_bf<3><<<dim3(1, rowTiles), 256, GEMM_SMEM>>>(
            p_ao, wb + OFF_GWO, ga_bo + l*CC, p_xT, p_xT, NTOK, 512, 128);
        // --- ff2 ---
        k_ln<<<lnGrid, 256>>>(ln4_g + l*CC, ln4_b + l*CC);
        k_gemm_bf<2><<<dim3(4, rowTiles), 256, GEMM_SMEM>>>(
            p_xn, wb + OFF_F2A, ff2_b1 + l*512, nullptr, p_ao, NTOK, 128, 512);
        k_gemm_bf<3><<<dim3(1, rowTiles), 256, GEMM_SMEM>>>(
            p_ao, wb + OFF_F2B, ff2_b2 + l*CC, p_xT, p_xT, NTOK, 512, 128);
    }
    k_tout<<<BB*TT, 256>>>((float*)d_out);
}

// round 15
// speedup vs baseline: 1.0414x; 1.0066x over previous
#include <cuda_runtime.h>
#include <cuda_bf16.h>
#include <math.h>
#include <stdint.h>

// ---------------- problem constants ----------------
#define BB     16
#define CC     128
#define TT     294
#define VV     25
#define NTOK   (BB*TT*VV)        // 117600 tokens
#define INNER  512
#define NHEAD  8
#define DH     64
#define PP     7
#define NTP    42                 // T / P
#define NKTOK  (BB*NTP*VV)        // 16800 kv tokens (global)
#define SCALE_ATT 0.125f
#define LN_EPS 1e-5f

// transposed bf16 weight layout (elements, per layer)
#define OFF_LQKV  0               // [1536,128]
#define OFF_LWO   196608          // [128,512]
#define OFF_F1A   262144          // [512,128]
#define OFF_F1B   327680          // [128,512]
#define OFF_GWQ   393216          // [512,128]
#define OFF_GWKV  458752          // [1024,896] (k reordered kp*128+c)
#define OFF_GWO   1376256         // [128,512]
#define OFF_F2A   1441792         // [512,128]
#define OFF_F2B   1507328         // [128,512]
#define WT_LSZ    1572864

// ---------------- scratch (static device memory; no allocs) ----------------
__device__ __align__(16) float          g_xT[NTOK*CC];          // residual, fp32
__device__ __align__(16) __nv_bfloat16  g_xn[NTOK*CC];          // LN output
__device__ __align__(16) __nv_bfloat16  g_qkv[(size_t)NTOK*1536];
__device__ __align__(16) __nv_bfloat16  g_q [NTOK*INNER];
__device__ __align__(16) __nv_bfloat16  g_kv[NKTOK*1024];
__device__ __align__(16) __nv_bfloat16  g_ao[NTOK*INNER];       // attn out / ff hidden
__device__ __align__(16) __nv_bfloat16  g_xg[NKTOK*896];
__device__ __align__(16) __nv_bfloat16  g_wt[2*WT_LSZ];

// ---------------- helpers ----------------
__device__ __forceinline__ uint32_t smem_u32(const void* p) {
    uint32_t a;
    asm("{ .reg .u64 t; cvta.to.shared.u64 t, %1; cvt.u32.u64 %0, t; }" : "=r"(a) : "l"(p));
    return a;
}
__device__ __forceinline__ float2 ldbf2(const __nv_bfloat16* p) {
    return __bfloat1622float2(*reinterpret_cast<const __nv_bfloat162*>(p));
}
__device__ __forceinline__ void stbf2(__nv_bfloat16* p, float2 v) {
    *reinterpret_cast<__nv_bfloat162*>(p) = __float22bfloat162_rn(v);
}
__device__ __forceinline__ float2 u2f2(uint32_t u) {
    return __bfloat1622float2(*reinterpret_cast<const __nv_bfloat162*>(&u));
}
__device__ __forceinline__ void mma_bf16(float* d, const uint32_t* a, const uint32_t* b) {
    asm volatile(
        "mma.sync.aligned.m16n8k16.row.col.f32.bf16.bf16.f32 "
        "{%0,%1,%2,%3}, {%4,%5,%6,%7}, {%8,%9}, {%0,%1,%2,%3};"
        : "+f"(d[0]), "+f"(d[1]), "+f"(d[2]), "+f"(d[3])
        : "r"(a[0]), "r"(a[1]), "r"(a[2]), "r"(a[3]), "r"(b[0]), "r"(b[1]));
}
__device__ __forceinline__ float gelu_exact(float v) {
    return 0.5f * v * (1.0f + erff(v * 0.7071067811865475f));
}

// ---------------- transpose in + fused LN(layer0, ln1) ----------------------
__global__ void k_tin(const float* __restrict__ x,
                      const float* __restrict__ gam, const float* __restrict__ bet) {
    int bt = blockIdx.x;
    int t = bt % TT, b = bt / TT;
    __shared__ float sm[CC*VV];
    for (int idx = threadIdx.x; idx < CC*VV; idx += blockDim.x) {
        int c = idx / VV, v = idx % VV;
        sm[idx] = x[(((size_t)b*CC + c)*TT + t)*VV + v];
    }
    __syncthreads();
    size_t base = ((size_t)(b*TT + t))*VV*CC;
    for (int idx = threadIdx.x; idx < CC*VV; idx += blockDim.x) {
        int v = idx / CC, c = idx % CC;
        g_xT[base + idx] = sm[c*VV + v];
    }
    int wid = threadIdx.x >> 5, lane = threadIdx.x & 31;
    int c0 = lane * 4;
    float4 gg = *(const float4*)(gam + c0);
    float4 bb = *(const float4*)(bet + c0);
    for (int v = wid; v < VV; v += 8) {
        float f0 = sm[(c0+0)*VV + v], f1 = sm[(c0+1)*VV + v];
        float f2 = sm[(c0+2)*VV + v], f3 = sm[(c0+3)*VV + v];
        float s = f0+f1+f2+f3, ss = f0*f0+f1*f1+f2*f2+f3*f3;
        #pragma unroll
        for (int o = 16; o; o >>= 1) {
            s  += __shfl_xor_sync(0xffffffffu, s,  o);
            ss += __shfl_xor_sync(0xffffffffu, ss, o);
        }
        float m = s*(1.f/128.f), var = ss*(1.f/128.f) - m*m;
        float r = rsqrtf(var + LN_EPS);
        __nv_bfloat16* dst = g_xn + base + (size_t)v*CC + c0;
        stbf2(dst,     make_float2((f0-m)*r*gg.x + bb.x, (f1-m)*r*gg.y + bb.y));
        stbf2(dst + 2, make_float2((f2-m)*r*gg.z + bb.z, (f3-m)*r*gg.w + bb.w));
    }
}

__global__ void k_tout(float* __restrict__ out) {
    int bt = blockIdx.x;
    int t = bt % TT, b = bt / TT;
    __shared__ float sm[CC*VV];
    size_t base = ((size_t)(b*TT + t))*VV*CC;
    for (int idx = threadIdx.x; idx < CC*VV; idx += blockDim.x)
        sm[idx] = g_xT[base + idx];
    __syncthreads();
    for (int idx = threadIdx.x; idx < CC*VV; idx += blockDim.x) {
        int c = idx / VV, v = idx % VV;
        out[(((size_t)b*CC + c)*TT + t)*VV + v] = sm[v*CC + c];
    }
}

// ---------------- weight prep: single launch, both layers ------------------
__global__ void k_wprep(const float* __restrict__ wq,  const float* __restrict__ wkv,
                        const float* __restrict__ wo,  const float* __restrict__ f1a,
                        const float* __restrict__ f1b, const float* __restrict__ gwq,
                        const float* __restrict__ gwkv,const float* __restrict__ gwo,
                        const float* __restrict__ f2a, const float* __restrict__ f2b,
                        __nv_bfloat16* __restrict__ dst)
{
    for (int gidx = blockIdx.x*256 + threadIdx.x; gidx < 2*WT_LSZ; gidx += gridDim.x*256) {
        int l   = gidx / WT_LSZ;
        int idx = gidx - l*WT_LSZ;
        float v;
        if (idx < OFF_LWO) {
            int m = idx >> 7, k = idx & 127;
            v = (m < 512) ? wq[(size_t)l*65536 + k*512 + m]
                          : wkv[(size_t)l*131072 + k*1024 + (m-512)];
        } else if (idx < OFF_F1A) {
            int r = idx - OFF_LWO; int m = r >> 9, k = r & 511;
            v = wo[(size_t)l*65536 + k*128 + m];
        } else if (idx < OFF_F1B) {
            int r = idx - OFF_F1A; int m = r >> 7, k = r & 127;
            v = f1a[(size_t)l*65536 + k*512 + m];
        } else if (idx < OFF_GWQ) {
            int r = idx - OFF_F1B; int m = r >> 9, k = r & 511;
            v = f1b[(size_t)l*65536 + k*128 + m];
        } else if (idx < OFF_GWKV) {
            int r = idx - OFF_GWQ; int m = r >> 7, k = r & 127;
            v = gwq[(size_t)l*65536 + k*512 + m];
        } else if (idx < OFF_GWO) {
            int r = idx - OFF_GWKV; int i = r / 896; int kk = r - i*896;
            int kp = kk >> 7, c = kk & 127;
            v = gwkv[(size_t)l*917504 + (c*PP + kp)*1024 + i];
        } else if (idx < OFF_F2A) {
            int r = idx - OFF_GWO; int m = r >> 9, k = r & 511;
            v = gwo[(size_t)l*65536 + k*128 + m];
        } else if (idx < OFF_F2B) {
            int r = idx - OFF_F2A; int m = r >> 7, k = r & 127;
            v = f2a[(size_t)l*65536 + k*512 + m];
        } else {
            int r = idx - OFF_F2B; int m = r >> 9, k = r & 511;
            v = f2b[(size_t)l*65536 + k*128 + m];
        }
        dst[gidx] = __float2bfloat16(v);
    }
}

// ---------------- channel layernorm (optionally fused gather) --------------
template<bool GATHER>
__global__ void __launch_bounds__(256) k_ln(const float* __restrict__ gam,
                                            const float* __restrict__ bet) {
    int n = blockIdx.x * 8 + (threadIdx.x >> 5);
    if (n >= NTOK) return;
    int lane = threadIdx.x & 31;
    float4 a = ((const float4*)(g_xT + (size_t)n*CC))[lane];
    float s  = a.x + a.y + a.z + a.w;
    float ss = a.x*a.x + a.y*a.y + a.z*a.z + a.w*a.w;
    #pragma unroll
    for (int o = 16; o; o >>= 1) {
        s  += __shfl_xor_sync(0xffffffffu, s,  o);
        ss += __shfl_xor_sync(0xffffffffu, ss, o);
    }
    float m   = s * (1.f/128.f);
    float var = ss * (1.f/128.f) - m*m;
    float r   = rsqrtf(var + LN_EPS);
    float4 gg = ((const float4*)gam)[lane];
    float4 bb = ((const float4*)bet)[lane];
    float2 p0 = make_float2((a.x - m)*r*gg.x + bb.x, (a.y - m)*r*gg.y + bb.y);
    float2 p1 = make_float2((a.z - m)*r*gg.z + bb.z, (a.w - m)*r*gg.w + bb.w);
    uint2 st;
    __nv_bfloat162 h0 = __float22bfloat162_rn(p0);
    __nv_bfloat162 h1 = __float22bfloat162_rn(p1);
    st.x = *reinterpret_cast<uint32_t*>(&h0);
    st.y = *reinterpret_cast<uint32_t*>(&h1);
    *reinterpret_cast<uint2*>(g_xn + (size_t)n*CC + lane*4) = st;
    if (GATHER) {
        int v  = n % VV;
        int bt = n / VV;
        int t  = bt % TT;
        int b  = bt / TT;
        int tt = t / PP, kp = t - tt*PP;
        int nk = (b*NTP + tt)*VV + v;
        *reinterpret_cast<uint2*>(g_xg + (size_t)nk*896 + kp*128 + lane*4) = st;
    }
}

// ---------------- GEMM mainloop body (shared) -------------------------------
#define GSTAGE_BYTES 16384
#define GEMM_SMEM   (4*GSTAGE_BYTES)

#define GEMM_BODY(A_, Wt_, Nrows_, K_, rowBase_, colBase_)                        \
    const int t = threadIdx.x;                                                    \
    const int lane = t & 31, wid = t >> 5;                                         \
    const int wr = wid & 1, wc = wid >> 1;                                         \
    const int rL = t >> 1, half = t & 1;                                           \
    int ga = (rowBase_) + rL; if (ga >= (Nrows_)) ga = (Nrows_) - 1;               \
    const __nv_bfloat16* aP = (A_)  + (size_t)ga * (K_) + (half << 4);             \
    const __nv_bfloat16* bP = (Wt_) + (size_t)((colBase_) + rL) * (K_) + (half << 4); \
    const int fL = (rL >> 1) & 3;                                                  \
    const uint32_t dA = rL*64 + 16*((2*half) ^ fL);                                \
    const uint32_t dB = 8192 + dA;                                                 \
    const int rA  = (lane & 7) + ((lane >> 3) & 1) * 8;                            \
    const int ca  = lane >> 4;                                                     \
    const int fra = (rA >> 1) & 3;                                                 \
    const int g   = lane >> 3;                                                     \
    const int nB  = ((g >> 1) & 1) * 8 + (lane & 7);                               \
    const int cb  = g & 1;                                                         \
    const int fnb = (nB >> 1) & 3;                                                 \
    float acc[4][4][4];                                                            \
    _Pragma("unroll")                                                              \
    for (int mt = 0; mt < 4; ++mt)                                                 \
        _Pragma("unroll")                                                          \
        for (int nt = 0; nt < 4; ++nt)                                             \
            _Pragma("unroll")                                                      \
            for (int e = 0; e < 4; ++e) acc[mt][nt][e] = 0.f;                      \
    const int nk = (K_) >> 5;                                                      \
    G_ISSUE(0); asm volatile("cp.async.commit_group;");                            \
    G_ISSUE(1); asm volatile("cp.async.commit_group;");                            \
    G_ISSUE(2); asm volatile("cp.async.commit_group;");                            \
    for (int kt = 0; kt < nk; ++kt) {                                              \
        asm volatile("cp.async.wait_group 2;");                                    \
        __syncthreads();                                                           \
        if (kt + 3 < nk) G_ISSUE(kt + 3);                                          \
        asm volatile("cp.async.commit_group;");                                    \
        const uint32_t stA = smb + (kt & 3) * GSTAGE_BYTES;                        \
        const uint32_t stB = stA + 8192;                                           \
        _Pragma("unroll")                                                          \
        for (int ks = 0; ks < 2; ++ks) {                                           \
            uint32_t af[4][4], bf[4][2];                                           \
            _Pragma("unroll")                                                      \
            for (int mt = 0; mt < 4; ++mt) {                                       \
                uint32_t addr = stA + (uint32_t)((wr*64 + mt*16 + rA)*64)          \
                              + 16u*(uint32_t)(((ks<<1) + ca) ^ fra);              \
                asm volatile("ldmatrix.sync.aligned.m8n8.x4.shared.b16 {%0,%1,%2,%3}, [%4];" \
                    : "=r"(af[mt][0]), "=r"(af[mt][1]), "=r"(af[mt][2]), "=r"(af[mt][3]) \
                    : "r"(addr));                                                  \
            }                                                                      \
            _Pragma("unroll")                                                      \
            for (int j = 0; j < 2; ++j) {                                          \
                int n = wc*32 + j*16 + nB;                                         \
                uint32_t addr = stB + (uint32_t)(n*64)                             \
                              + 16u*(uint32_t)(((ks<<1) + cb) ^ fnb);              \
                asm volatile("ldmatrix.sync.aligned.m8n8.x4.shared.b16 {%0,%1,%2,%3}, [%4];" \
                    : "=r"(bf[2*j][0]), "=r"(bf[2*j][1]), "=r"(bf[2*j+1][0]), "=r"(bf[2*j+1][1]) \
                    : "r"(addr));                                                  \
            }                                                                      \
            _Pragma("unroll")                                                      \
            for (int mt = 0; mt < 4; ++mt)                                         \
                _Pragma("unroll")                                                  \
                for (int nt = 0; nt < 4; ++nt)                                     \
                    mma_bf16(acc[mt][nt], af[mt], bf[nt]);                         \
        }                                                                          \
    }

#define G_ISSUE(kt_) do {                                                   \
    const uint32_t st_ = smb + ((kt_) & 3) * GSTAGE_BYTES;                   \
    size_t sa_ = __cvta_generic_to_global(aP + ((size_t)(kt_) << 5));        \
    size_t sb_ = __cvta_generic_to_global(bP + ((size_t)(kt_) << 5));        \
    uint32_t a1_ = st_ + dA, b1_ = st_ + dB;                                 \
    asm volatile("cp.async.cg.shared.global [%0], [%1], 16;" :: "r"(a1_), "l"(sa_)); \
    asm volatile("cp.async.cg.shared.global [%0], [%1], 16;" :: "r"(a1_ ^ 16u), "l"(sa_ + 16)); \
    asm volatile("cp.async.cg.shared.global [%0], [%1], 16;" :: "r"(b1_), "l"(sb_)); \
    asm volatile("cp.async.cg.shared.global [%0], [%1], 16;" :: "r"(b1_ ^ 16u), "l"(sb_ + 16)); \
} while (0)

// ---------------- bf16 mma GEMM: C[N,M] = A[N,K] @ Wt[M,K]^T ---------------
// EPI: 0 none (bf16 out), 2 bias+gelu (bf16 out), 3 bias+residual (fp32 out)
template<int EPI>
__global__ void __launch_bounds__(256, 2) k_gemm_bf(
    const __nv_bfloat16* __restrict__ A, const __nv_bfloat16* __restrict__ Wt,
    const float* __restrict__ bias, const float* __restrict__ res,
    void* __restrict__ Cv, int Nrows, int K, int M)
{
    extern __shared__ char smraw[];
    const uint32_t smb = smem_u32(smraw);
    const int rowBase = blockIdx.y << 7, colBase = blockIdx.x << 7;

    GEMM_BODY(A, Wt, Nrows, K, rowBase, colBase)

    #pragma unroll
    for (int nt = 0; nt < 4; ++nt) {
        const int col = colBase + wc*32 + nt*8 + (lane & 3)*2;
        float2 bb = make_float2(0.f, 0.f);
        if (EPI >= 1) bb = *(const float2*)(bias + col);
        #pragma unroll
        for (int mt = 0; mt < 4; ++mt) {
            #pragma unroll
            for (int hf = 0; hf < 2; ++hf) {
                const int r = rowBase + wr*64 + mt*16 + (lane >> 2) + hf*8;
                if (r >= Nrows) continue;
                float2 o = make_float2(acc[mt][nt][hf*2+0] + bb.x,
                                       acc[mt][nt][hf*2+1] + bb.y);
                if (EPI == 2) { o.x = gelu_exact(o.x); o.y = gelu_exact(o.y); }
                if (EPI == 3) {
                    float2 rv = *(const float2*)(res + (size_t)r*M + col);
                    o.x += rv.x; o.y += rv.y;
                    *(float2*)((float*)Cv + (size_t)r*M + col) = o;
                } else {
                    stbf2((__nv_bfloat16*)Cv + (size_t)r*M + col, o);
                }
            }
        }
    }
}

// ---------------- merged GWQ + GWKV launch (both EPI0, independent) --------
__global__ void __launch_bounds__(256, 2) k_gemm_gproj(
    const __nv_bfloat16* __restrict__ xn, const __nv_bfloat16* __restrict__ wtQ,
    __nv_bfloat16* __restrict__ Cq,
    const __nv_bfloat16* __restrict__ xg, const __nv_bfloat16* __restrict__ wtKV,
    __nv_bfloat16* __restrict__ Ckv)
{
    extern __shared__ char smraw[];
    const uint32_t smb = smem_u32(smraw);

    const int i = blockIdx.x;
    const bool isQ = (i < 3676);
    const __nv_bfloat16* A;
    const __nv_bfloat16* Wt;
    __nv_bfloat16* C;
    int Nrows, K, M, rowBase, colBase;
    if (isQ) {
        A = xn; Wt = wtQ; C = Cq;
        Nrows = NTOK; K = 128; M = 512;
        colBase = (i & 3) << 7; rowBase = (i >> 2) << 7;
    } else {
        int j = i - 3676;
        A = xg; Wt = wtKV; C = Ckv;
        Nrows = NKTOK; K = 896; M = 1024;
        colBase = (j & 7) << 7; rowBase = (j >> 3) << 7;
    }

    GEMM_BODY(A, Wt, Nrows, K, rowBase, colBase)

    #pragma unroll
    for (int nt = 0; nt < 4; ++nt) {
        const int col = colBase + wc*32 + nt*8 + (lane & 3)*2;
        #pragma unroll
        for (int mt = 0; mt < 4; ++mt) {
            #pragma unroll
            for (int hf = 0; hf < 2; ++hf) {
                const int r = rowBase + wr*64 + mt*16 + (lane >> 2) + hf*8;
                if (r >= Nrows) continue;
                stbf2(C + (size_t)r*M + col,
                      make_float2(acc[mt][nt][hf*2+0], acc[mt][nt][hf*2+1]));
            }
        }
    }
}

// ---------------- local attention: one warp per (b, patch, v, head) --------
__global__ void __launch_bounds__(256) k_lattn() {
    int w = blockIdx.x * 8 + (threadIdx.x >> 5);
    int lane = threadIdx.x & 31;
    int h = w & 7;
    int g = w >> 3;
    int v = g % VV;
    int r = g / VV;
    int tt = r % NTP;
    int b = r / NTP;
    int d0 = lane * 2;

    float2 q[PP], kk[PP], vv[PP];
    #pragma unroll
    for (int p = 0; p < PP; ++p) {
        int n = (b*TT + tt*PP + p)*VV + v;
        const __nv_bfloat16* rowp = g_qkv + (size_t)n*1536 + h*DH + d0;
        q[p]  = ldbf2(rowp);
        kk[p] = ldbf2(rowp + 512);
        vv[p] = ldbf2(rowp + 1024);
    }
    float dots[PP][PP];
    #pragma unroll
    for (int i = 0; i < PP; ++i)
        #pragma unroll
        for (int j = 0; j < PP; ++j)
            dots[i][j] = q[i].x*kk[j].x + q[i].y*kk[j].y;
    #pragma unroll
    for (int o = 16; o; o >>= 1)
        #pragma unroll
        for (int i = 0; i < PP; ++i)
            #pragma unroll
            for (int j = 0; j < PP; ++j)
                dots[i][j] += __shfl_xor_sync(0xffffffffu, dots[i][j], o);
    #pragma unroll
    for (int i = 0; i < PP; ++i) {
        float mx = -1e30f;
        #pragma unroll
        for (int j = 0; j < PP; ++j) {
            dots[i][j] *= SCALE_ATT;
            mx = fmaxf(mx, dots[i][j]);
        }
        float s = 0.f;
        #pragma unroll
        for (int j = 0; j < PP; ++j) { dots[i][j] = __expf(dots[i][j] - mx); s += dots[i][j]; }
        float inv = 1.f / s;
        #pragma unroll
        for (int j = 0; j < PP; ++j) dots[i][j] *= inv;
    }
    #pragma unroll
    for (int i = 0; i < PP; ++i) {
        float2 o = make_float2(0.f, 0.f);
        #pragma unroll
        for (int j = 0; j < PP; ++j) {
            o.x += dots[i][j] * vv[j].x;
            o.y += dots[i][j] * vv[j].y;
        }
        int n = (b*TT + tt*PP + i)*VV + v;
        stbf2(g_ao + (size_t)n*INNER + h*DH + d0, o);
    }
}

// ---------------- global attention: one block per (b, h, v) ----------------
__global__ void __launch_bounds__(160) k_gattn() {
    int bid = blockIdx.x;
    int v = bid % VV;
    int rr = bid / VV;
    int h = rr & 7;
    int b = rr >> 3;
    __shared__ float ks[NTP][DH];
    __shared__ float vs[NTP][DH];
    for (int idx = threadIdx.x; idx < NTP*DH/2; idx += 160) {
        int j = idx >> 5, d2 = idx & 31;
        int nk = (b*NTP + j)*VV + v;
        size_t o = (size_t)nk*1024 + h*DH + d2*2;
        float2 kf = ldbf2(g_kv + o);
        float2 vf = ldbf2(g_kv + o + 512);
        ks[j][d2*2] = kf.x; ks[j][d2*2+1] = kf.y;
        vs[j][d2*2] = vf.x; vs[j][d2*2+1] = vf.y;
    }
    __syncthreads();
    int tid = threadIdx.x;
    if (tid >= 147) return;
    int i0 = 2*tid;
    size_t q0 = (size_t)((b*TT + i0)*VV + v)*INNER + h*DH;
    size_t q1 = q0 + (size_t)VV*INNER;

    float da[NTP], db[NTP];
    #pragma unroll
    for (int j = 0; j < NTP; ++j) { da[j] = 0.f; db[j] = 0.f; }

    for (int dchunk = 0; dchunk < 4; ++dchunk) {
        int dbase = dchunk * 16;
        float qa[16], qb[16];
        {
            uint4 u0 = *(const uint4*)(g_q + q0 + dbase);
            uint4 u1 = *(const uint4*)(g_q + q0 + dbase + 8);
            uint4 w0 = *(const uint4*)(g_q + q1 + dbase);
            uint4 w1 = *(const uint4*)(g_q + q1 + dbase + 8);
            float2 f;
            f=u2f2(u0.x); qa[0]=f.x; qa[1]=f.y;  f=u2f2(u0.y); qa[2]=f.x; qa[3]=f.y;
            f=u2f2(u0.z); qa[4]=f.x; qa[5]=f.y;  f=u2f2(u0.w); qa[6]=f.x; qa[7]=f.y;
            f=u2f2(u1.x); qa[8]=f.x; qa[9]=f.y;  f=u2f2(u1.y); qa[10]=f.x; qa[11]=f.y;
            f=u2f2(u1.z); qa[12]=f.x; qa[13]=f.y; f=u2f2(u1.w); qa[14]=f.x; qa[15]=f.y;
            f=u2f2(w0.x); qb[0]=f.x; qb[1]=f.y;  f=u2f2(w0.y); qb[2]=f.x; qb[3]=f.y;
            f=u2f2(w0.z); qb[4]=f.x; qb[5]=f.y;  f=u2f2(w0.w); qb[6]=f.x; qb[7]=f.y;
            f=u2f2(w1.x); qb[8]=f.x; qb[9]=f.y;  f=u2f2(w1.y); qb[10]=f.x; qb[11]=f.y;
            f=u2f2(w1.z); qb[12]=f.x; qb[13]=f.y; f=u2f2(w1.w); qb[14]=f.x; qb[15]=f.y;
        }
        #pragma unroll
        for (int j = 0; j < NTP; ++j) {
            #pragma unroll
            for (int dd = 0; dd < 16; ++dd) {
                float kv = ks[j][dbase + dd];
                da[j] += qa[dd] * kv;
                db[j] += qb[dd] * kv;
            }
        }
    }
    {
        float mx = -1e30f;
        #pragma unroll
        for (int j = 0; j < NTP; ++j) { da[j] *= SCALE_ATT; mx = fmaxf(mx, da[j]); }
        float s = 0.f;
        #pragma unroll
        for (int j = 0; j < NTP; ++j) { da[j] = __expf(da[j] - mx); s += da[j]; }
        float inv = 1.f / s;
        #pragma unroll
        for (int j = 0; j < NTP; ++j) da[j] *= inv;
    }
    {
        float mx = -1e30f;
        #pragma unroll
        for (int j = 0; j < NTP; ++j) { db[j] *= SCALE_ATT; mx = fmaxf(mx, db[j]); }
        float s = 0.f;
        #pragma unroll
        for (int j = 0; j < NTP; ++j) { db[j] = __expf(db[j] - mx); s += db[j]; }
        float inv = 1.f / s;
        #pragma unroll
        for (int j = 0; j < NTP; ++j) db[j] *= inv;
    }
    size_t o0 = q0, o1 = q1;
    for (int dchunk = 0; dchunk < 4; ++dchunk) {
        int dbase = dchunk * 16;
        float oa[16], ob[16];
        #pragma unroll
        for (int dd = 0; dd < 16; ++dd) { oa[dd] = 0.f; ob[dd] = 0.f; }
        #pragma unroll
        for (int j = 0; j < NTP; ++j) {
            #pragma unroll
            for (int dd = 0; dd < 16; ++dd) {
                float vv = vs[j][dbase + dd];
                oa[dd] += da[j] * vv;
                ob[dd] += db[j] * vv;
            }
        }
        #pragma unroll
        for (int dd = 0; dd < 16; dd += 2) {
            stbf2(g_ao + o0 + dbase + dd, make_float2(oa[dd], oa[dd+1]));
            stbf2(g_ao + o1 + dbase + dd, make_float2(ob[dd], ob[dd+1]));
        }
    }
}

// ---------------- launch -----------------------------------------------------
extern "C" void kernel_launch(void* const* d_in, const int* in_sizes, int n_in,
                              void* d_out, int out_size) {
    (void)in_sizes; (void)n_in; (void)out_size;
    float* p_xT;
    __nv_bfloat16 *p_xn, *p_qkv, *p_q, *p_kv, *p_ao, *p_xg, *p_wt;
    cudaGetSymbolAddress((void**)&p_xT,  g_xT);
    cudaGetSymbolAddress((void**)&p_xn,  g_xn);
    cudaGetSymbolAddress((void**)&p_qkv, g_qkv);
    cudaGetSymbolAddress((void**)&p_q,   g_q);
    cudaGetSymbolAddress((void**)&p_kv,  g_kv);
    cudaGetSymbolAddress((void**)&p_ao,  g_ao);
    cudaGetSymbolAddress((void**)&p_xg,  g_xg);
    cudaGetSymbolAddress((void**)&p_wt,  g_wt);

    cudaFuncSetAttribute(k_gemm_bf<0>, cudaFuncAttributeMaxDynamicSharedMemorySize, GEMM_SMEM);
    cudaFuncSetAttribute(k_gemm_bf<2>, cudaFuncAttributeMaxDynamicSharedMemorySize, GEMM_SMEM);
    cudaFuncSetAttribute(k_gemm_bf<3>, cudaFuncAttributeMaxDynamicSharedMemorySize, GEMM_SMEM);
    cudaFuncSetAttribute(k_gemm_gproj, cudaFuncAttributeMaxDynamicSharedMemorySize, GEMM_SMEM);

    const float* x      = (const float*)d_in[0];
    const float* ln1_g  = (const float*)d_in[1];
    const float* ln1_b  = (const float*)d_in[2];
    const float* la_wq  = (const float*)d_in[3];
    const float* la_wkv = (const float*)d_in[4];
    const float* la_wo  = (const float*)d_in[5];
    const float* la_bo  = (const float*)d_in[6];
    const float* ln2_g  = (const float*)d_in[7];
    const float* ln2_b  = (const float*)d_in[8];
    const float* ff1_w1 = (const float*)d_in[9];
    const float* ff1_b1 = (const float*)d_in[10];
    const float* ff1_w2 = (const float*)d_in[11];
    const float* ff1_b2 = (const float*)d_in[12];
    const float* ln3_g  = (const float*)d_in[13];
    const float* ln3_b  = (const float*)d_in[14];
    const float* ga_wq  = (const float*)d_in[15];
    const float* ga_wkv = (const float*)d_in[16];
    const float* ga_wo  = (const float*)d_in[17];
    const float* ga_bo  = (const float*)d_in[18];
    const float* ln4_g  = (const float*)d_in[19];
    const float* ln4_b  = (const float*)d_in[20];
    const float* ff2_w1 = (const float*)d_in[21];
    const float* ff2_b1 = (const float*)d_in[22];
    const float* ff2_w2 = (const float*)d_in[23];
    const float* ff2_b2 = (const float*)d_in[24];

    // weight prep: single launch, both layers
    k_wprep<<<8192, 256>>>(la_wq, la_wkv, la_wo, ff1_w1, ff1_w2,
                           ga_wq, ga_wkv, ga_wo, ff2_w1, ff2_w2, p_wt);

    const int rowTiles  = (NTOK  + 127) / 128;   // 919
    const int lnGrid = NTOK / 8;

    // transpose-in + fused LN1(layer 0)
    k_tin<<<BB*TT, 256>>>(x, ln1_g, ln1_b);

    for (int l = 0; l < 2; ++l) {
        __nv_bfloat16* wb = p_wt + (size_t)l*WT_LSZ;
        // --- local attention block ---
        if (l == 1) k_ln<false><<<lnGrid, 256>>>(ln1_g + CC, ln1_b + CC);
        k_gemm_bf<0><<<dim3(12, rowTiles), 256, GEMM_SMEM>>>(
            p_xn, wb + OFF_LQKV, nullptr, nullptr, p_qkv, NTOK, 128, 1536);
        k_lattn<<<NKTOK, 256>>>();
        k_gemm_bf<3><<<dim3(1, rowTiles), 256, GEMM_SMEM>>>(
            p_ao, wb + OFF_LWO, la_bo + l*CC, p_xT, p_xT, NTOK, 512, 128);
        // --- ff1 ---
        k_ln<false><<<lnGrid, 256>>>(ln2_g + l*CC, ln2_b + l*CC);
        k_gemm_bf<2><<<dim3(4, rowTiles), 256, GEMM_SMEM>>>(
            p_xn, wb + OFF_F1A, ff1_b1 + l*512, nullptr, p_ao, NTOK, 128, 512);
        k_gemm_bf<3><<<dim3(1, rowTiles), 256, GEMM_SMEM>>>(
            p_ao, wb + OFF_F1B, ff1_b2 + l*CC, p_xT, p_xT, NTOK, 512, 128);
        // --- global attention block (LN + fused gather, merged q/kv proj) ---
        k_ln<true><<<lnGrid, 256>>>(ln3_g + l*CC, ln3_b + l*CC);
        k_gemm_gproj<<<4732, 256, GEMM_SMEM>>>(
            p_xn, wb + OFF_GWQ, p_q, p_xg, wb + OFF_GWKV, p_kv);
        k_gattn<<<BB*NHEAD*VV, 160>>>();
        k_gemm_bf<3><<<dim3(1, rowTiles), 256, GEMM_SMEM>>>(
            p_ao, wb + OFF_GWO, ga_bo + l*CC, p_xT, p_xT, NTOK, 512, 128);
        // --- ff2 ---
        k_ln<false><<<lnGrid, 256>>>(ln4_g + l*CC, ln4_b + l*CC);
        k_gemm_bf<2><<<dim3(4, rowTiles), 256, GEMM_SMEM>>>(
            p_xn, wb + OFF_F2A, ff2_b1 + l*512, nullptr, p_ao, NTOK, 128, 512);
        k_gemm_bf<3><<<dim3(1, rowTiles), 256, GEMM_SMEM>>>(
            p_ao, wb + OFF_F2B, ff2_b2 + l*CC, p_xT, p_xT, NTOK, 512, 128);
    }
    k_tout<<<BB*TT, 256>>>((float*)d_out);
}

// round 16
// speedup vs baseline: 1.0558x; 1.0138x over previous
#include <cuda_runtime.h>
#include <cuda_bf16.h>
#include <math.h>
#include <stdint.h>

// ---------------- problem constants ----------------
#define BB     16
#define CC     128
#define TT     294
#define VV     25
#define NTOK   (BB*TT*VV)        // 117600 tokens
#define INNER  512
#define NHEAD  8
#define DH     64
#define PP     7
#define NTP    42                 // T / P
#define NKTOK  (BB*NTP*VV)        // 16800 kv tokens (global)
#define SCALE_ATT 0.125f
#define EXP2C  (0.125f * 1.44269504088896340736f)   // scale * log2(e)
#define LN_EPS 1e-5f

// transposed bf16 weight layout (elements, per layer)
#define OFF_LQKV  0               // [1536,128]
#define OFF_LWO   196608          // [128,512]
#define OFF_F1A   262144          // [512,128]
#define OFF_F1B   327680          // [128,512]
#define OFF_GWQ   393216          // [512,128]
#define OFF_GWKV  458752          // [1024,896] (k reordered kp*128+c)
#define OFF_GWO   1376256         // [128,512]
#define OFF_F2A   1441792         // [512,128]
#define OFF_F2B   1507328         // [128,512]
#define WT_LSZ    1572864

// ---------------- scratch (static device memory; no allocs) ----------------
__device__ __align__(16) float          g_xT[NTOK*CC];          // residual, fp32
__device__ __align__(16) __nv_bfloat16  g_xn[NTOK*CC];          // LN output
__device__ __align__(16) __nv_bfloat16  g_qkv[(size_t)NTOK*1536];
__device__ __align__(16) __nv_bfloat16  g_q [NTOK*INNER];
__device__ __align__(16) __nv_bfloat16  g_kv[NKTOK*1024];
__device__ __align__(16) __nv_bfloat16  g_ao[NTOK*INNER];       // attn out / ff hidden
__device__ __align__(16) __nv_bfloat16  g_xg[NKTOK*896];
__device__ __align__(16) __nv_bfloat16  g_wt[2*WT_LSZ];

// ---------------- helpers ----------------
__device__ __forceinline__ uint32_t smem_u32(const void* p) {
    uint32_t a;
    asm("{ .reg .u64 t; cvta.to.shared.u64 t, %1; cvt.u32.u64 %0, t; }" : "=r"(a) : "l"(p));
    return a;
}
__device__ __forceinline__ float2 ldbf2(const __nv_bfloat16* p) {
    return __bfloat1622float2(*reinterpret_cast<const __nv_bfloat162*>(p));
}
__device__ __forceinline__ void stbf2(__nv_bfloat16* p, float2 v) {
    *reinterpret_cast<__nv_bfloat162*>(p) = __float22bfloat162_rn(v);
}
__device__ __forceinline__ float2 u2f2(uint32_t u) {
    return __bfloat1622float2(*reinterpret_cast<const __nv_bfloat162*>(&u));
}
__device__ __forceinline__ void mma_bf16(float* d, const uint32_t* a, const uint32_t* b) {
    asm volatile(
        "mma.sync.aligned.m16n8k16.row.col.f32.bf16.bf16.f32 "
        "{%0,%1,%2,%3}, {%4,%5,%6,%7}, {%8,%9}, {%0,%1,%2,%3};"
        : "+f"(d[0]), "+f"(d[1]), "+f"(d[2]), "+f"(d[3])
        : "r"(a[0]), "r"(a[1]), "r"(a[2]), "r"(a[3]), "r"(b[0]), "r"(b[1]));
}
__device__ __forceinline__ float gelu_exact(float v) {
    return 0.5f * v * (1.0f + erff(v * 0.7071067811865475f));
}

// ---------------- transpose in + fused LN(layer0, ln1) ----------------------
__global__ void k_tin(const float* __restrict__ x,
                      const float* __restrict__ gam, const float* __restrict__ bet) {
    int bt = blockIdx.x;
    int t = bt % TT, b = bt / TT;
    __shared__ float sm[CC*VV];
    for (int idx = threadIdx.x; idx < CC*VV; idx += blockDim.x) {
        int c = idx / VV, v = idx % VV;
        sm[idx] = x[(((size_t)b*CC + c)*TT + t)*VV + v];
    }
    __syncthreads();
    size_t base = ((size_t)(b*TT + t))*VV*CC;
    for (int idx = threadIdx.x; idx < CC*VV; idx += blockDim.x) {
        int v = idx / CC, c = idx % CC;
        g_xT[base + idx] = sm[c*VV + v];
    }
    int wid = threadIdx.x >> 5, lane = threadIdx.x & 31;
    int c0 = lane * 4;
    float4 gg = *(const float4*)(gam + c0);
    float4 bb = *(const float4*)(bet + c0);
    for (int v = wid; v < VV; v += 8) {
        float f0 = sm[(c0+0)*VV + v], f1 = sm[(c0+1)*VV + v];
        float f2 = sm[(c0+2)*VV + v], f3 = sm[(c0+3)*VV + v];
        float s = f0+f1+f2+f3, ss = f0*f0+f1*f1+f2*f2+f3*f3;
        #pragma unroll
        for (int o = 16; o; o >>= 1) {
            s  += __shfl_xor_sync(0xffffffffu, s,  o);
            ss += __shfl_xor_sync(0xffffffffu, ss, o);
        }
        float m = s*(1.f/128.f), var = ss*(1.f/128.f) - m*m;
        float r = rsqrtf(var + LN_EPS);
        __nv_bfloat16* dst = g_xn + base + (size_t)v*CC + c0;
        stbf2(dst,     make_float2((f0-m)*r*gg.x + bb.x, (f1-m)*r*gg.y + bb.y));
        stbf2(dst + 2, make_float2((f2-m)*r*gg.z + bb.z, (f3-m)*r*gg.w + bb.w));
    }
}

__global__ void k_tout(float* __restrict__ out) {
    int bt = blockIdx.x;
    int t = bt % TT, b = bt / TT;
    __shared__ float sm[CC*VV];
    size_t base = ((size_t)(b*TT + t))*VV*CC;
    for (int idx = threadIdx.x; idx < CC*VV; idx += blockDim.x)
        sm[idx] = g_xT[base + idx];
    __syncthreads();
    for (int idx = threadIdx.x; idx < CC*VV; idx += blockDim.x) {
        int c = idx / VV, v = idx % VV;
        out[(((size_t)b*CC + c)*TT + t)*VV + v] = sm[v*CC + c];
    }
}

// ---------------- weight prep: single launch, both layers ------------------
__global__ void k_wprep(const float* __restrict__ wq,  const float* __restrict__ wkv,
                        const float* __restrict__ wo,  const float* __restrict__ f1a,
                        const float* __restrict__ f1b, const float* __restrict__ gwq,
                        const float* __restrict__ gwkv,const float* __restrict__ gwo,
                        const float* __restrict__ f2a, const float* __restrict__ f2b,
                        __nv_bfloat16* __restrict__ dst)
{
    for (int gidx = blockIdx.x*256 + threadIdx.x; gidx < 2*WT_LSZ; gidx += gridDim.x*256) {
        int l   = gidx / WT_LSZ;
        int idx = gidx - l*WT_LSZ;
        float v;
        if (idx < OFF_LWO) {
            int m = idx >> 7, k = idx & 127;
            v = (m < 512) ? wq[(size_t)l*65536 + k*512 + m]
                          : wkv[(size_t)l*131072 + k*1024 + (m-512)];
        } else if (idx < OFF_F1A) {
            int r = idx - OFF_LWO; int m = r >> 9, k = r & 511;
            v = wo[(size_t)l*65536 + k*128 + m];
        } else if (idx < OFF_F1B) {
            int r = idx - OFF_F1A; int m = r >> 7, k = r & 127;
            v = f1a[(size_t)l*65536 + k*512 + m];
        } else if (idx < OFF_GWQ) {
            int r = idx - OFF_F1B; int m = r >> 9, k = r & 511;
            v = f1b[(size_t)l*65536 + k*128 + m];
        } else if (idx < OFF_GWKV) {
            int r = idx - OFF_GWQ; int m = r >> 7, k = r & 127;
            v = gwq[(size_t)l*65536 + k*512 + m];
        } else if (idx < OFF_GWO) {
            int r = idx - OFF_GWKV; int i = r / 896; int kk = r - i*896;
            int kp = kk >> 7, c = kk & 127;
            v = gwkv[(size_t)l*917504 + (c*PP + kp)*1024 + i];
        } else if (idx < OFF_F2A) {
            int r = idx - OFF_GWO; int m = r >> 9, k = r & 511;
            v = gwo[(size_t)l*65536 + k*128 + m];
        } else if (idx < OFF_F2B) {
            int r = idx - OFF_F2A; int m = r >> 7, k = r & 127;
            v = f2a[(size_t)l*65536 + k*512 + m];
        } else {
            int r = idx - OFF_F2B; int m = r >> 9, k = r & 511;
            v = f2b[(size_t)l*65536 + k*128 + m];
        }
        dst[gidx] = __float2bfloat16(v);
    }
}

// ---------------- channel layernorm (optionally fused gather) --------------
template<bool GATHER>
__global__ void __launch_bounds__(256) k_ln(const float* __restrict__ gam,
                                            const float* __restrict__ bet) {
    int n = blockIdx.x * 8 + (threadIdx.x >> 5);
    if (n >= NTOK) return;
    int lane = threadIdx.x & 31;
    float4 a = ((const float4*)(g_xT + (size_t)n*CC))[lane];
    float s  = a.x + a.y + a.z + a.w;
    float ss = a.x*a.x + a.y*a.y + a.z*a.z + a.w*a.w;
    #pragma unroll
    for (int o = 16; o; o >>= 1) {
        s  += __shfl_xor_sync(0xffffffffu, s,  o);
        ss += __shfl_xor_sync(0xffffffffu, ss, o);
    }
    float m   = s * (1.f/128.f);
    float var = ss * (1.f/128.f) - m*m;
    float r   = rsqrtf(var + LN_EPS);
    float4 gg = ((const float4*)gam)[lane];
    float4 bb = ((const float4*)bet)[lane];
    float2 p0 = make_float2((a.x - m)*r*gg.x + bb.x, (a.y - m)*r*gg.y + bb.y);
    float2 p1 = make_float2((a.z - m)*r*gg.z + bb.z, (a.w - m)*r*gg.w + bb.w);
    uint2 st;
    __nv_bfloat162 h0 = __float22bfloat162_rn(p0);
    __nv_bfloat162 h1 = __float22bfloat162_rn(p1);
    st.x = *reinterpret_cast<uint32_t*>(&h0);
    st.y = *reinterpret_cast<uint32_t*>(&h1);
    *reinterpret_cast<uint2*>(g_xn + (size_t)n*CC + lane*4) = st;
    if (GATHER) {
        int v  = n % VV;
        int bt = n / VV;
        int t  = bt % TT;
        int b  = bt / TT;
        int tt = t / PP, kp = t - tt*PP;
        int nk = (b*NTP + tt)*VV + v;
        *reinterpret_cast<uint2*>(g_xg + (size_t)nk*896 + kp*128 + lane*4) = st;
    }
}

// ---------------- GEMM mainloop body (shared) -------------------------------
#define GSTAGE_BYTES 16384
#define GEMM_SMEM   (4*GSTAGE_BYTES)

#define GEMM_BODY(A_, Wt_, Nrows_, K_, rowBase_, colBase_)                        \
    const int t = threadIdx.x;                                                    \
    const int lane = t & 31, wid = t >> 5;                                         \
    const int wr = wid & 1, wc = wid >> 1;                                         \
    const int rL = t >> 1, half = t & 1;                                           \
    int ga = (rowBase_) + rL; if (ga >= (Nrows_)) ga = (Nrows_) - 1;               \
    const __nv_bfloat16* aP = (A_)  + (size_t)ga * (K_) + (half << 4);             \
    const __nv_bfloat16* bP = (Wt_) + (size_t)((colBase_) + rL) * (K_) + (half << 4); \
    const int fL = (rL >> 1) & 3;                                                  \
    const uint32_t dA = rL*64 + 16*((2*half) ^ fL);                                \
    const uint32_t dB = 8192 + dA;                                                 \
    const int rA  = (lane & 7) + ((lane >> 3) & 1) * 8;                            \
    const int ca  = lane >> 4;                                                     \
    const int fra = (rA >> 1) & 3;                                                 \
    const int g   = lane >> 3;                                                     \
    const int nB  = ((g >> 1) & 1) * 8 + (lane & 7);                               \
    const int cb  = g & 1;                                                         \
    const int fnb = (nB >> 1) & 3;                                                 \
    float acc[4][4][4];                                                            \
    _Pragma("unroll")                                                              \
    for (int mt = 0; mt < 4; ++mt)                                                 \
        _Pragma("unroll")                                                          \
        for (int nt = 0; nt < 4; ++nt)                                             \
            _Pragma("unroll")                                                      \
            for (int e = 0; e < 4; ++e) acc[mt][nt][e] = 0.f;                      \
    const int nk = (K_) >> 5;                                                      \
    G_ISSUE(0); asm volatile("cp.async.commit_group;");                            \
    G_ISSUE(1); asm volatile("cp.async.commit_group;");                            \
    G_ISSUE(2); asm volatile("cp.async.commit_group;");                            \
    for (int kt = 0; kt < nk; ++kt) {                                              \
        asm volatile("cp.async.wait_group 2;");                                    \
        __syncthreads();                                                           \
        if (kt + 3 < nk) G_ISSUE(kt + 3);                                          \
        asm volatile("cp.async.commit_group;");                                    \
        const uint32_t stA = smb + (kt & 3) * GSTAGE_BYTES;                        \
        const uint32_t stB = stA + 8192;                                           \
        _Pragma("unroll")                                                          \
        for (int ks = 0; ks < 2; ++ks) {                                           \
            uint32_t af[4][4], bf[4][2];                                           \
            _Pragma("unroll")                                                      \
            for (int mt = 0; mt < 4; ++mt) {                                       \
                uint32_t addr = stA + (uint32_t)((wr*64 + mt*16 + rA)*64)          \
                              + 16u*(uint32_t)(((ks<<1) + ca) ^ fra);              \
                asm volatile("ldmatrix.sync.aligned.m8n8.x4.shared.b16 {%0,%1,%2,%3}, [%4];" \
                    : "=r"(af[mt][0]), "=r"(af[mt][1]), "=r"(af[mt][2]), "=r"(af[mt][3]) \
                    : "r"(addr));                                                  \
            }                                                                      \
            _Pragma("unroll")                                                      \
            for (int j = 0; j < 2; ++j) {                                          \
                int n = wc*32 + j*16 + nB;                                         \
                uint32_t addr = stB + (uint32_t)(n*64)                             \
                              + 16u*(uint32_t)(((ks<<1) + cb) ^ fnb);              \
                asm volatile("ldmatrix.sync.aligned.m8n8.x4.shared.b16 {%0,%1,%2,%3}, [%4];" \
                    : "=r"(bf[2*j][0]), "=r"(bf[2*j][1]), "=r"(bf[2*j+1][0]), "=r"(bf[2*j+1][1]) \
                    : "r"(addr));                                                  \
            }                                                                      \
            _Pragma("unroll")                                                      \
            for (int mt = 0; mt < 4; ++mt)                                         \
                _Pragma("unroll")                                                  \
                for (int nt = 0; nt < 4; ++nt)                                     \
                    mma_bf16(acc[mt][nt], af[mt], bf[nt]);                         \
        }                                                                          \
    }

#define G_ISSUE(kt_) do {                                                   \
    const uint32_t st_ = smb + ((kt_) & 3) * GSTAGE_BYTES;                   \
    size_t sa_ = __cvta_generic_to_global(aP + ((size_t)(kt_) << 5));        \
    size_t sb_ = __cvta_generic_to_global(bP + ((size_t)(kt_) << 5));        \
    uint32_t a1_ = st_ + dA, b1_ = st_ + dB;                                 \
    asm volatile("cp.async.cg.shared.global [%0], [%1], 16;" :: "r"(a1_), "l"(sa_)); \
    asm volatile("cp.async.cg.shared.global [%0], [%1], 16;" :: "r"(a1_ ^ 16u), "l"(sa_ + 16)); \
    asm volatile("cp.async.cg.shared.global [%0], [%1], 16;" :: "r"(b1_), "l"(sb_)); \
    asm volatile("cp.async.cg.shared.global [%0], [%1], 16;" :: "r"(b1_ ^ 16u), "l"(sb_ + 16)); \
} while (0)

// ---------------- bf16 mma GEMM: C[N,M] = A[N,K] @ Wt[M,K]^T ---------------
// EPI: 0 none (bf16 out), 2 bias+gelu (bf16 out), 3 bias+residual (fp32 out)
template<int EPI>
__global__ void __launch_bounds__(256, 2) k_gemm_bf(
    const __nv_bfloat16* __restrict__ A, const __nv_bfloat16* __restrict__ Wt,
    const float* __restrict__ bias, const float* __restrict__ res,
    void* __restrict__ Cv, int Nrows, int K, int M)
{
    extern __shared__ char smraw[];
    const uint32_t smb = smem_u32(smraw);
    const int rowBase = blockIdx.y << 7, colBase = blockIdx.x << 7;

    GEMM_BODY(A, Wt, Nrows, K, rowBase, colBase)

    #pragma unroll
    for (int nt = 0; nt < 4; ++nt) {
        const int col = colBase + wc*32 + nt*8 + (lane & 3)*2;
        float2 bb = make_float2(0.f, 0.f);
        if (EPI >= 1) bb = *(const float2*)(bias + col);
        #pragma unroll
        for (int mt = 0; mt < 4; ++mt) {
            #pragma unroll
            for (int hf = 0; hf < 2; ++hf) {
                const int r = rowBase + wr*64 + mt*16 + (lane >> 2) + hf*8;
                if (r >= Nrows) continue;
                float2 o = make_float2(acc[mt][nt][hf*2+0] + bb.x,
                                       acc[mt][nt][hf*2+1] + bb.y);
                if (EPI == 2) { o.x = gelu_exact(o.x); o.y = gelu_exact(o.y); }
                if (EPI == 3) {
                    float2 rv = *(const float2*)(res + (size_t)r*M + col);
                    o.x += rv.x; o.y += rv.y;
                    *(float2*)((float*)Cv + (size_t)r*M + col) = o;
                } else {
                    stbf2((__nv_bfloat16*)Cv + (size_t)r*M + col, o);
                }
            }
        }
    }
}

// ---------------- merged GWQ + GWKV launch (both EPI0, independent) --------
__global__ void __launch_bounds__(256, 2) k_gemm_gproj(
    const __nv_bfloat16* __restrict__ xn, const __nv_bfloat16* __restrict__ wtQ,
    __nv_bfloat16* __restrict__ Cq,
    const __nv_bfloat16* __restrict__ xg, const __nv_bfloat16* __restrict__ wtKV,
    __nv_bfloat16* __restrict__ Ckv)
{
    extern __shared__ char smraw[];
    const uint32_t smb = smem_u32(smraw);

    const int i = blockIdx.x;
    const bool isQ = (i < 3676);
    const __nv_bfloat16* A;
    const __nv_bfloat16* Wt;
    __nv_bfloat16* C;
    int Nrows, K, M, rowBase, colBase;
    if (isQ) {
        A = xn; Wt = wtQ; C = Cq;
        Nrows = NTOK; K = 128; M = 512;
        colBase = (i & 3) << 7; rowBase = (i >> 2) << 7;
    } else {
        int j = i - 3676;
        A = xg; Wt = wtKV; C = Ckv;
        Nrows = NKTOK; K = 896; M = 1024;
        colBase = (j & 7) << 7; rowBase = (j >> 3) << 7;
    }

    GEMM_BODY(A, Wt, Nrows, K, rowBase, colBase)

    #pragma unroll
    for (int nt = 0; nt < 4; ++nt) {
        const int col = colBase + wc*32 + nt*8 + (lane & 3)*2;
        #pragma unroll
        for (int mt = 0; mt < 4; ++mt) {
            #pragma unroll
            for (int hf = 0; hf < 2; ++hf) {
                const int r = rowBase + wr*64 + mt*16 + (lane >> 2) + hf*8;
                if (r >= Nrows) continue;
                stbf2(C + (size_t)r*M + col,
                      make_float2(acc[mt][nt][hf*2+0], acc[mt][nt][hf*2+1]));
            }
        }
    }
}

// ---------------- local attention: one warp per (b, patch, v, head) --------
// softmax: max-free (values tiny), SCALE folded into exp2 constant
__global__ void __launch_bounds__(256) k_lattn() {
    int w = blockIdx.x * 8 + (threadIdx.x >> 5);
    int lane = threadIdx.x & 31;
    int h = w & 7;
    int g = w >> 3;
    int v = g % VV;
    int r = g / VV;
    int tt = r % NTP;
    int b = r / NTP;
    int d0 = lane * 2;

    float2 q[PP], kk[PP], vv[PP];
    #pragma unroll
    for (int p = 0; p < PP; ++p) {
        int n = (b*TT + tt*PP + p)*VV + v;
        const __nv_bfloat16* rowp = g_qkv + (size_t)n*1536 + h*DH + d0;
        q[p]  = ldbf2(rowp);
        kk[p] = ldbf2(rowp + 512);
        vv[p] = ldbf2(rowp + 1024);
    }
    float dots[PP][PP];
    #pragma unroll
    for (int i = 0; i < PP; ++i)
        #pragma unroll
        for (int j = 0; j < PP; ++j)
            dots[i][j] = q[i].x*kk[j].x + q[i].y*kk[j].y;
    #pragma unroll
    for (int o = 16; o; o >>= 1)
        #pragma unroll
        for (int i = 0; i < PP; ++i)
            #pragma unroll
            for (int j = 0; j < PP; ++j)
                dots[i][j] += __shfl_xor_sync(0xffffffffu, dots[i][j], o);
    #pragma unroll
    for (int i = 0; i < PP; ++i) {
        float s = 0.f;
        #pragma unroll
        for (int j = 0; j < PP; ++j) {
            dots[i][j] = exp2f(dots[i][j] * EXP2C);
            s += dots[i][j];
        }
        float inv = 1.f / s;
        #pragma unroll
        for (int j = 0; j < PP; ++j) dots[i][j] *= inv;
    }
    #pragma unroll
    for (int i = 0; i < PP; ++i) {
        float2 o = make_float2(0.f, 0.f);
        #pragma unroll
        for (int j = 0; j < PP; ++j) {
            o.x += dots[i][j] * vv[j].x;
            o.y += dots[i][j] * vv[j].y;
        }
        int n = (b*TT + tt*PP + i)*VV + v;
        stbf2(g_ao + (size_t)n*INNER + h*DH + d0, o);
    }
}

// ---------------- global attention: one block per (b, h, v) ----------------
__global__ void __launch_bounds__(160) k_gattn() {
    int bid = blockIdx.x;
    int v = bid % VV;
    int rr = bid / VV;
    int h = rr & 7;
    int b = rr >> 3;
    __shared__ float ks[NTP][DH];
    __shared__ float vs[NTP][DH];
    for (int idx = threadIdx.x; idx < NTP*DH/2; idx += 160) {
        int j = idx >> 5, d2 = idx & 31;
        int nk = (b*NTP + j)*VV + v;
        size_t o = (size_t)nk*1024 + h*DH + d2*2;
        float2 kf = ldbf2(g_kv + o);
        float2 vf = ldbf2(g_kv + o + 512);
        ks[j][d2*2] = kf.x; ks[j][d2*2+1] = kf.y;
        vs[j][d2*2] = vf.x; vs[j][d2*2+1] = vf.y;
    }
    __syncthreads();
    int tid = threadIdx.x;
    if (tid >= 147) return;
    int i0 = 2*tid;
    size_t q0 = (size_t)((b*TT + i0)*VV + v)*INNER + h*DH;
    size_t q1 = q0 + (size_t)VV*INNER;

    float da[NTP], db[NTP];
    #pragma unroll
    for (int j = 0; j < NTP; ++j) { da[j] = 0.f; db[j] = 0.f; }

    for (int dchunk = 0; dchunk < 4; ++dchunk) {
        int dbase = dchunk * 16;
        float qa[16], qb[16];
        {
            uint4 u0 = *(const uint4*)(g_q + q0 + dbase);
            uint4 u1 = *(const uint4*)(g_q + q0 + dbase + 8);
            uint4 w0 = *(const uint4*)(g_q + q1 + dbase);
            uint4 w1 = *(const uint4*)(g_q + q1 + dbase + 8);
            float2 f;
            f=u2f2(u0.x); qa[0]=f.x; qa[1]=f.y;  f=u2f2(u0.y); qa[2]=f.x; qa[3]=f.y;
            f=u2f2(u0.z); qa[4]=f.x; qa[5]=f.y;  f=u2f2(u0.w); qa[6]=f.x; qa[7]=f.y;
            f=u2f2(u1.x); qa[8]=f.x; qa[9]=f.y;  f=u2f2(u1.y); qa[10]=f.x; qa[11]=f.y;
            f=u2f2(u1.z); qa[12]=f.x; qa[13]=f.y; f=u2f2(u1.w); qa[14]=f.x; qa[15]=f.y;
            f=u2f2(w0.x); qb[0]=f.x; qb[1]=f.y;  f=u2f2(w0.y); qb[2]=f.x; qb[3]=f.y;
            f=u2f2(w0.z); qb[4]=f.x; qb[5]=f.y;  f=u2f2(w0.w); qb[6]=f.x; qb[7]=f.y;
            f=u2f2(w1.x); qb[8]=f.x; qb[9]=f.y;  f=u2f2(w1.y); qb[10]=f.x; qb[11]=f.y;
            f=u2f2(w1.z); qb[12]=f.x; qb[13]=f.y; f=u2f2(w1.w); qb[14]=f.x; qb[15]=f.y;
        }
        #pragma unroll
        for (int j = 0; j < NTP; ++j) {
            #pragma unroll
            for (int dd = 0; dd < 16; ++dd) {
                float kv = ks[j][dbase + dd];
                da[j] += qa[dd] * kv;
                db[j] += qb[dd] * kv;
            }
        }
    }
    {
        float s = 0.f;
        #pragma unroll
        for (int j = 0; j < NTP; ++j) { da[j] = exp2f(da[j] * EXP2C); s += da[j]; }
        float inv = 1.f / s;
        #pragma unroll
        for (int j = 0; j < NTP; ++j) da[j] *= inv;
    }
    {
        float s = 0.f;
        #pragma unroll
        for (int j = 0; j < NTP; ++j) { db[j] = exp2f(db[j] * EXP2C); s += db[j]; }
        float inv = 1.f / s;
        #pragma unroll
        for (int j = 0; j < NTP; ++j) db[j] *= inv;
    }
    size_t o0 = q0, o1 = q1;
    for (int dchunk = 0; dchunk < 4; ++dchunk) {
        int dbase = dchunk * 16;
        float oa[16], ob[16];
        #pragma unroll
        for (int dd = 0; dd < 16; ++dd) { oa[dd] = 0.f; ob[dd] = 0.f; }
        #pragma unroll
        for (int j = 0; j < NTP; ++j) {
            #pragma unroll
            for (int dd = 0; dd < 16; ++dd) {
                float vv = vs[j][dbase + dd];
                oa[dd] += da[j] * vv;
                ob[dd] += db[j] * vv;
            }
        }
        #pragma unroll
        for (int dd = 0; dd < 16; dd += 2) {
            stbf2(g_ao + o0 + dbase + dd, make_float2(oa[dd], oa[dd+1]));
            stbf2(g_ao + o1 + dbase + dd, make_float2(ob[dd], ob[dd+1]));
        }
    }
}

// ---------------- launch -----------------------------------------------------
extern "C" void kernel_launch(void* const* d_in, const int* in_sizes, int n_in,
                              void* d_out, int out_size) {
    (void)in_sizes; (void)n_in; (void)out_size;
    float* p_xT;
    __nv_bfloat16 *p_xn, *p_qkv, *p_q, *p_kv, *p_ao, *p_xg, *p_wt;
    cudaGetSymbolAddress((void**)&p_xT,  g_xT);
    cudaGetSymbolAddress((void**)&p_xn,  g_xn);
    cudaGetSymbolAddress((void**)&p_qkv, g_qkv);
    cudaGetSymbolAddress((void**)&p_q,   g_q);
    cudaGetSymbolAddress((void**)&p_kv,  g_kv);
    cudaGetSymbolAddress((void**)&p_ao,  g_ao);
    cudaGetSymbolAddress((void**)&p_xg,  g_xg);
    cudaGetSymbolAddress((void**)&p_wt,  g_wt);

    cudaFuncSetAttribute(k_gemm_bf<0>, cudaFuncAttributeMaxDynamicSharedMemorySize, GEMM_SMEM);
    cudaFuncSetAttribute(k_gemm_bf<2>, cudaFuncAttributeMaxDynamicSharedMemorySize, GEMM_SMEM);
    cudaFuncSetAttribute(k_gemm_bf<3>, cudaFuncAttributeMaxDynamicSharedMemorySize, GEMM_SMEM);
    cudaFuncSetAttribute(k_gemm_gproj, cudaFuncAttributeMaxDynamicSharedMemorySize, GEMM_SMEM);

    const float* x      = (const float*)d_in[0];
    const float* ln1_g  = (const float*)d_in[1];
    const float* ln1_b  = (const float*)d_in[2];
    const float* la_wq  = (const float*)d_in[3];
    const float* la_wkv = (const float*)d_in[4];
    const float* la_wo  = (const float*)d_in[5];
    const float* la_bo  = (const float*)d_in[6];
    const float* ln2_g  = (const float*)d_in[7];
    const float* ln2_b  = (const float*)d_in[8];
    const float* ff1_w1 = (const float*)d_in[9];
    const float* ff1_b1 = (const float*)d_in[10];
    const float* ff1_w2 = (const float*)d_in[11];
    const float* ff1_b2 = (const float*)d_in[12];
    const float* ln3_g  = (const float*)d_in[13];
    const float* ln3_b  = (const float*)d_in[14];
    const float* ga_wq  = (const float*)d_in[15];
    const float* ga_wkv = (const float*)d_in[16];
    const float* ga_wo  = (const float*)d_in[17];
    const float* ga_bo  = (const float*)d_in[18];
    const float* ln4_g  = (const float*)d_in[19];
    const float* ln4_b  = (const float*)d_in[20];
    const float* ff2_w1 = (const float*)d_in[21];
    const float* ff2_b1 = (const float*)d_in[22];
    const float* ff2_w2 = (const float*)d_in[23];
    const float* ff2_b2 = (const float*)d_in[24];

    // weight prep: single launch, both layers
    k_wprep<<<8192, 256>>>(la_wq, la_wkv, la_wo, ff1_w1, ff1_w2,
                           ga_wq, ga_wkv, ga_wo, ff2_w1, ff2_w2, p_wt);

    const int rowTiles  = (NTOK  + 127) / 128;   // 919
    const int lnGrid = NTOK / 8;

    // transpose-in + fused LN1(layer 0)
    k_tin<<<BB*TT, 256>>>(x, ln1_g, ln1_b);

    for (int l = 0; l < 2; ++l) {
        __nv_bfloat16* wb = p_wt + (size_t)l*WT_LSZ;
        // --- local attention block ---
        if (l == 1) k_ln<false><<<lnGrid, 256>>>(ln1_g + CC, ln1_b + CC);
        k_gemm_bf<0><<<dim3(12, rowTiles), 256, GEMM_SMEM>>>(
            p_xn, wb + OFF_LQKV, nullptr, nullptr, p_qkv, NTOK, 128, 1536);
        k_lattn<<<NKTOK, 256>>>();
        k_gemm_bf<3><<<dim3(1, rowTiles), 256, GEMM_SMEM>>>(
            p_ao, wb + OFF_LWO, la_bo + l*CC, p_xT, p_xT, NTOK, 512, 128);
        // --- ff1 ---
        k_ln<false><<<lnGrid, 256>>>(ln2_g + l*CC, ln2_b + l*CC);
        k_gemm_bf<2><<<dim3(4, rowTiles), 256, GEMM_SMEM>>>(
            p_xn, wb + OFF_F1A, ff1_b1 + l*512, nullptr, p_ao, NTOK, 128, 512);
        k_gemm_bf<3><<<dim3(1, rowTiles), 256, GEMM_SMEM>>>(
            p_ao, wb + OFF_F1B, ff1_b2 + l*CC, p_xT, p_xT, NTOK, 512, 128);
        // --- global attention block (LN + fused gather, merged q/kv proj) ---
        k_ln<true><<<lnGrid, 256>>>(ln3_g + l*CC, ln3_b + l*CC);
        k_gemm_gproj<<<4732, 256, GEMM_SMEM>>>(
            p_xn, wb + OFF_GWQ, p_q, p_xg, wb + OFF_GWKV, p_kv);
        k_gattn<<<BB*NHEAD*VV, 160>>>();
        k_gemm_bf<3><<<dim3(1, rowTiles), 256, GEMM_SMEM>>>(
            p_ao, wb + OFF_GWO, ga_bo + l*CC, p_xT, p_xT, NTOK, 512, 128);
        // --- ff2 ---
        k_ln<false><<<lnGrid, 256>>>(ln4_g + l*CC, ln4_b + l*CC);
        k_gemm_bf<2><<<dim3(4, rowTiles), 256, GEMM_SMEM>>>(
            p_xn, wb + OFF_F2A, ff2_b1 + l*512, nullptr, p_ao, NTOK, 128, 512);
        k_gemm_bf<3><<<dim3(1, rowTiles), 256, GEMM_SMEM>>>(
            p_ao, wb + OFF_F2B, ff2_b2 + l*CC, p_xT, p_xT, NTOK, 512, 128);
    }
    k_tout<<<BB*TT, 256>>>((float*)d_out);
}

// round 17
// speedup vs baseline: 1.0947x; 1.0369x over previous
#include <cuda_runtime.h>
#include <cuda_bf16.h>
#include <math.h>
#include <stdint.h>

// ---------------- problem constants ----------------
#define BB     16
#define CC     128
#define TT     294
#define VV     25
#define NTOK   (BB*TT*VV)        // 117600 tokens
#define INNER  512
#define NHEAD  8
#define DH     64
#define PP     7
#define NTP    42                 // T / P
#define NKTOK  (BB*NTP*VV)        // 16800 kv tokens (global)
#define SCALE_ATT 0.125f
#define EXP2C  (0.125f * 1.44269504088896340736f)   // scale * log2(e)
#define LN_EPS 1e-5f

// transposed bf16 weight layout (elements, per layer)
#define OFF_LQKV  0               // [1536,128]
#define OFF_LWO   196608          // [128,512]
#define OFF_F1A   262144          // [512,128]
#define OFF_F1B   327680          // [128,512]
#define OFF_GWQ   393216          // [512,128]
#define OFF_GWKV  458752          // [1024,896] (k reordered kp*128+c)
#define OFF_GWO   1376256         // [128,512]
#define OFF_F2A   1441792         // [512,128]
#define OFF_F2B   1507328         // [128,512]
#define WT_LSZ    1572864

// ---------------- scratch (static device memory; no allocs) ----------------
__device__ __align__(16) float          g_xT[NTOK*CC];          // residual, fp32
__device__ __align__(16) __nv_bfloat16  g_xn[NTOK*CC];          // LN output
__device__ __align__(16) __nv_bfloat16  g_qkv[(size_t)NTOK*1536];
__device__ __align__(16) __nv_bfloat16  g_q [NTOK*INNER];
__device__ __align__(16) __nv_bfloat16  g_kv[NKTOK*1024];
__device__ __align__(16) __nv_bfloat16  g_ao[NTOK*INNER];       // attn out / ff hidden
__device__ __align__(16) __nv_bfloat16  g_xg[NKTOK*896];
__device__ __align__(16) __nv_bfloat16  g_wt[2*WT_LSZ];

// ---------------- helpers ----------------
__device__ __forceinline__ uint32_t smem_u32(const void* p) {
    uint32_t a;
    asm("{ .reg .u64 t; cvta.to.shared.u64 t, %1; cvt.u32.u64 %0, t; }" : "=r"(a) : "l"(p));
    return a;
}
__device__ __forceinline__ float2 ldbf2(const __nv_bfloat16* p) {
    return __bfloat1622float2(*reinterpret_cast<const __nv_bfloat162*>(p));
}
__device__ __forceinline__ void stbf2(__nv_bfloat16* p, float2 v) {
    *reinterpret_cast<__nv_bfloat162*>(p) = __float22bfloat162_rn(v);
}
__device__ __forceinline__ float2 u2f2(uint32_t u) {
    return __bfloat1622float2(*reinterpret_cast<const __nv_bfloat162*>(&u));
}
__device__ __forceinline__ void mma_bf16(float* d, const uint32_t* a, const uint32_t* b) {
    asm volatile(
        "mma.sync.aligned.m16n8k16.row.col.f32.bf16.bf16.f32 "
        "{%0,%1,%2,%3}, {%4,%5,%6,%7}, {%8,%9}, {%0,%1,%2,%3};"
        : "+f"(d[0]), "+f"(d[1]), "+f"(d[2]), "+f"(d[3])
        : "r"(a[0]), "r"(a[1]), "r"(a[2]), "r"(a[3]), "r"(b[0]), "r"(b[1]));
}
__device__ __forceinline__ float gelu_exact(float v) {
    return 0.5f * v * (1.0f + erff(v * 0.7071067811865475f));
}

// ---------------- transpose in + fused LN(layer0, ln1) ----------------------
__global__ void k_tin(const float* __restrict__ x,
                      const float* __restrict__ gam, const float* __restrict__ bet) {
    int bt = blockIdx.x;
    int t = bt % TT, b = bt / TT;
    __shared__ float sm[CC*VV];
    for (int idx = threadIdx.x; idx < CC*VV; idx += blockDim.x) {
        int c = idx / VV, v = idx % VV;
        sm[idx] = x[(((size_t)b*CC + c)*TT + t)*VV + v];
    }
    __syncthreads();
    size_t base = ((size_t)(b*TT + t))*VV*CC;
    for (int idx = threadIdx.x; idx < CC*VV; idx += blockDim.x) {
        int v = idx / CC, c = idx % CC;
        g_xT[base + idx] = sm[c*VV + v];
    }
    int wid = threadIdx.x >> 5, lane = threadIdx.x & 31;
    int c0 = lane * 4;
    float4 gg = *(const float4*)(gam + c0);
    float4 bb = *(const float4*)(bet + c0);
    for (int v = wid; v < VV; v += 8) {
        float f0 = sm[(c0+0)*VV + v], f1 = sm[(c0+1)*VV + v];
        float f2 = sm[(c0+2)*VV + v], f3 = sm[(c0+3)*VV + v];
        float s = f0+f1+f2+f3, ss = f0*f0+f1*f1+f2*f2+f3*f3;
        #pragma unroll
        for (int o = 16; o; o >>= 1) {
            s  += __shfl_xor_sync(0xffffffffu, s,  o);
            ss += __shfl_xor_sync(0xffffffffu, ss, o);
        }
        float m = s*(1.f/128.f), var = ss*(1.f/128.f) - m*m;
        float r = rsqrtf(var + LN_EPS);
        __nv_bfloat16* dst = g_xn + base + (size_t)v*CC + c0;
        stbf2(dst,     make_float2((f0-m)*r*gg.x + bb.x, (f1-m)*r*gg.y + bb.y));
        stbf2(dst + 2, make_float2((f2-m)*r*gg.z + bb.z, (f3-m)*r*gg.w + bb.w));
    }
}

__global__ void k_tout(float* __restrict__ out) {
    int bt = blockIdx.x;
    int t = bt % TT, b = bt / TT;
    __shared__ float sm[CC*VV];
    size_t base = ((size_t)(b*TT + t))*VV*CC;
    for (int idx = threadIdx.x; idx < CC*VV; idx += blockDim.x)
        sm[idx] = g_xT[base + idx];
    __syncthreads();
    for (int idx = threadIdx.x; idx < CC*VV; idx += blockDim.x) {
        int c = idx / VV, v = idx % VV;
        out[(((size_t)b*CC + c)*TT + t)*VV + v] = sm[v*CC + c];
    }
}

// ---------------- weight prep: single launch, both layers ------------------
__global__ void k_wprep(const float* __restrict__ wq,  const float* __restrict__ wkv,
                        const float* __restrict__ wo,  const float* __restrict__ f1a,
                        const float* __restrict__ f1b, const float* __restrict__ gwq,
                        const float* __restrict__ gwkv,const float* __restrict__ gwo,
                        const float* __restrict__ f2a, const float* __restrict__ f2b,
                        __nv_bfloat16* __restrict__ dst)
{
    for (int gidx = blockIdx.x*256 + threadIdx.x; gidx < 2*WT_LSZ; gidx += gridDim.x*256) {
        int l   = gidx / WT_LSZ;
        int idx = gidx - l*WT_LSZ;
        float v;
        if (idx < OFF_LWO) {
            int m = idx >> 7, k = idx & 127;
            v = (m < 512) ? wq[(size_t)l*65536 + k*512 + m]
                          : wkv[(size_t)l*131072 + k*1024 + (m-512)];
        } else if (idx < OFF_F1A) {
            int r = idx - OFF_LWO; int m = r >> 9, k = r & 511;
            v = wo[(size_t)l*65536 + k*128 + m];
        } else if (idx < OFF_F1B) {
            int r = idx - OFF_F1A; int m = r >> 7, k = r & 127;
            v = f1a[(size_t)l*65536 + k*512 + m];
        } else if (idx < OFF_GWQ) {
            int r = idx - OFF_F1B; int m = r >> 9, k = r & 511;
            v = f1b[(size_t)l*65536 + k*128 + m];
        } else if (idx < OFF_GWKV) {
            int r = idx - OFF_GWQ; int m = r >> 7, k = r & 127;
            v = gwq[(size_t)l*65536 + k*512 + m];
        } else if (idx < OFF_GWO) {
            int r = idx - OFF_GWKV; int i = r / 896; int kk = r - i*896;
            int kp = kk >> 7, c = kk & 127;
            v = gwkv[(size_t)l*917504 + (c*PP + kp)*1024 + i];
        } else if (idx < OFF_F2A) {
            int r = idx - OFF_GWO; int m = r >> 9, k = r & 511;
            v = gwo[(size_t)l*65536 + k*128 + m];
        } else if (idx < OFF_F2B) {
            int r = idx - OFF_F2A; int m = r >> 7, k = r & 127;
            v = f2a[(size_t)l*65536 + k*512 + m];
        } else {
            int r = idx - OFF_F2B; int m = r >> 9, k = r & 511;
            v = f2b[(size_t)l*65536 + k*128 + m];
        }
        dst[gidx] = __float2bfloat16(v);
    }
}

// ---------------- channel layernorm (optionally fused gather) --------------
template<bool GATHER>
__global__ void __launch_bounds__(256) k_ln(const float* __restrict__ gam,
                                            const float* __restrict__ bet) {
    int n = blockIdx.x * 8 + (threadIdx.x >> 5);
    if (n >= NTOK) return;
    int lane = threadIdx.x & 31;
    float4 a = ((const float4*)(g_xT + (size_t)n*CC))[lane];
    float s  = a.x + a.y + a.z + a.w;
    float ss = a.x*a.x + a.y*a.y + a.z*a.z + a.w*a.w;
    #pragma unroll
    for (int o = 16; o; o >>= 1) {
        s  += __shfl_xor_sync(0xffffffffu, s,  o);
        ss += __shfl_xor_sync(0xffffffffu, ss, o);
    }
    float m   = s * (1.f/128.f);
    float var = ss * (1.f/128.f) - m*m;
    float r   = rsqrtf(var + LN_EPS);
    float4 gg = ((const float4*)gam)[lane];
    float4 bb = ((const float4*)bet)[lane];
    float2 p0 = make_float2((a.x - m)*r*gg.x + bb.x, (a.y - m)*r*gg.y + bb.y);
    float2 p1 = make_float2((a.z - m)*r*gg.z + bb.z, (a.w - m)*r*gg.w + bb.w);
    uint2 st;
    __nv_bfloat162 h0 = __float22bfloat162_rn(p0);
    __nv_bfloat162 h1 = __float22bfloat162_rn(p1);
    st.x = *reinterpret_cast<uint32_t*>(&h0);
    st.y = *reinterpret_cast<uint32_t*>(&h1);
    *reinterpret_cast<uint2*>(g_xn + (size_t)n*CC + lane*4) = st;
    if (GATHER) {
        int v  = n % VV;
        int bt = n / VV;
        int t  = bt % TT;
        int b  = bt / TT;
        int tt = t / PP, kp = t - tt*PP;
        int nk = (b*NTP + tt)*VV + v;
        *reinterpret_cast<uint2*>(g_xg + (size_t)nk*896 + kp*128 + lane*4) = st;
    }
}

// ---------------- GEMM mainloop body (shared) -------------------------------
#define GSTAGE_BYTES 16384
#define GEMM_SMEM   (4*GSTAGE_BYTES)

#define GEMM_BODY(A_, Wt_, Nrows_, K_, rowBase_, colBase_)                        \
    const int t = threadIdx.x;                                                    \
    const int lane = t & 31, wid = t >> 5;                                         \
    const int wr = wid & 1, wc = wid >> 1;                                         \
    const int rL = t >> 1, half = t & 1;                                           \
    int ga = (rowBase_) + rL; if (ga >= (Nrows_)) ga = (Nrows_) - 1;               \
    const __nv_bfloat16* aP = (A_)  + (size_t)ga * (K_) + (half << 4);             \
    const __nv_bfloat16* bP = (Wt_) + (size_t)((colBase_) + rL) * (K_) + (half << 4); \
    const int fL = (rL >> 1) & 3;                                                  \
    const uint32_t dA = rL*64 + 16*((2*half) ^ fL);                                \
    const uint32_t dB = 8192 + dA;                                                 \
    const int rA  = (lane & 7) + ((lane >> 3) & 1) * 8;                            \
    const int ca  = lane >> 4;                                                     \
    const int fra = (rA >> 1) & 3;                                                 \
    const int g   = lane >> 3;                                                     \
    const int nB  = ((g >> 1) & 1) * 8 + (lane & 7);                               \
    const int cb  = g & 1;                                                         \
    const int fnb = (nB >> 1) & 3;                                                 \
    float acc[4][4][4];                                                            \
    _Pragma("unroll")                                                              \
    for (int mt = 0; mt < 4; ++mt)                                                 \
        _Pragma("unroll")                                                          \
        for (int nt = 0; nt < 4; ++nt)                                             \
            _Pragma("unroll")                                                      \
            for (int e = 0; e < 4; ++e) acc[mt][nt][e] = 0.f;                      \
    const int nk = (K_) >> 5;                                                      \
    G_ISSUE(0); asm volatile("cp.async.commit_group;");                            \
    G_ISSUE(1); asm volatile("cp.async.commit_group;");                            \
    G_ISSUE(2); asm volatile("cp.async.commit_group;");                            \
    for (int kt = 0; kt < nk; ++kt) {                                              \
        asm volatile("cp.async.wait_group 2;");                                    \
        __syncthreads();                                                           \
        if (kt + 3 < nk) G_ISSUE(kt + 3);                                          \
        asm volatile("cp.async.commit_group;");                                    \
        const uint32_t stA = smb + (kt & 3) * GSTAGE_BYTES;                        \
        const uint32_t stB = stA + 8192;                                           \
        _Pragma("unroll")                                                          \
        for (int ks = 0; ks < 2; ++ks) {                                           \
            uint32_t af[4][4], bf[4][2];                                           \
            _Pragma("unroll")                                                      \
            for (int mt = 0; mt < 4; ++mt) {                                       \
                uint32_t addr = stA + (uint32_t)((wr*64 + mt*16 + rA)*64)          \
                              + 16u*(uint32_t)(((ks<<1) + ca) ^ fra);              \
                asm volatile("ldmatrix.sync.aligned.m8n8.x4.shared.b16 {%0,%1,%2,%3}, [%4];" \
                    : "=r"(af[mt][0]), "=r"(af[mt][1]), "=r"(af[mt][2]), "=r"(af[mt][3]) \
                    : "r"(addr));                                                  \
            }                                                                      \
            _Pragma("unroll")                                                      \
            for (int j = 0; j < 2; ++j) {                                          \
                int n = wc*32 + j*16 + nB;                                         \
                uint32_t addr = stB + (uint32_t)(n*64)                             \
                              + 16u*(uint32_t)(((ks<<1) + cb) ^ fnb);              \
                asm volatile("ldmatrix.sync.aligned.m8n8.x4.shared.b16 {%0,%1,%2,%3}, [%4];" \
                    : "=r"(bf[2*j][0]), "=r"(bf[2*j][1]), "=r"(bf[2*j+1][0]), "=r"(bf[2*j+1][1]) \
                    : "r"(addr));                                                  \
            }                                                                      \
            _Pragma("unroll")                                                      \
            for (int mt = 0; mt < 4; ++mt)                                         \
                _Pragma("unroll")                                                  \
                for (int nt = 0; nt < 4; ++nt)                                     \
                    mma_bf16(acc[mt][nt], af[mt], bf[nt]);                         \
        }                                                                          \
    }

#define G_ISSUE(kt_) do {                                                   \
    const uint32_t st_ = smb + ((kt_) & 3) * GSTAGE_BYTES;                   \
    size_t sa_ = __cvta_generic_to_global(aP + ((size_t)(kt_) << 5));        \
    size_t sb_ = __cvta_generic_to_global(bP + ((size_t)(kt_) << 5));        \
    uint32_t a1_ = st_ + dA, b1_ = st_ + dB;                                 \
    asm volatile("cp.async.cg.shared.global [%0], [%1], 16;" :: "r"(a1_), "l"(sa_)); \
    asm volatile("cp.async.cg.shared.global [%0], [%1], 16;" :: "r"(a1_ ^ 16u), "l"(sa_ + 16)); \
    asm volatile("cp.async.cg.shared.global [%0], [%1], 16;" :: "r"(b1_), "l"(sb_)); \
    asm volatile("cp.async.cg.shared.global [%0], [%1], 16;" :: "r"(b1_ ^ 16u), "l"(sb_ + 16)); \
} while (0)

// ---------------- bf16 mma GEMM: C[N,M] = A[N,K] @ Wt[M,K]^T ---------------
// EPI: 0 none (bf16 out), 2 bias+gelu (bf16 out), 3 bias+residual (fp32 out)
template<int EPI>
__global__ void __launch_bounds__(256, 2) k_gemm_bf(
    const __nv_bfloat16* __restrict__ A, const __nv_bfloat16* __restrict__ Wt,
    const float* __restrict__ bias, const float* __restrict__ res,
    void* __restrict__ Cv, int Nrows, int K, int M)
{
    extern __shared__ char smraw[];
    const uint32_t smb = smem_u32(smraw);
    const int rowBase = blockIdx.y << 7, colBase = blockIdx.x << 7;

    GEMM_BODY(A, Wt, Nrows, K, rowBase, colBase)

    #pragma unroll
    for (int nt = 0; nt < 4; ++nt) {
        const int col = colBase + wc*32 + nt*8 + (lane & 3)*2;
        float2 bb = make_float2(0.f, 0.f);
        if (EPI >= 1) bb = *(const float2*)(bias + col);
        #pragma unroll
        for (int mt = 0; mt < 4; ++mt) {
            #pragma unroll
            for (int hf = 0; hf < 2; ++hf) {
                const int r = rowBase + wr*64 + mt*16 + (lane >> 2) + hf*8;
                if (r >= Nrows) continue;
                float2 o = make_float2(acc[mt][nt][hf*2+0] + bb.x,
                                       acc[mt][nt][hf*2+1] + bb.y);
                if (EPI == 2) { o.x = gelu_exact(o.x); o.y = gelu_exact(o.y); }
                if (EPI == 3) {
                    float2 rv = *(const float2*)(res + (size_t)r*M + col);
                    o.x += rv.x; o.y += rv.y;
                    *(float2*)((float*)Cv + (size_t)r*M + col) = o;
                } else {
                    stbf2((__nv_bfloat16*)Cv + (size_t)r*M + col, o);
                }
            }
        }
    }
}

// ---------------- merged GWQ + GWKV launch (both EPI0, independent) --------
__global__ void __launch_bounds__(256, 2) k_gemm_gproj(
    const __nv_bfloat16* __restrict__ xn, const __nv_bfloat16* __restrict__ wtQ,
    __nv_bfloat16* __restrict__ Cq,
    const __nv_bfloat16* __restrict__ xg, const __nv_bfloat16* __restrict__ wtKV,
    __nv_bfloat16* __restrict__ Ckv)
{
    extern __shared__ char smraw[];
    const uint32_t smb = smem_u32(smraw);

    const int i = blockIdx.x;
    const bool isQ = (i < 3676);
    const __nv_bfloat16* A;
    const __nv_bfloat16* Wt;
    __nv_bfloat16* C;
    int Nrows, K, M, rowBase, colBase;
    if (isQ) {
        A = xn; Wt = wtQ; C = Cq;
        Nrows = NTOK; K = 128; M = 512;
        colBase = (i & 3) << 7; rowBase = (i >> 2) << 7;
    } else {
        int j = i - 3676;
        A = xg; Wt = wtKV; C = Ckv;
        Nrows = NKTOK; K = 896; M = 1024;
        colBase = (j & 7) << 7; rowBase = (j >> 3) << 7;
    }

    GEMM_BODY(A, Wt, Nrows, K, rowBase, colBase)

    #pragma unroll
    for (int nt = 0; nt < 4; ++nt) {
        const int col = colBase + wc*32 + nt*8 + (lane & 3)*2;
        #pragma unroll
        for (int mt = 0; mt < 4; ++mt) {
            #pragma unroll
            for (int hf = 0; hf < 2; ++hf) {
                const int r = rowBase + wr*64 + mt*16 + (lane >> 2) + hf*8;
                if (r >= Nrows) continue;
                stbf2(C + (size_t)r*M + col,
                      make_float2(acc[mt][nt][hf*2+0], acc[mt][nt][hf*2+1]));
            }
        }
    }
}

// ---------------- local attention: half-warp per (b, patch, v, head) -------
// 2 units per warp; lane owns 4 dims; 4-round butterfly within 16-lane half.
__global__ void __launch_bounds__(128) k_lattn() {
    int warp2 = blockIdx.x * 4 + (threadIdx.x >> 5);   // 0 .. 67199
    int lane = threadIdx.x & 31;
    int half = lane >> 4;
    int sub  = lane & 15;
    int unit = warp2*2 + half;                         // 0 .. 134399
    int h = unit & 7;
    int g = unit >> 3;
    int v = g % VV;
    int r = g / VV;
    int tt = r % NTP;
    int b = r / NTP;
    int d0 = sub * 4;

    float qf[PP][4], kf[PP][4], vf[PP][4];
    #pragma unroll
    for (int p = 0; p < PP; ++p) {
        int n = (b*TT + tt*PP + p)*VV + v;
        const __nv_bfloat16* rowp = g_qkv + (size_t)n*1536 + h*DH + d0;
        uint2 qu = *(const uint2*)rowp;
        uint2 ku = *(const uint2*)(rowp + 512);
        uint2 vu = *(const uint2*)(rowp + 1024);
        float2 f;
        f = u2f2(qu.x); qf[p][0]=f.x; qf[p][1]=f.y;
        f = u2f2(qu.y); qf[p][2]=f.x; qf[p][3]=f.y;
        f = u2f2(ku.x); kf[p][0]=f.x; kf[p][1]=f.y;
        f = u2f2(ku.y); kf[p][2]=f.x; kf[p][3]=f.y;
        f = u2f2(vu.x); vf[p][0]=f.x; vf[p][1]=f.y;
        f = u2f2(vu.y); vf[p][2]=f.x; vf[p][3]=f.y;
    }
    float dots[PP][PP];
    #pragma unroll
    for (int i = 0; i < PP; ++i)
        #pragma unroll
        for (int j = 0; j < PP; ++j)
            dots[i][j] = qf[i][0]*kf[j][0] + qf[i][1]*kf[j][1]
                       + qf[i][2]*kf[j][2] + qf[i][3]*kf[j][3];
    #pragma unroll
    for (int o = 8; o; o >>= 1)
        #pragma unroll
        for (int i = 0; i < PP; ++i)
            #pragma unroll
            for (int j = 0; j < PP; ++j)
                dots[i][j] += __shfl_xor_sync(0xffffffffu, dots[i][j], o);
    #pragma unroll
    for (int i = 0; i < PP; ++i) {
        float s = 0.f;
        #pragma unroll
        for (int j = 0; j < PP; ++j) {
            dots[i][j] = exp2f(dots[i][j] * EXP2C);
            s += dots[i][j];
        }
        float inv = 1.f / s;
        #pragma unroll
        for (int j = 0; j < PP; ++j) dots[i][j] *= inv;
    }
    #pragma unroll
    for (int i = 0; i < PP; ++i) {
        float o0 = 0.f, o1 = 0.f, o2 = 0.f, o3 = 0.f;
        #pragma unroll
        for (int j = 0; j < PP; ++j) {
            o0 += dots[i][j] * vf[j][0];
            o1 += dots[i][j] * vf[j][1];
            o2 += dots[i][j] * vf[j][2];
            o3 += dots[i][j] * vf[j][3];
        }
        int n = (b*TT + tt*PP + i)*VV + v;
        __nv_bfloat162 h0 = __float22bfloat162_rn(make_float2(o0, o1));
        __nv_bfloat162 h1 = __float22bfloat162_rn(make_float2(o2, o3));
        uint2 st;
        st.x = *reinterpret_cast<uint32_t*>(&h0);
        st.y = *reinterpret_cast<uint32_t*>(&h1);
        *reinterpret_cast<uint2*>(g_ao + (size_t)n*INNER + h*DH + d0) = st;
    }
}

// ---------------- global attention: one block per (b, h, v) ----------------
__global__ void __launch_bounds__(160) k_gattn() {
    int bid = blockIdx.x;
    int v = bid % VV;
    int rr = bid / VV;
    int h = rr & 7;
    int b = rr >> 3;
    __shared__ float ks[NTP][DH];
    __shared__ float vs[NTP][DH];
    for (int idx = threadIdx.x; idx < NTP*DH/2; idx += 160) {
        int j = idx >> 5, d2 = idx & 31;
        int nk = (b*NTP + j)*VV + v;
        size_t o = (size_t)nk*1024 + h*DH + d2*2;
        float2 kf = ldbf2(g_kv + o);
        float2 vf = ldbf2(g_kv + o + 512);
        ks[j][d2*2] = kf.x; ks[j][d2*2+1] = kf.y;
        vs[j][d2*2] = vf.x; vs[j][d2*2+1] = vf.y;
    }
    __syncthreads();
    int tid = threadIdx.x;
    if (tid >= 147) return;
    int i0 = 2*tid;
    size_t q0 = (size_t)((b*TT + i0)*VV + v)*INNER + h*DH;
    size_t q1 = q0 + (size_t)VV*INNER;

    float da[NTP], db[NTP];
    #pragma unroll
    for (int j = 0; j < NTP; ++j) { da[j] = 0.f; db[j] = 0.f; }

    for (int dchunk = 0; dchunk < 4; ++dchunk) {
        int dbase = dchunk * 16;
        float qa[16], qb[16];
        {
            uint4 u0 = *(const uint4*)(g_q + q0 + dbase);
            uint4 u1 = *(const uint4*)(g_q + q0 + dbase + 8);
            uint4 w0 = *(const uint4*)(g_q + q1 + dbase);
            uint4 w1 = *(const uint4*)(g_q + q1 + dbase + 8);
            float2 f;
            f=u2f2(u0.x); qa[0]=f.x; qa[1]=f.y;  f=u2f2(u0.y); qa[2]=f.x; qa[3]=f.y;
            f=u2f2(u0.z); qa[4]=f.x; qa[5]=f.y;  f=u2f2(u0.w); qa[6]=f.x; qa[7]=f.y;
            f=u2f2(u1.x); qa[8]=f.x; qa[9]=f.y;  f=u2f2(u1.y); qa[10]=f.x; qa[11]=f.y;
            f=u2f2(u1.z); qa[12]=f.x; qa[13]=f.y; f=u2f2(u1.w); qa[14]=f.x; qa[15]=f.y;
            f=u2f2(w0.x); qb[0]=f.x; qb[1]=f.y;  f=u2f2(w0.y); qb[2]=f.x; qb[3]=f.y;
            f=u2f2(w0.z); qb[4]=f.x; qb[5]=f.y;  f=u2f2(w0.w); qb[6]=f.x; qb[7]=f.y;
            f=u2f2(w1.x); qb[8]=f.x; qb[9]=f.y;  f=u2f2(w1.y); qb[10]=f.x; qb[11]=f.y;
            f=u2f2(w1.z); qb[12]=f.x; qb[13]=f.y; f=u2f2(w1.w); qb[14]=f.x; qb[15]=f.y;
        }
        #pragma unroll
        for (int j = 0; j < NTP; ++j) {
            #pragma unroll
            for (int dd = 0; dd < 16; ++dd) {
                float kv = ks[j][dbase + dd];
                da[j] += qa[dd] * kv;
                db[j] += qb[dd] * kv;
            }
        }
    }
    {
        float s = 0.f;
        #pragma unroll
        for (int j = 0; j < NTP; ++j) { da[j] = exp2f(da[j] * EXP2C); s += da[j]; }
        float inv = 1.f / s;
        #pragma unroll
        for (int j = 0; j < NTP; ++j) da[j] *= inv;
    }
    {
        float s = 0.f;
        #pragma unroll
        for (int j = 0; j < NTP; ++j) { db[j] = exp2f(db[j] * EXP2C); s += db[j]; }
        float inv = 1.f / s;
        #pragma unroll
        for (int j = 0; j < NTP; ++j) db[j] *= inv;
    }
    size_t o0 = q0, o1 = q1;
    for (int dchunk = 0; dchunk < 4; ++dchunk) {
        int dbase = dchunk * 16;
        float oa[16], ob[16];
        #pragma unroll
        for (int dd = 0; dd < 16; ++dd) { oa[dd] = 0.f; ob[dd] = 0.f; }
        #pragma unroll
        for (int j = 0; j < NTP; ++j) {
            #pragma unroll
            for (int dd = 0; dd < 16; ++dd) {
                float vv = vs[j][dbase + dd];
                oa[dd] += da[j] * vv;
                ob[dd] += db[j] * vv;
            }
        }
        #pragma unroll
        for (int dd = 0; dd < 16; dd += 2) {
            stbf2(g_ao + o0 + dbase + dd, make_float2(oa[dd], oa[dd+1]));
            stbf2(g_ao + o1 + dbase + dd, make_float2(ob[dd], ob[dd+1]));
        }
    }
}

// ---------------- launch -----------------------------------------------------
extern "C" void kernel_launch(void* const* d_in, const int* in_sizes, int n_in,
                              void* d_out, int out_size) {
    (void)in_sizes; (void)n_in; (void)out_size;
    float* p_xT;
    __nv_bfloat16 *p_xn, *p_qkv, *p_q, *p_kv, *p_ao, *p_xg, *p_wt;
    cudaGetSymbolAddress((void**)&p_xT,  g_xT);
    cudaGetSymbolAddress((void**)&p_xn,  g_xn);
    cudaGetSymbolAddress((void**)&p_qkv, g_qkv);
    cudaGetSymbolAddress((void**)&p_q,   g_q);
    cudaGetSymbolAddress((void**)&p_kv,  g_kv);
    cudaGetSymbolAddress((void**)&p_ao,  g_ao);
    cudaGetSymbolAddress((void**)&p_xg,  g_xg);
    cudaGetSymbolAddress((void**)&p_wt,  g_wt);

    cudaFuncSetAttribute(k_gemm_bf<0>, cudaFuncAttributeMaxDynamicSharedMemorySize, GEMM_SMEM);
    cudaFuncSetAttribute(k_gemm_bf<2>, cudaFuncAttributeMaxDynamicSharedMemorySize, GEMM_SMEM);
    cudaFuncSetAttribute(k_gemm_bf<3>, cudaFuncAttributeMaxDynamicSharedMemorySize, GEMM_SMEM);
    cudaFuncSetAttribute(k_gemm_gproj, cudaFuncAttributeMaxDynamicSharedMemorySize, GEMM_SMEM);

    const float* x      = (const float*)d_in[0];
    const float* ln1_g  = (const float*)d_in[1];
    const float* ln1_b  = (const float*)d_in[2];
    const float* la_wq  = (const float*)d_in[3];
    const float* la_wkv = (const float*)d_in[4];
    const float* la_wo  = (const float*)d_in[5];
    const float* la_bo  = (const float*)d_in[6];
    const float* ln2_g  = (const float*)d_in[7];
    const float* ln2_b  = (const float*)d_in[8];
    const float* ff1_w1 = (const float*)d_in[9];
    const float* ff1_b1 = (const float*)d_in[10];
    const float* ff1_w2 = (const float*)d_in[11];
    const float* ff1_b2 = (const float*)d_in[12];
    const float* ln3_g  = (const float*)d_in[13];
    const float* ln3_b  = (const float*)d_in[14];
    const float* ga_wq  = (const float*)d_in[15];
    const float* ga_wkv = (const float*)d_in[16];
    const float* ga_wo  = (const float*)d_in[17];
    const float* ga_bo  = (const float*)d_in[18];
    const float* ln4_g  = (const float*)d_in[19];
    const float* ln4_b  = (const float*)d_in[20];
    const float* ff2_w1 = (const float*)d_in[21];
    const float* ff2_b1 = (const float*)d_in[22];
    const float* ff2_w2 = (const float*)d_in[23];
    const float* ff2_b2 = (const float*)d_in[24];

    // weight prep: single launch, both layers
    k_wprep<<<8192, 256>>>(la_wq, la_wkv, la_wo, ff1_w1, ff1_w2,
                           ga_wq, ga_wkv, ga_wo, ff2_w1, ff2_w2, p_wt);

    const int rowTiles  = (NTOK  + 127) / 128;   // 919
    const int lnGrid = NTOK / 8;

    // transpose-in + fused LN1(layer 0)
    k_tin<<<BB*TT, 256>>>(x, ln1_g, ln1_b);

    for (int l = 0; l < 2; ++l) {
        __nv_bfloat16* wb = p_wt + (size_t)l*WT_LSZ;
        // --- local attention block ---
        if (l == 1) k_ln<false><<<lnGrid, 256>>>(ln1_g + CC, ln1_b + CC);
        k_gemm_bf<0><<<dim3(12, rowTiles), 256, GEMM_SMEM>>>(
            p_xn, wb + OFF_LQKV, nullptr, nullptr, p_qkv, NTOK, 128, 1536);
        k_lattn<<<NKTOK, 128>>>();
        k_gemm_bf<3><<<dim3(1, rowTiles), 256, GEMM_SMEM>>>(
            p_ao, wb + OFF_LWO, la_bo + l*CC, p_xT, p_xT, NTOK, 512, 128);
        // --- ff1 ---
        k_ln<false><<<lnGrid, 256>>>(ln2_g + l*CC, ln2_b + l*CC);
        k_gemm_bf<2><<<dim3(4, rowTiles), 256, GEMM_SMEM>>>(
            p_xn, wb + OFF_F1A, ff1_b1 + l*512, nullptr, p_ao, NTOK, 128, 512);
        k_gemm_bf<3><<<dim3(1, rowTiles), 256, GEMM_SMEM>>>(
            p_ao, wb + OFF_F1B, ff1_b2 + l*CC, p_xT, p_xT, NTOK, 512, 128);
        // --- global attention block (LN + fused gather, merged q/kv proj) ---
        k_ln<true><<<lnGrid, 256>>>(ln3_g + l*CC, ln3_b + l*CC);
        k_gemm_gproj<<<4732, 256, GEMM_SMEM>>>(
            p_xn, wb + OFF_GWQ, p_q, p_xg, wb + OFF_GWKV, p_kv);
        k_gattn<<<BB*NHEAD*VV, 160>>>();
        k_gemm_bf<3><<<dim3(1, rowTiles), 256, GEMM_SMEM>>>(
            p_ao, wb + OFF_GWO, ga_bo + l*CC, p_xT, p_xT, NTOK, 512, 128);
        // --- ff2 ---
        k_ln<false><<<lnGrid, 256>>>(ln4_g + l*CC, ln4_b + l*CC);
        k_gemm_bf<2><<<dim3(4, rowTiles), 256, GEMM_SMEM>>>(
            p_xn, wb + OFF_F2A, ff2_b1 + l*512, nullptr, p_ao, NTOK, 128, 512);
        k_gemm_bf<3><<<dim3(1, rowTiles), 256, GEMM_SMEM>>>(
            p_ao, wb + OFF_F2B, ff2_b2 + l*CC, p_xT, p_xT, NTOK, 512, 128);
    }
    k_tout<<<BB*TT, 256>>>((float*)d_out);
}